// round 2
// baseline (speedup 1.0000x reference)
#include <cuda_runtime.h>
#include <math.h>

namespace {
constexpr int B  = 128;
constexpr int T  = 512;
constexpr int A  = 256;
constexpr int UG = 512;
constexpr int ROWS = B * T;       // 65536
constexpr int XK = 768;           // x feature width: act(256)+inp2(256)+inp3(256)
constexpr int XN = 1536;          // 3 * UG
}

// ---------------- scratch (device globals; no allocation allowed) ------------
__device__ float g_x [(size_t)ROWS * XK];   // 201 MB: [t*B+b][768]
__device__ float g_xp[(size_t)ROWS * XN];   // 402 MB: x @ gru_k + gru_b[0], [t*B+b][1536]
__device__ float g_h [2][B * UG];           // ping-pong GRU state
__device__ float g_hmax[B * UG];            // running max over time of hs
__device__ float g_ms[B * 256];
__device__ float g_rs[B * 256];

__device__ __forceinline__ float eluf(float v) { return v > 0.f ? v : (expf(v) - 1.f); }
__device__ __forceinline__ float sigm(float v) { return 1.f / (1.f + expf(-v)); }

// ---------------- small front-end kernels -----------------------------------

// ms = elu(motion @ W_mot + b), rs = elu(robot @ W_rob + b)   [128,64]@[64,256]
__global__ void k_msrs(const float* __restrict__ motion, const float* __restrict__ robot,
                       const float* __restrict__ Wm, const float* __restrict__ bm,
                       const float* __restrict__ Wr, const float* __restrict__ br) {
    int b = blockIdx.x;
    int j = threadIdx.x; // 256
    __shared__ float sm[64], sr[64];
    if (j < 64) sm[j] = motion[b * 64 + j];
    else if (j < 128) sr[j - 64] = robot[b * 64 + (j - 64)];
    __syncthreads();
    float accm = bm[j], accr = br[j];
    for (int k = 0; k < 64; k++) {
        accm += sm[k] * Wm[k * 256 + j];
        accr += sr[k] * Wr[k * 256 + j];
    }
    g_ms[b * 256 + j] = eluf(accm);
    g_rs[b * 256 + j] = eluf(accr);
}

// h0 = elu(concat(ms,rs,state) @ W_comb + b_comb); also init hmax = -inf
__global__ void k_h0(const float* __restrict__ state, const float* __restrict__ Wc,
                     const float* __restrict__ bc) {
    int b = blockIdx.x;
    int u = threadIdx.x; // 512
    __shared__ float s[1024];
    s[u] = (u < 256) ? g_ms[b * 256 + u] : g_rs[b * 256 + (u - 256)];
    s[512 + u] = state[b * 512 + u];
    __syncthreads();
    float acc = bc[u];
    for (int k = 0; k < 1024; k++) acc += s[k] * Wc[k * 512 + u];
    g_h[0][b * 512 + u] = eluf(acc);
    g_hmax[b * 512 + u] = -INFINITY;
}

// x[:, 0:256] = action * mu + mean   (row r = t*B + b)
__global__ void k_act(const float* __restrict__ action, const float* __restrict__ mu,
                      const float* __restrict__ mean) {
    int r = blockIdx.x;
    int t = r >> 7;
    int b = r & 127;
    int a = threadIdx.x;
    float v = action[((size_t)b * T + t) * A + a] * mu[b * A + a] + mean[b * A + a];
    g_x[(size_t)r * XK + a] = v;
}

// x[:, 256:512] = elu(osc[..., :64] @ W_oscr + b)   K=64, 8 rows/block
__global__ void k_inp2(const float* __restrict__ osc, const float* __restrict__ W,
                       const float* __restrict__ bias) {
    int r0 = blockIdx.x * 8;
    int j = threadIdx.x; // 256
    __shared__ float s[8][64];
    for (int i = threadIdx.x; i < 8 * 64; i += 256) {
        int rr = i >> 6, k = i & 63;
        int r = r0 + rr;
        int t = r >> 7, b = r & 127;
        s[rr][k] = osc[((size_t)b * T + t) * 128 + k];
    }
    __syncthreads();
    float bj = bias[j];
    float acc[8];
#pragma unroll
    for (int i = 0; i < 8; i++) acc[i] = bj;
    for (int k = 0; k < 64; k++) {
        float w = W[k * 256 + j];
#pragma unroll
        for (int i = 0; i < 8; i++) acc[i] += s[i][k] * w;
    }
#pragma unroll
    for (int i = 0; i < 8; i++) g_x[(size_t)(r0 + i) * XK + 256 + j] = eluf(acc[i]);
}

// x[:, 512:768] = elu(inp2[..., 64:] @ W_osci + b)  (faithful slicing bug) K=192
__global__ void k_inp3(const float* __restrict__ W, const float* __restrict__ bias) {
    int r0 = blockIdx.x * 8;
    int j = threadIdx.x; // 256
    __shared__ float s[8][192];
    for (int i = threadIdx.x; i < 8 * 192; i += 256) {
        int rr = i / 192, k = i % 192;
        s[rr][k] = g_x[(size_t)(r0 + rr) * XK + 320 + k]; // 256 + 64 .. 512
    }
    __syncthreads();
    float bj = bias[j];
    float acc[8];
#pragma unroll
    for (int i = 0; i < 8; i++) acc[i] = bj;
    for (int k = 0; k < 192; k++) {
        float w = W[k * 256 + j];
#pragma unroll
        for (int i = 0; i < 8; i++) acc[i] += s[i][k] * w;
    }
#pragma unroll
    for (int i = 0; i < 8; i++) g_x[(size_t)(r0 + i) * XK + 512 + j] = eluf(acc[i]);
}

// ---------------- big GEMM: g_xp = g_x @ gru_k + gru_b[0] -------------------
// M=65536 N=1536 K=768 fp32. 128x128 tile, 256 thr, 8x8 micro-tile.
__global__ void __launch_bounds__(256) k_xproj(const float* __restrict__ gk,
                                               const float* __restrict__ gb) {
    __shared__ float As[16][128]; // [k][m] transposed
    __shared__ float Bs[16][128]; // [k][n]
    const int m0 = blockIdx.y * 128;
    const int n0 = blockIdx.x * 128;
    const int tid = threadIdx.x;
    const int tm = (tid >> 4) << 3;  // 0..120
    const int tn = (tid & 15) << 3;  // 0..120
    float acc[8][8];
#pragma unroll
    for (int i = 0; i < 8; i++)
#pragma unroll
        for (int j = 0; j < 8; j++) acc[i][j] = 0.f;

    for (int k0 = 0; k0 < XK; k0 += 16) {
#pragma unroll
        for (int l = 0; l < 2; l++) {           // A tile: 128x16
            int f = tid + (l << 8);
            int row = f >> 2;
            int kq = (f & 3) << 2;
            float4 v = *(const float4*)&g_x[(size_t)(m0 + row) * XK + k0 + kq];
            As[kq + 0][row] = v.x;
            As[kq + 1][row] = v.y;
            As[kq + 2][row] = v.z;
            As[kq + 3][row] = v.w;
        }
#pragma unroll
        for (int l = 0; l < 2; l++) {           // B tile: 16x128
            int f = tid + (l << 8);
            int k = f >> 5;
            int nq = (f & 31) << 2;
            *(float4*)&Bs[k][nq] = *(const float4*)&gk[(size_t)(k0 + k) * XN + n0 + nq];
        }
        __syncthreads();
#pragma unroll
        for (int k = 0; k < 16; k++) {
            float4 a0 = *(const float4*)&As[k][tm];
            float4 a1 = *(const float4*)&As[k][tm + 4];
            float4 c0 = *(const float4*)&Bs[k][tn];
            float4 c1 = *(const float4*)&Bs[k][tn + 4];
            float av[8] = {a0.x, a0.y, a0.z, a0.w, a1.x, a1.y, a1.z, a1.w};
            float bv[8] = {c0.x, c0.y, c0.z, c0.w, c1.x, c1.y, c1.z, c1.w};
#pragma unroll
            for (int i = 0; i < 8; i++)
#pragma unroll
                for (int j = 0; j < 8; j++) acc[i][j] += av[i] * bv[j];
        }
        __syncthreads();
    }

    float bias[8];
#pragma unroll
    for (int j = 0; j < 8; j++) bias[j] = gb[n0 + tn + j]; // gru_b row 0
#pragma unroll
    for (int i = 0; i < 8; i++) {
        size_t base = (size_t)(m0 + tm + i) * XN + n0 + tn;
        float4 o0 = make_float4(acc[i][0] + bias[0], acc[i][1] + bias[1],
                                acc[i][2] + bias[2], acc[i][3] + bias[3]);
        float4 o1 = make_float4(acc[i][4] + bias[4], acc[i][5] + bias[5],
                                acc[i][6] + bias[6], acc[i][7] + bias[7]);
        *(float4*)&g_xp[base] = o0;
        *(float4*)&g_xp[base + 4] = o1;
    }
}

// ---------------- GRU step --------------------------------------------------
// Block tile: 64 batch rows x 8 u (=> 24 W columns across z|r|h gates).
// Grid (64 u-tiles, 2 b-tiles) = 128 blocks, 128 threads.
// Per thread: 4 rows x 1 u x 3 gates. K=512 in 16 chunks of 32, double-buffered.
__global__ void __launch_bounds__(128) k_step(const float* __restrict__ Wr,
                                              const float* __restrict__ gb,
                                              int t, int par) {
    __shared__ float sh[2][32][64]; // [buf][k][swizzled row]
    __shared__ float sw[2][32][24]; // [buf][k][gate-seg*8 + cg]
    const float* hp = g_h[par];
    float* hnxt = g_h[par ^ 1];
    const int b0 = blockIdx.y * 64;
    const int u0 = blockIdx.x * 8;
    const int tid = threadIdx.x;
    const int rg = tid >> 3;  // 0..15 -> rows b0 + rg*4 + i
    const int cg = tid & 7;   // 0..7  -> u = u0 + cg
    const int u = u0 + cg;

    float az[4], ar[4], ah[4];
    {
        float bz  = gb[XN + u];
        float brr = gb[XN + 512 + u];
        float bh  = gb[XN + 1024 + u];
#pragma unroll
        for (int i = 0; i < 4; i++) { az[i] = bz; ar[i] = brr; ah[i] = bh; }
    }

    float4 hv[4];
    float wv[6];

    auto loadH = [&](int kc) {
#pragma unroll
        for (int l = 0; l < 4; l++) {
            int q = tid + 128 * l;
            int row = q >> 3;
            int kq = (q & 7) << 2;
            hv[l] = *(const float4*)&hp[(size_t)(b0 + row) * UG + kc + kq];
        }
    };
    auto storeH = [&](int buf) {
#pragma unroll
        for (int l = 0; l < 4; l++) {
            int q = tid + 128 * l;
            int row = q >> 3;
            int kq = (q & 7) << 2;
            int srow = row ^ (((kq >> 2) & 7) << 3); // bank swizzle
            sh[buf][kq + 0][srow] = hv[l].x;
            sh[buf][kq + 1][srow] = hv[l].y;
            sh[buf][kq + 2][srow] = hv[l].z;
            sh[buf][kq + 3][srow] = hv[l].w;
        }
    };
    auto loadW = [&](int kc) {
#pragma unroll
        for (int l = 0; l < 6; l++) {
            int e = tid + 128 * l;
            int k = e / 24, c = e % 24;
            int seg = c >> 3, w = c & 7;
            wv[l] = Wr[(size_t)(kc + k) * XN + seg * 512 + u0 + w];
        }
    };
    auto storeW = [&](int buf) {
#pragma unroll
        for (int l = 0; l < 6; l++) {
            int e = tid + 128 * l;
            int k = e / 24, c = e % 24;
            sw[buf][k][c] = wv[l];
        }
    };

    loadH(0); loadW(0);
    storeH(0); storeW(0);
    __syncthreads();

    for (int ch = 0; ch < 16; ch++) {
        int buf = ch & 1;
        if (ch < 15) { loadH((ch + 1) * 32); loadW((ch + 1) * 32); }
#pragma unroll
        for (int k = 0; k < 32; k++) {
            int srow = (rg << 2) ^ (((k >> 2) & 7) << 3);
            float4 h4 = *(const float4*)&sh[buf][k][srow];
            float wz = sw[buf][k][cg];
            float wr2 = sw[buf][k][8 + cg];
            float wh = sw[buf][k][16 + cg];
            az[0] += h4.x * wz;  az[1] += h4.y * wz;  az[2] += h4.z * wz;  az[3] += h4.w * wz;
            ar[0] += h4.x * wr2; ar[1] += h4.y * wr2; ar[2] += h4.z * wr2; ar[3] += h4.w * wr2;
            ah[0] += h4.x * wh;  ah[1] += h4.y * wh;  ah[2] += h4.z * wh;  ah[3] += h4.w * wh;
        }
        __syncthreads();
        if (ch < 15) { storeH(buf ^ 1); storeW(buf ^ 1); __syncthreads(); }
    }

    const float* xp = g_xp + (size_t)t * B * XN;
#pragma unroll
    for (int i = 0; i < 4; i++) {
        int b = b0 + (rg << 2) + i;
        size_t xb = (size_t)b * XN;
        float z  = sigm(xp[xb + u] + az[i]);
        float r  = sigm(xp[xb + 512 + u] + ar[i]);
        float hc = tanhf(xp[xb + 1024 + u] + r * ah[i]);
        float hprev = hp[(size_t)b * UG + u];
        float hn = z * hprev + (1.f - z) * hc;
        hnxt[(size_t)b * UG + u] = hn;
        float* pm = &g_hmax[(size_t)b * UG + u];
        *pm = fmaxf(*pm, hn);
    }
}

// ---------------- epilogue: out = elu(hmax @ W_out + b_out); copy h_final ---
__global__ void k_out(const float* __restrict__ Wout, const float* __restrict__ bout,
                      float* __restrict__ dout, int par, int out_size) {
    int b = blockIdx.x;
    int tid = threadIdx.x; // 256
    __shared__ float red[256];
    float s = 0.f;
    for (int uu = tid; uu < UG; uu += 256) s += g_hmax[b * UG + uu] * Wout[uu];
    red[tid] = s;
    __syncthreads();
    for (int o = 128; o > 0; o >>= 1) {
        if (tid < o) red[tid] += red[tid + o];
        __syncthreads();
    }
    if (tid == 0 && b < out_size) dout[b] = eluf(red[0] + bout[0]);
    for (int uu = tid; uu < UG; uu += 256) {
        int idx = B + b * UG + uu;
        if (idx < out_size) dout[idx] = g_h[par][b * UG + uu];
    }
}

// ---------------- launch ------------------------------------------------------
extern "C" void kernel_launch(void* const* d_in, const int* in_sizes, int n_in,
                              void* d_out, int out_size) {
    const float* motion = (const float*)d_in[0];
    const float* robot  = (const float*)d_in[1];
    // d_in[2] = osc_state (unused by the reference forward)
    const float* action = (const float*)d_in[3];
    const float* osc    = (const float*)d_in[4];
    const float* mu     = (const float*)d_in[5];
    const float* mean   = (const float*)d_in[6];
    const float* state  = (const float*)d_in[7];
    const float* W_mot  = (const float*)d_in[8];
    const float* b_mot  = (const float*)d_in[9];
    const float* W_rob  = (const float*)d_in[10];
    const float* b_rob  = (const float*)d_in[11];
    const float* W_comb = (const float*)d_in[12];
    const float* b_comb = (const float*)d_in[13];
    const float* W_oscr = (const float*)d_in[14];
    const float* b_oscr = (const float*)d_in[15];
    const float* W_osci = (const float*)d_in[16];
    const float* b_osci = (const float*)d_in[17];
    const float* gru_k  = (const float*)d_in[18];
    const float* gru_rk = (const float*)d_in[19];
    const float* gru_b  = (const float*)d_in[20];
    const float* W_out  = (const float*)d_in[21];
    const float* b_out  = (const float*)d_in[22];
    float* out = (float*)d_out;

    k_msrs<<<B, 256>>>(motion, robot, W_mot, b_mot, W_rob, b_rob);
    k_h0<<<B, 512>>>(state, W_comb, b_comb);
    k_act<<<ROWS, 256>>>(action, mu, mean);
    k_inp2<<<ROWS / 8, 256>>>(osc, W_oscr, b_oscr);
    k_inp3<<<ROWS / 8, 256>>>(W_osci, b_osci);
    k_xproj<<<dim3(XN / 128, ROWS / 128), 256>>>(gru_k, gru_b);
    for (int t = 0; t < T; t++)
        k_step<<<dim3(UG / 8, B / 64), 128>>>(gru_rk, gru_b, t, t & 1);
    // after 512 steps the final h sits in g_h[(511 & 1) ^ 1] == g_h[0]
    k_out<<<B, 256>>>(W_out, b_out, out, 0, out_size);
}

// round 4
// speedup vs baseline: 1.1419x; 1.1419x over previous
#include <cuda_runtime.h>
#include <cuda_bf16.h>
#include <cstdint>
#include <math.h>

namespace {
constexpr int B  = 128;
constexpr int T  = 512;
constexpr int A  = 256;
constexpr int UG = 512;
constexpr int ROWS = B * T;       // 65536
constexpr int XK = 768;           // x feature width
constexpr int XN = 1536;          // 3 * UG
}

// ---------------- scratch (device globals; no allocation allowed) ------------
__device__ float g_x [(size_t)ROWS * XK];              // fp32 x (only cols 256:512 used by inp3)
__device__ __nv_bfloat16 g_xh[(size_t)ROWS * XK];      // bf16 hi of x
__device__ __nv_bfloat16 g_xl[(size_t)ROWS * XK];      // bf16 lo of x
__device__ __nv_bfloat16 g_bh[(size_t)XN * XK];        // gru_k transposed [N,K] hi
__device__ __nv_bfloat16 g_bl[(size_t)XN * XK];        // gru_k transposed [N,K] lo
__device__ float g_xp[(size_t)ROWS * XN];              // x @ gru_k + gru_b[0]
__device__ float g_h [2][B * UG];                      // ping-pong GRU state
__device__ float g_hmax[B * UG];
__device__ float g_ms[B * 256];
__device__ float g_rs[B * 256];

__device__ __forceinline__ float eluf(float v) { return v > 0.f ? v : (expf(v) - 1.f); }
__device__ __forceinline__ float sigm(float v) { return 1.f / (1.f + expf(-v)); }
__device__ __forceinline__ void split_bf16(float v, __nv_bfloat16& h, __nv_bfloat16& l) {
    h = __float2bfloat16(v);
    l = __float2bfloat16(v - __bfloat162float(h));
}

// ---------------- PTX helpers (plain sm_103-safe: no tcgen05) ----------------
__device__ __forceinline__ uint32_t smem_u32(const void* p) {
    uint32_t a;
    asm("{ .reg .u64 t; cvta.to.shared.u64 t, %1; cvt.u32.u64 %0, t; }" : "=r"(a) : "l"(p));
    return a;
}
__device__ __forceinline__ void cpa16(uint32_t s, const void* g) {
    asm volatile("cp.async.cg.shared.global [%0], [%1], 16;" :: "r"(s), "l"(g));
}
__device__ __forceinline__ void ldm4(uint32_t* r, uint32_t a) {
    asm volatile("ldmatrix.sync.aligned.m8n8.x4.shared.b16 {%0,%1,%2,%3}, [%4];"
                 : "=r"(r[0]), "=r"(r[1]), "=r"(r[2]), "=r"(r[3]) : "r"(a));
}
__device__ __forceinline__ void mma16816(float* c, const uint32_t* a, uint32_t b0, uint32_t b1) {
    asm volatile(
        "mma.sync.aligned.m16n8k16.row.col.f32.bf16.bf16.f32 "
        "{%0,%1,%2,%3}, {%4,%5,%6,%7}, {%8,%9}, {%0,%1,%2,%3};"
        : "+f"(c[0]), "+f"(c[1]), "+f"(c[2]), "+f"(c[3])
        : "r"(a[0]), "r"(a[1]), "r"(a[2]), "r"(a[3]), "r"(b0), "r"(b1));
}

// ---------------- small front-end kernels -----------------------------------
__global__ void k_msrs(const float* __restrict__ motion, const float* __restrict__ robot,
                       const float* __restrict__ Wm, const float* __restrict__ bm,
                       const float* __restrict__ Wr, const float* __restrict__ br) {
    int b = blockIdx.x;
    int j = threadIdx.x; // 256
    __shared__ float sm[64], sr[64];
    if (j < 64) sm[j] = motion[b * 64 + j];
    else if (j < 128) sr[j - 64] = robot[b * 64 + (j - 64)];
    __syncthreads();
    float accm = bm[j], accr = br[j];
    for (int k = 0; k < 64; k++) {
        accm += sm[k] * Wm[k * 256 + j];
        accr += sr[k] * Wr[k * 256 + j];
    }
    g_ms[b * 256 + j] = eluf(accm);
    g_rs[b * 256 + j] = eluf(accr);
}

__global__ void k_h0(const float* __restrict__ state, const float* __restrict__ Wc,
                     const float* __restrict__ bc) {
    int b = blockIdx.x;
    int u = threadIdx.x; // 512
    __shared__ float s[1024];
    s[u] = (u < 256) ? g_ms[b * 256 + u] : g_rs[b * 256 + (u - 256)];
    s[512 + u] = state[b * 512 + u];
    __syncthreads();
    float acc = bc[u];
    for (int k = 0; k < 1024; k++) acc += s[k] * Wc[k * 512 + u];
    g_h[0][b * 512 + u] = eluf(acc);
    g_hmax[b * 512 + u] = -INFINITY;
}

// x[:, 0:256] = action * mu + mean  -> bf16 hi/lo
__global__ void k_act(const float* __restrict__ action, const float* __restrict__ mu,
                      const float* __restrict__ mean) {
    int r = blockIdx.x;
    int t = r >> 7;
    int b = r & 127;
    int a = threadIdx.x;
    float v = action[((size_t)b * T + t) * A + a] * mu[b * A + a] + mean[b * A + a];
    size_t idx = (size_t)r * XK + a;
    split_bf16(v, g_xh[idx], g_xl[idx]);
}

// x[:, 256:512] = elu(osc[..., :64] @ W_oscr + b); fp32 (for inp3) + hi/lo
__global__ void k_inp2(const float* __restrict__ osc, const float* __restrict__ W,
                       const float* __restrict__ bias) {
    int r0 = blockIdx.x * 8;
    int j = threadIdx.x; // 256
    __shared__ float s[8][64];
    for (int i = threadIdx.x; i < 8 * 64; i += 256) {
        int rr = i >> 6, k = i & 63;
        int r = r0 + rr;
        int t = r >> 7, b = r & 127;
        s[rr][k] = osc[((size_t)b * T + t) * 128 + k];
    }
    __syncthreads();
    float bj = bias[j];
    float acc[8];
#pragma unroll
    for (int i = 0; i < 8; i++) acc[i] = bj;
    for (int k = 0; k < 64; k++) {
        float w = W[k * 256 + j];
#pragma unroll
        for (int i = 0; i < 8; i++) acc[i] += s[i][k] * w;
    }
#pragma unroll
    for (int i = 0; i < 8; i++) {
        float v = eluf(acc[i]);
        size_t idx = (size_t)(r0 + i) * XK + 256 + j;
        g_x[idx] = v;
        split_bf16(v, g_xh[idx], g_xl[idx]);
    }
}

// x[:, 512:768] = elu(inp2[..., 64:] @ W_osci + b)  (faithful slicing bug)
__global__ void k_inp3(const float* __restrict__ W, const float* __restrict__ bias) {
    int r0 = blockIdx.x * 8;
    int j = threadIdx.x; // 256
    __shared__ float s[8][192];
    for (int i = threadIdx.x; i < 8 * 192; i += 256) {
        int rr = i / 192, k = i % 192;
        s[rr][k] = g_x[(size_t)(r0 + rr) * XK + 320 + k];
    }
    __syncthreads();
    float bj = bias[j];
    float acc[8];
#pragma unroll
    for (int i = 0; i < 8; i++) acc[i] = bj;
    for (int k = 0; k < 192; k++) {
        float w = W[k * 256 + j];
#pragma unroll
        for (int i = 0; i < 8; i++) acc[i] += s[i][k] * w;
    }
#pragma unroll
    for (int i = 0; i < 8; i++) {
        size_t idx = (size_t)(r0 + i) * XK + 512 + j;
        split_bf16(eluf(acc[i]), g_xh[idx], g_xl[idx]);
    }
}

// transpose + split gru_k [768,1536] -> g_bh/g_bl [1536,768]
__global__ void k_trb(const float* __restrict__ gk) {
    __shared__ float s[32][33];
    int n0 = blockIdx.x * 32, k0 = blockIdx.y * 32;
    int tx = threadIdx.x, ty = threadIdx.y; // 32 x 8
#pragma unroll
    for (int i = 0; i < 32; i += 8)
        s[ty + i][tx] = gk[(size_t)(k0 + ty + i) * XN + n0 + tx];
    __syncthreads();
#pragma unroll
    for (int i = 0; i < 32; i += 8) {
        size_t idx = (size_t)(n0 + ty + i) * XK + k0 + tx;
        split_bf16(s[tx][ty + i], g_bh[idx], g_bl[idx]);
    }
}

// ---------------- HMMA GEMM: g_xp = x @ gru_k + gru_b[0] ---------------------
// split-bf16 (3 terms: AH*BH + AL*BH + AH*BL), mma.sync m16n8k16.
// Block tile 128x128, K-chunk 32, cp.async double-buffered.
// smem layout per buffer: AH[128][40] | AL | BH | BL  (80B row pitch -> ldmatrix
// conflict-free: 16B-bank index = 5*row mod 8 is a permutation).
namespace {
constexpr int PITCHB = 80;                 // bytes per 40-bf16 row
constexpr int ARRB   = 128 * PITCHB;       // 10240 per array
constexpr int BUFB   = 4 * ARRB;           // 40960 per buffer
constexpr int SMEM_GEMM = 2 * BUFB;        // 81920
constexpr int KCH = 24;                    // 768 / 32 chunks
}

__global__ void __launch_bounds__(256, 1) k_xmma(const float* __restrict__ gb) {
    extern __shared__ char smem[];
    const uint32_t sb = smem_u32(smem);
    const int tid = threadIdx.x;
    const int lane = tid & 31, wid = tid >> 5;
    const int wm = wid & 3;       // warp row group (32 rows)
    const int wn = wid >> 2;      // warp col group (64 cols)
    const int m0 = blockIdx.y * 128;
    const int n0 = blockIdx.x * 128;

    const __nv_bfloat16* gptr[4] = {
        g_xh + (size_t)m0 * XK, g_xl + (size_t)m0 * XK,
        g_bh + (size_t)n0 * XK, g_bl + (size_t)n0 * XK};

    auto load_chunk = [&](int c, int buf) {
        uint32_t base = sb + buf * BUFB;
#pragma unroll
        for (int l = 0; l < 8; l++) {
            int idx = tid + 256 * l;
            int arr = idx >> 9;            // 0..3
            int rem = idx & 511;
            int row = rem >> 2;            // 0..127
            int cch = rem & 3;             // 0..3 (16B chunks of the 64B row)
            cpa16(base + arr * ARRB + row * PITCHB + cch * 16,
                  gptr[arr] + (size_t)row * XK + c * 32 + cch * 8);
        }
        asm volatile("cp.async.commit_group;" ::: "memory");
    };

    float acc[2][8][4];
#pragma unroll
    for (int i = 0; i < 2; i++)
#pragma unroll
        for (int j = 0; j < 8; j++)
#pragma unroll
            for (int q = 0; q < 4; q++) acc[i][j][q] = 0.f;

    // ldmatrix base addresses (within array 0 / buffer 0)
    const uint32_t aAddr = sb + (wm * 32 + (lane & 15)) * PITCHB + (lane >> 4) * 16;
    const uint32_t bAddr = sb + 2 * ARRB + (wn * 64 + (lane & 15)) * PITCHB + (lane >> 4) * 16;

    load_chunk(0, 0);

    for (int c = 0; c < KCH; c++) {
        int buf = c & 1;
        if (c + 1 < KCH) load_chunk(c + 1, buf ^ 1);
        if (c + 1 < KCH) asm volatile("cp.async.wait_group 1;" ::: "memory");
        else             asm volatile("cp.async.wait_group 0;" ::: "memory");
        __syncthreads();

        uint32_t boff = buf * BUFB;
#pragma unroll
        for (int ks = 0; ks < 2; ks++) {
            uint32_t ah[2][4], al[2][4], bh[4][4], bl[4][4];
#pragma unroll
            for (int mt = 0; mt < 2; mt++) {
                uint32_t a = aAddr + boff + mt * (16 * PITCHB) + ks * 32;
                ldm4(ah[mt], a);
                ldm4(al[mt], a + ARRB);
            }
#pragma unroll
            for (int ng = 0; ng < 4; ng++) {
                uint32_t a = bAddr + boff + ng * (16 * PITCHB) + ks * 32;
                ldm4(bh[ng], a);
                ldm4(bl[ng], a + ARRB);
            }
#pragma unroll
            for (int mt = 0; mt < 2; mt++)
#pragma unroll
                for (int ng = 0; ng < 4; ng++)
#pragma unroll
                    for (int hf = 0; hf < 2; hf++) {
                        int nt = ng * 2 + hf;
                        mma16816(acc[mt][nt], ah[mt], bh[ng][hf], bh[ng][hf + 2]);
                        mma16816(acc[mt][nt], al[mt], bh[ng][hf], bh[ng][hf + 2]);
                        mma16816(acc[mt][nt], ah[mt], bl[ng][hf], bl[ng][hf + 2]);
                    }
        }
        __syncthreads();
    }

    // epilogue: add bias (gru_b row 0), store fp32
    const int qr = lane >> 2, qc = lane & 3;
#pragma unroll
    for (int mt = 0; mt < 2; mt++)
#pragma unroll
        for (int nt = 0; nt < 8; nt++) {
            int nb = n0 + wn * 64 + nt * 8 + 2 * qc;
            float b0 = gb[nb], b1 = gb[nb + 1];
#pragma unroll
            for (int rp = 0; rp < 2; rp++) {
                int m = m0 + wm * 32 + mt * 16 + qr + 8 * rp;
                float2 v = make_float2(acc[mt][nt][2 * rp] + b0,
                                       acc[mt][nt][2 * rp + 1] + b1);
                *(float2*)&g_xp[(size_t)m * XN + nb] = v;
            }
        }
}

// ---------------- GRU step (unchanged from R1, correct & ~4.5 ms total) -------
__global__ void __launch_bounds__(128) k_step(const float* __restrict__ Wr,
                                              const float* __restrict__ gb,
                                              int t, int par) {
    __shared__ float sh[2][32][64];
    __shared__ float sw[2][32][24];
    const float* hp = g_h[par];
    float* hnxt = g_h[par ^ 1];
    const int b0 = blockIdx.y * 64;
    const int u0 = blockIdx.x * 8;
    const int tid = threadIdx.x;
    const int rg = tid >> 3;
    const int cg = tid & 7;
    const int u = u0 + cg;

    float az[4], ar[4], ah[4];
    {
        float bz  = gb[XN + u];
        float brr = gb[XN + 512 + u];
        float bh  = gb[XN + 1024 + u];
#pragma unroll
        for (int i = 0; i < 4; i++) { az[i] = bz; ar[i] = brr; ah[i] = bh; }
    }

    float4 hv[4];
    float wv[6];

    auto loadH = [&](int kc) {
#pragma unroll
        for (int l = 0; l < 4; l++) {
            int q = tid + 128 * l;
            int row = q >> 3;
            int kq = (q & 7) << 2;
            hv[l] = *(const float4*)&hp[(size_t)(b0 + row) * UG + kc + kq];
        }
    };
    auto storeH = [&](int buf) {
#pragma unroll
        for (int l = 0; l < 4; l++) {
            int q = tid + 128 * l;
            int row = q >> 3;
            int kq = (q & 7) << 2;
            int srow = row ^ (((kq >> 2) & 7) << 3);
            sh[buf][kq + 0][srow] = hv[l].x;
            sh[buf][kq + 1][srow] = hv[l].y;
            sh[buf][kq + 2][srow] = hv[l].z;
            sh[buf][kq + 3][srow] = hv[l].w;
        }
    };
    auto loadW = [&](int kc) {
#pragma unroll
        for (int l = 0; l < 6; l++) {
            int e = tid + 128 * l;
            int k = e / 24, c = e % 24;
            int seg = c >> 3, w = c & 7;
            wv[l] = Wr[(size_t)(kc + k) * XN + seg * 512 + u0 + w];
        }
    };
    auto storeW = [&](int buf) {
#pragma unroll
        for (int l = 0; l < 6; l++) {
            int e = tid + 128 * l;
            int k = e / 24, c = e % 24;
            sw[buf][k][c] = wv[l];
        }
    };

    loadH(0); loadW(0);
    storeH(0); storeW(0);
    __syncthreads();

    for (int ch = 0; ch < 16; ch++) {
        int buf = ch & 1;
        if (ch < 15) { loadH((ch + 1) * 32); loadW((ch + 1) * 32); }
#pragma unroll
        for (int k = 0; k < 32; k++) {
            int srow = (rg << 2) ^ (((k >> 2) & 7) << 3);
            float4 h4 = *(const float4*)&sh[buf][k][srow];
            float wz = sw[buf][k][cg];
            float wr2 = sw[buf][k][8 + cg];
            float wh = sw[buf][k][16 + cg];
            az[0] += h4.x * wz;  az[1] += h4.y * wz;  az[2] += h4.z * wz;  az[3] += h4.w * wz;
            ar[0] += h4.x * wr2; ar[1] += h4.y * wr2; ar[2] += h4.z * wr2; ar[3] += h4.w * wr2;
            ah[0] += h4.x * wh;  ah[1] += h4.y * wh;  ah[2] += h4.z * wh;  ah[3] += h4.w * wh;
        }
        __syncthreads();
        if (ch < 15) { storeH(buf ^ 1); storeW(buf ^ 1); __syncthreads(); }
    }

    const float* xp = g_xp + (size_t)t * B * XN;
#pragma unroll
    for (int i = 0; i < 4; i++) {
        int b = b0 + (rg << 2) + i;
        size_t xb = (size_t)b * XN;
        float z  = sigm(xp[xb + u] + az[i]);
        float r  = sigm(xp[xb + 512 + u] + ar[i]);
        float hc = tanhf(xp[xb + 1024 + u] + r * ah[i]);
        float hprev = hp[(size_t)b * UG + u];
        float hn = z * hprev + (1.f - z) * hc;
        hnxt[(size_t)b * UG + u] = hn;
        float* pm = &g_hmax[(size_t)b * UG + u];
        *pm = fmaxf(*pm, hn);
    }
}

// ---------------- epilogue ---------------------------------------------------
__global__ void k_out(const float* __restrict__ Wout, const float* __restrict__ bout,
                      float* __restrict__ dout, int par, int out_size) {
    int b = blockIdx.x;
    int tid = threadIdx.x; // 256
    __shared__ float red[256];
    float s = 0.f;
    for (int uu = tid; uu < UG; uu += 256) s += g_hmax[b * UG + uu] * Wout[uu];
    red[tid] = s;
    __syncthreads();
    for (int o = 128; o > 0; o >>= 1) {
        if (tid < o) red[tid] += red[tid + o];
        __syncthreads();
    }
    if (tid == 0 && b < out_size) dout[b] = eluf(red[0] + bout[0]);
    for (int uu = tid; uu < UG; uu += 256) {
        int idx = B + b * UG + uu;
        if (idx < out_size) dout[idx] = g_h[par][b * UG + uu];
    }
}

// ---------------- launch ------------------------------------------------------
extern "C" void kernel_launch(void* const* d_in, const int* in_sizes, int n_in,
                              void* d_out, int out_size) {
    const float* motion = (const float*)d_in[0];
    const float* robot  = (const float*)d_in[1];
    const float* action = (const float*)d_in[3];
    const float* osc    = (const float*)d_in[4];
    const float* mu     = (const float*)d_in[5];
    const float* mean   = (const float*)d_in[6];
    const float* state  = (const float*)d_in[7];
    const float* W_mot  = (const float*)d_in[8];
    const float* b_mot  = (const float*)d_in[9];
    const float* W_rob  = (const float*)d_in[10];
    const float* b_rob  = (const float*)d_in[11];
    const float* W_comb = (const float*)d_in[12];
    const float* b_comb = (const float*)d_in[13];
    const float* W_oscr = (const float*)d_in[14];
    const float* b_oscr = (const float*)d_in[15];
    const float* W_osci = (const float*)d_in[16];
    const float* b_osci = (const float*)d_in[17];
    const float* gru_k  = (const float*)d_in[18];
    const float* gru_rk = (const float*)d_in[19];
    const float* gru_b  = (const float*)d_in[20];
    const float* W_out  = (const float*)d_in[21];
    const float* b_out  = (const float*)d_in[22];
    float* out = (float*)d_out;

    static bool attr_set = false;
    if (!attr_set) {
        cudaFuncSetAttribute(k_xmma, cudaFuncAttributeMaxDynamicSharedMemorySize, SMEM_GEMM);
        attr_set = true;
    }

    k_msrs<<<B, 256>>>(motion, robot, W_mot, b_mot, W_rob, b_rob);
    k_h0<<<B, 512>>>(state, W_comb, b_comb);
    k_act<<<ROWS, 256>>>(action, mu, mean);
    k_inp2<<<ROWS / 8, 256>>>(osc, W_oscr, b_oscr);
    k_inp3<<<ROWS / 8, 256>>>(W_osci, b_osci);
    k_trb<<<dim3(XN / 32, XK / 32), dim3(32, 8)>>>(gru_k);
    k_xmma<<<dim3(XN / 128, ROWS / 128), 256, SMEM_GEMM>>>(gru_b);
    for (int t = 0; t < T; t++)
        k_step<<<dim3(UG / 8, B / 64), 128>>>(gru_rk, gru_b, t, t & 1);
    // after 512 steps the final h sits in g_h[0]
    k_out<<<B, 256>>>(W_out, b_out, out, 0, out_size);
}

// round 5
// speedup vs baseline: 2.9030x; 2.5422x over previous
#include <cuda_runtime.h>
#include <cuda_bf16.h>
#include <cstdint>
#include <math.h>

namespace {
constexpr int B  = 128;
constexpr int T  = 512;
constexpr int A  = 256;
constexpr int UG = 512;
constexpr int ROWS = B * T;       // 65536
constexpr int XK = 768;           // x feature width
constexpr int XN = 1536;          // 3 * UG
}

// ---------------- scratch (device globals; no allocation allowed) ------------
__device__ float g_x [(size_t)ROWS * XK];              // fp32 x (cols 256:512 used by inp3)
__device__ __nv_bfloat16 g_xh[(size_t)ROWS * XK];      // bf16 hi of x
__device__ __nv_bfloat16 g_xl[(size_t)ROWS * XK];      // bf16 lo of x
__device__ __nv_bfloat16 g_bh[(size_t)XN * XK];        // gru_k^T [N,K] hi
__device__ __nv_bfloat16 g_bl[(size_t)XN * XK];        // gru_k^T [N,K] lo
__device__ __nv_bfloat16 g_rh[(size_t)XN * UG];        // gru_rk^T [1536,512] hi
__device__ __nv_bfloat16 g_rl[(size_t)XN * UG];        // gru_rk^T [1536,512] lo
__device__ float g_xp[(size_t)ROWS * XN];              // x @ gru_k + gru_b[0]
__device__ float g_h0f[B * UG];                        // h0 fp32 / final h
__device__ __nv_bfloat16 g_hh[2][B * UG];              // h ping-pong, bf16 hi
__device__ __nv_bfloat16 g_hl[2][B * UG];              // h ping-pong, bf16 lo
__device__ float g_hmax[B * UG];
__device__ float g_ms[B * 256];
__device__ float g_rs[B * 256];
__device__ unsigned g_bar;                             // grid barrier arrivals (cumulative)
__device__ unsigned g_gen;                             // grid barrier generation

__device__ __forceinline__ float eluf(float v) { return v > 0.f ? v : (expf(v) - 1.f); }
__device__ __forceinline__ float sigm(float v) { return 1.f / (1.f + expf(-v)); }
__device__ __forceinline__ void split_bf16(float v, __nv_bfloat16& h, __nv_bfloat16& l) {
    h = __float2bfloat16(v);
    l = __float2bfloat16(v - __bfloat162float(h));
}

// ---------------- PTX helpers (plain sm_103-safe: no tcgen05) ----------------
__device__ __forceinline__ uint32_t smem_u32(const void* p) {
    uint32_t a;
    asm("{ .reg .u64 t; cvta.to.shared.u64 t, %1; cvt.u32.u64 %0, t; }" : "=r"(a) : "l"(p));
    return a;
}
__device__ __forceinline__ void cpa16(uint32_t s, const void* g) {
    asm volatile("cp.async.cg.shared.global [%0], [%1], 16;" :: "r"(s), "l"(g));
}
__device__ __forceinline__ void ldm4(uint32_t* r, uint32_t a) {
    asm volatile("ldmatrix.sync.aligned.m8n8.x4.shared.b16 {%0,%1,%2,%3}, [%4];"
                 : "=r"(r[0]), "=r"(r[1]), "=r"(r[2]), "=r"(r[3]) : "r"(a));
}
__device__ __forceinline__ void ldm2(uint32_t* r, uint32_t a) {
    asm volatile("ldmatrix.sync.aligned.m8n8.x2.shared.b16 {%0,%1}, [%2];"
                 : "=r"(r[0]), "=r"(r[1]) : "r"(a));
}
__device__ __forceinline__ void mma16816(float* c, const uint32_t* a, uint32_t b0, uint32_t b1) {
    asm volatile(
        "mma.sync.aligned.m16n8k16.row.col.f32.bf16.bf16.f32 "
        "{%0,%1,%2,%3}, {%4,%5,%6,%7}, {%8,%9}, {%0,%1,%2,%3};"
        : "+f"(c[0]), "+f"(c[1]), "+f"(c[2]), "+f"(c[3])
        : "r"(a[0]), "r"(a[1]), "r"(a[2]), "r"(a[3]), "r"(b0), "r"(b1));
}
__device__ __forceinline__ unsigned atomAddRel(unsigned* p, unsigned v) {
    unsigned o;
    asm volatile("atom.release.gpu.global.add.u32 %0, [%1], %2;"
                 : "=r"(o) : "l"(p), "r"(v) : "memory");
    return o;
}
__device__ __forceinline__ void stRel(unsigned* p, unsigned v) {
    asm volatile("st.release.gpu.global.u32 [%0], %1;" :: "l"(p), "r"(v) : "memory");
}
__device__ __forceinline__ unsigned ldAcq(unsigned* p) {
    unsigned v;
    asm volatile("ld.acquire.gpu.global.u32 %0, [%1];" : "=r"(v) : "l"(p) : "memory");
    return v;
}

// ---------------- small front-end kernels -----------------------------------
__global__ void k_reset() { g_bar = 0; g_gen = 0; }

__global__ void k_msrs(const float* __restrict__ motion, const float* __restrict__ robot,
                       const float* __restrict__ Wm, const float* __restrict__ bm,
                       const float* __restrict__ Wr, const float* __restrict__ br) {
    int b = blockIdx.x;
    int j = threadIdx.x; // 256
    __shared__ float sm[64], sr[64];
    if (j < 64) sm[j] = motion[b * 64 + j];
    else if (j < 128) sr[j - 64] = robot[b * 64 + (j - 64)];
    __syncthreads();
    float accm = bm[j], accr = br[j];
    for (int k = 0; k < 64; k++) {
        accm += sm[k] * Wm[k * 256 + j];
        accr += sr[k] * Wr[k * 256 + j];
    }
    g_ms[b * 256 + j] = eluf(accm);
    g_rs[b * 256 + j] = eluf(accr);
}

__global__ void k_h0(const float* __restrict__ state, const float* __restrict__ Wc,
                     const float* __restrict__ bc) {
    int b = blockIdx.x;
    int u = threadIdx.x; // 512
    __shared__ float s[1024];
    s[u] = (u < 256) ? g_ms[b * 256 + u] : g_rs[b * 256 + (u - 256)];
    s[512 + u] = state[b * 512 + u];
    __syncthreads();
    float acc = bc[u];
    for (int k = 0; k < 1024; k++) acc += s[k] * Wc[k * 512 + u];
    float h0 = eluf(acc);
    size_t idx = (size_t)b * 512 + u;
    g_h0f[idx] = h0;
    split_bf16(h0, g_hh[0][idx], g_hl[0][idx]);
}

__global__ void k_act(const float* __restrict__ action, const float* __restrict__ mu,
                      const float* __restrict__ mean) {
    int r = blockIdx.x;
    int t = r >> 7;
    int b = r & 127;
    int a = threadIdx.x;
    float v = action[((size_t)b * T + t) * A + a] * mu[b * A + a] + mean[b * A + a];
    size_t idx = (size_t)r * XK + a;
    split_bf16(v, g_xh[idx], g_xl[idx]);
}

__global__ void k_inp2(const float* __restrict__ osc, const float* __restrict__ W,
                       const float* __restrict__ bias) {
    int r0 = blockIdx.x * 8;
    int j = threadIdx.x; // 256
    __shared__ float s[8][64];
    for (int i = threadIdx.x; i < 8 * 64; i += 256) {
        int rr = i >> 6, k = i & 63;
        int r = r0 + rr;
        int t = r >> 7, b = r & 127;
        s[rr][k] = osc[((size_t)b * T + t) * 128 + k];
    }
    __syncthreads();
    float bj = bias[j];
    float acc[8];
#pragma unroll
    for (int i = 0; i < 8; i++) acc[i] = bj;
    for (int k = 0; k < 64; k++) {
        float w = W[k * 256 + j];
#pragma unroll
        for (int i = 0; i < 8; i++) acc[i] += s[i][k] * w;
    }
#pragma unroll
    for (int i = 0; i < 8; i++) {
        float v = eluf(acc[i]);
        size_t idx = (size_t)(r0 + i) * XK + 256 + j;
        g_x[idx] = v;
        split_bf16(v, g_xh[idx], g_xl[idx]);
    }
}

__global__ void k_inp3(const float* __restrict__ W, const float* __restrict__ bias) {
    int r0 = blockIdx.x * 8;
    int j = threadIdx.x; // 256
    __shared__ float s[8][192];
    for (int i = threadIdx.x; i < 8 * 192; i += 256) {
        int rr = i / 192, k = i % 192;
        s[rr][k] = g_x[(size_t)(r0 + rr) * XK + 320 + k];
    }
    __syncthreads();
    float bj = bias[j];
    float acc[8];
#pragma unroll
    for (int i = 0; i < 8; i++) acc[i] = bj;
    for (int k = 0; k < 192; k++) {
        float w = W[k * 256 + j];
#pragma unroll
        for (int i = 0; i < 8; i++) acc[i] += s[i][k] * w;
    }
#pragma unroll
    for (int i = 0; i < 8; i++) {
        size_t idx = (size_t)(r0 + i) * XK + 512 + j;
        split_bf16(eluf(acc[i]), g_xh[idx], g_xl[idx]);
    }
}

// transpose + split gru_k [768,1536] -> g_bh/g_bl [1536,768]
__global__ void k_trb(const float* __restrict__ gk) {
    __shared__ float s[32][33];
    int n0 = blockIdx.x * 32, k0 = blockIdx.y * 32;
    int tx = threadIdx.x, ty = threadIdx.y; // 32 x 8
#pragma unroll
    for (int i = 0; i < 32; i += 8)
        s[ty + i][tx] = gk[(size_t)(k0 + ty + i) * XN + n0 + tx];
    __syncthreads();
#pragma unroll
    for (int i = 0; i < 32; i += 8) {
        size_t idx = (size_t)(n0 + ty + i) * XK + k0 + tx;
        split_bf16(s[tx][ty + i], g_bh[idx], g_bl[idx]);
    }
}

// transpose + split gru_rk [512,1536] -> g_rh/g_rl [1536,512]
__global__ void k_trw(const float* __restrict__ wr) {
    __shared__ float s[32][33];
    int n0 = blockIdx.x * 32, k0 = blockIdx.y * 32;
    int tx = threadIdx.x, ty = threadIdx.y; // 32 x 8
#pragma unroll
    for (int i = 0; i < 32; i += 8)
        s[ty + i][tx] = wr[(size_t)(k0 + ty + i) * XN + n0 + tx];
    __syncthreads();
#pragma unroll
    for (int i = 0; i < 32; i += 8) {
        size_t idx = (size_t)(n0 + ty + i) * UG + k0 + tx;
        split_bf16(s[tx][ty + i], g_rh[idx], g_rl[idx]);
    }
}

// ---------------- HMMA GEMM: g_xp = x @ gru_k + gru_b[0]  (verified R3) ------
namespace {
constexpr int PITCHB = 80;
constexpr int ARRB   = 128 * PITCHB;
constexpr int BUFB   = 4 * ARRB;
constexpr int SMEM_GEMM = 2 * BUFB;        // 81920
constexpr int KCH = 24;
}

__global__ void __launch_bounds__(256, 1) k_xmma(const float* __restrict__ gb) {
    extern __shared__ char smem[];
    const uint32_t sb = smem_u32(smem);
    const int tid = threadIdx.x;
    const int lane = tid & 31, wid = tid >> 5;
    const int wm = wid & 3;
    const int wn = wid >> 2;
    const int m0 = blockIdx.y * 128;
    const int n0 = blockIdx.x * 128;

    const __nv_bfloat16* gptr[4] = {
        g_xh + (size_t)m0 * XK, g_xl + (size_t)m0 * XK,
        g_bh + (size_t)n0 * XK, g_bl + (size_t)n0 * XK};

    auto load_chunk = [&](int c, int buf) {
        uint32_t base = sb + buf * BUFB;
#pragma unroll
        for (int l = 0; l < 8; l++) {
            int idx = tid + 256 * l;
            int arr = idx >> 9;
            int rem = idx & 511;
            int row = rem >> 2;
            int cch = rem & 3;
            cpa16(base + arr * ARRB + row * PITCHB + cch * 16,
                  gptr[arr] + (size_t)row * XK + c * 32 + cch * 8);
        }
        asm volatile("cp.async.commit_group;" ::: "memory");
    };

    float acc[2][8][4];
#pragma unroll
    for (int i = 0; i < 2; i++)
#pragma unroll
        for (int j = 0; j < 8; j++)
#pragma unroll
            for (int q = 0; q < 4; q++) acc[i][j][q] = 0.f;

    const uint32_t aAddr = sb + (wm * 32 + (lane & 15)) * PITCHB + (lane >> 4) * 16;
    const uint32_t bAddr = sb + 2 * ARRB + (wn * 64 + (lane & 15)) * PITCHB + (lane >> 4) * 16;

    load_chunk(0, 0);

    for (int c = 0; c < KCH; c++) {
        int buf = c & 1;
        if (c + 1 < KCH) load_chunk(c + 1, buf ^ 1);
        if (c + 1 < KCH) asm volatile("cp.async.wait_group 1;" ::: "memory");
        else             asm volatile("cp.async.wait_group 0;" ::: "memory");
        __syncthreads();

        uint32_t boff = buf * BUFB;
#pragma unroll
        for (int ks = 0; ks < 2; ks++) {
            uint32_t ah[2][4], al[2][4], bh[4][4], bl[4][4];
#pragma unroll
            for (int mt = 0; mt < 2; mt++) {
                uint32_t a = aAddr + boff + mt * (16 * PITCHB) + ks * 32;
                ldm4(ah[mt], a);
                ldm4(al[mt], a + ARRB);
            }
#pragma unroll
            for (int ng = 0; ng < 4; ng++) {
                uint32_t a = bAddr + boff + ng * (16 * PITCHB) + ks * 32;
                ldm4(bh[ng], a);
                ldm4(bl[ng], a + ARRB);
            }
#pragma unroll
            for (int mt = 0; mt < 2; mt++)
#pragma unroll
                for (int ng = 0; ng < 4; ng++)
#pragma unroll
                    for (int hf = 0; hf < 2; hf++) {
                        int nt = ng * 2 + hf;
                        mma16816(acc[mt][nt], ah[mt], bh[ng][hf], bh[ng][hf + 2]);
                        mma16816(acc[mt][nt], al[mt], bh[ng][hf], bh[ng][hf + 2]);
                        mma16816(acc[mt][nt], ah[mt], bl[ng][hf], bl[ng][hf + 2]);
                    }
        }
        __syncthreads();
    }

    const int qr = lane >> 2, qc = lane & 3;
#pragma unroll
    for (int mt = 0; mt < 2; mt++)
#pragma unroll
        for (int nt = 0; nt < 8; nt++) {
            int nb = n0 + wn * 64 + nt * 8 + 2 * qc;
            float b0 = gb[nb], b1 = gb[nb + 1];
#pragma unroll
            for (int rp = 0; rp < 2; rp++) {
                int m = m0 + wm * 32 + mt * 16 + qr + 8 * rp;
                float2 v = make_float2(acc[mt][nt][2 * rp] + b0,
                                       acc[mt][nt][2 * rp + 1] + b1);
                *(float2*)&g_xp[(size_t)m * XN + nb] = v;
            }
        }
}

// ---------------- persistent GRU kernel --------------------------------------
// 128 blocks (1/SM), 128 threads. Block owns (32 b-rows x 16 u) -> all 3 gate
// columns per (b,u) in one thread: h_prev & hmax live in registers all 512 steps.
// W_rk slice smem-resident (bf16 hi/lo). h carried as bf16 hi/lo ping-pong in
// global; grid-wide release/acquire barrier between steps.
namespace {
constexpr int NBLK = 128;
constexpr int PITCH = 1040;                    // 512 bf16 + 16B pad (conflict-free ldmatrix)
constexpr int WSEC  = 16 * PITCH;              // 16640 per (gate,hi/lo) section
constexpr int AHI_OFF = 6 * WSEC;              // 99840
constexpr int ALO_OFF = AHI_OFF + 32 * PITCH;  // 133120
constexpr int SMEM_GRU = ALO_OFF + 32 * PITCH; // 166400
}

__global__ void __launch_bounds__(128, 1) k_gru(const float* __restrict__ gb) {
    extern __shared__ char smem[];
    const uint32_t sb = smem_u32(smem);
    const int tid = threadIdx.x, lane = tid & 31, wid = tid >> 5;
    const int bt = blockIdx.x & 3;         // b-tile (32 rows)
    const int ut = blockIdx.x >> 2;        // u-tile (16 u)
    const int u0 = ut * 16;
    const int row0 = bt * 32;
    const int mt = wid & 1;                // m16 tile within 32 rows
    const int uh = wid >> 1;               // u-half (8 u)
    const int qr = lane >> 2, qc = lane & 3;
    const int r1 = row0 + mt * 16 + qr;
    const int r2 = r1 + 8;
    const int uc = u0 + uh * 8 + 2 * qc;   // even global u col

    // ---- W slice -> smem (once): 3 gates x 16 n x 512 k, hi+lo ----
    for (int idx = tid; idx < 6144; idx += 128) {
        int sec = idx >> 10;               // 0..5 = (gate<<1)|lo
        int rem = idx & 1023;
        int r = rem >> 6, ch = rem & 63;
        int g = sec >> 1;
        const __nv_bfloat16* src = (sec & 1) ? g_rl : g_rh;
        cpa16(sb + sec * WSEC + r * PITCH + ch * 16,
              src + ((size_t)(g * 512 + u0 + r)) * UG + ch * 8);
    }
    asm volatile("cp.async.commit_group;" ::: "memory");

    // recurrent biases (gru_b row 1)
    const float* gbr = gb + XN;
    float bzc[2], brc[2], bhc[2];
#pragma unroll
    for (int j = 0; j < 2; j++) {
        bzc[j] = gbr[uc + j];
        brc[j] = gbr[512 + uc + j];
        bhc[j] = gbr[1024 + uc + j];
    }

    // register-resident h_prev / hmax (i = 2*rowpair + j)
    float hprev[4], hmax[4];
    hprev[0] = g_h0f[(size_t)r1 * UG + uc];
    hprev[1] = g_h0f[(size_t)r1 * UG + uc + 1];
    hprev[2] = g_h0f[(size_t)r2 * UG + uc];
    hprev[3] = g_h0f[(size_t)r2 * UG + uc + 1];
#pragma unroll
    for (int i = 0; i < 4; i++) hmax[i] = -INFINITY;

    // ldmatrix bases
    const uint32_t aHi = sb + AHI_OFF + (mt * 16 + (lane & 15)) * PITCH + ((lane >> 4) & 1) * 16;
    const uint32_t aLo = aHi + 32 * PITCH;
    uint32_t bHi[3], bLo[3];
    {
        int brow = uh * 8 + (lane & 7);
        int bch = (lane >> 3) & 1;
#pragma unroll
        for (int g = 0; g < 3; g++) {
            bHi[g] = sb + (2 * g) * WSEC + brow * PITCH + bch * 16;
            bLo[g] = bHi[g] + WSEC;
        }
    }

    auto stageA = [&](int par) {
        const __nv_bfloat16* shp = g_hh[par] + (size_t)row0 * UG;
        const __nv_bfloat16* slp = g_hl[par] + (size_t)row0 * UG;
        for (int idx = tid; idx < 2048; idx += 128) {
            int r = idx >> 6, ch = idx & 63;
            cpa16(sb + AHI_OFF + r * PITCH + ch * 16, shp + (size_t)r * UG + ch * 8);
            cpa16(sb + ALO_OFF + r * PITCH + ch * 16, slp + (size_t)r * UG + ch * 8);
        }
        asm volatile("cp.async.commit_group;" ::: "memory");
    };

    stageA(0);   // h0

    for (int t = 0; t < T; t++) {
        // prefetch xp (independent of barrier)
        const float* xp = g_xp + (size_t)t * ((size_t)B * XN);
        const float* xpr1 = xp + (size_t)r1 * XN;
        const float* xpr2 = xp + (size_t)r2 * XN;
        float2 xz[2], xr[2], xh[2];
        xz[0] = *(const float2*)(xpr1 + uc);        xz[1] = *(const float2*)(xpr2 + uc);
        xr[0] = *(const float2*)(xpr1 + 512 + uc);  xr[1] = *(const float2*)(xpr2 + 512 + uc);
        xh[0] = *(const float2*)(xpr1 + 1024 + uc); xh[1] = *(const float2*)(xpr2 + 1024 + uc);

        asm volatile("cp.async.wait_group 0;" ::: "memory");
        __syncthreads();

        float az[4] = {0.f, 0.f, 0.f, 0.f};
        float ar[4] = {0.f, 0.f, 0.f, 0.f};
        float ah2[4] = {0.f, 0.f, 0.f, 0.f};

#pragma unroll 4
        for (int ks = 0; ks < 32; ks++) {
            uint32_t ahf[4], alf[4];
            ldm4(ahf, aHi + ks * 32);
            ldm4(alf, aLo + ks * 32);
            uint32_t bh[2], bl[2];
            // gate z
            ldm2(bh, bHi[0] + ks * 32); ldm2(bl, bLo[0] + ks * 32);
            mma16816(az, ahf, bh[0], bh[1]);
            mma16816(az, alf, bh[0], bh[1]);
            mma16816(az, ahf, bl[0], bl[1]);
            // gate r
            ldm2(bh, bHi[1] + ks * 32); ldm2(bl, bLo[1] + ks * 32);
            mma16816(ar, ahf, bh[0], bh[1]);
            mma16816(ar, alf, bh[0], bh[1]);
            mma16816(ar, ahf, bl[0], bl[1]);
            // gate h
            ldm2(bh, bHi[2] + ks * 32); ldm2(bl, bLo[2] + ks * 32);
            mma16816(ah2, ahf, bh[0], bh[1]);
            mma16816(ah2, alf, bh[0], bh[1]);
            mma16816(ah2, ahf, bl[0], bl[1]);
        }

        // gates + register h update + bf16 hi/lo stores for next step
        int np = (t + 1) & 1;
        bool notlast = (t + 1 < T);
#pragma unroll
        for (int p = 0; p < 2; p++) {
            float hn[2];
#pragma unroll
            for (int j = 0; j < 2; j++) {
                int i = 2 * p + j;
                float xzv = j ? xz[p].y : xz[p].x;
                float xrv = j ? xr[p].y : xr[p].x;
                float xhv = j ? xh[p].y : xh[p].x;
                float z = sigm(xzv + az[i] + bzc[j]);
                float r = sigm(xrv + ar[i] + brc[j]);
                float hc = tanhf(xhv + r * (ah2[i] + bhc[j]));
                hn[j] = z * hprev[i] + (1.f - z) * hc;
                hprev[i] = hn[j];
                hmax[i] = fmaxf(hmax[i], hn[j]);
            }
            if (notlast) {
                int rowg = p ? r2 : r1;
                __nv_bfloat162 vh, vl;
                __nv_bfloat16 h0b, l0b, h1b, l1b;
                split_bf16(hn[0], h0b, l0b);
                split_bf16(hn[1], h1b, l1b);
                vh.x = h0b; vh.y = h1b;
                vl.x = l0b; vl.y = l1b;
                *(__nv_bfloat162*)&g_hh[np][(size_t)rowg * UG + uc] = vh;
                *(__nv_bfloat162*)&g_hl[np][(size_t)rowg * UG + uc] = vl;
            }
        }

        if (notlast) {
            __threadfence();
            __syncthreads();
            if (tid == 0) {
                unsigned target = (unsigned)(t + 1) * NBLK;
                unsigned old = atomAddRel(&g_bar, 1);
                if (old == target - 1) {
                    stRel(&g_gen, (unsigned)(t + 1));
                } else {
                    int spins = 0;
                    while (ldAcq(&g_gen) < (unsigned)(t + 1)) {
                        if (++spins > 32) asm volatile("nanosleep.u32 64;");
                    }
                }
            }
            __syncthreads();
            stageA(np);
        }
    }

    // final writes: hmax + h_final (fp32)
    float2 v;
    v.x = hmax[0]; v.y = hmax[1]; *(float2*)&g_hmax[(size_t)r1 * UG + uc] = v;
    v.x = hmax[2]; v.y = hmax[3]; *(float2*)&g_hmax[(size_t)r2 * UG + uc] = v;
    v.x = hprev[0]; v.y = hprev[1]; *(float2*)&g_h0f[(size_t)r1 * UG + uc] = v;
    v.x = hprev[2]; v.y = hprev[3]; *(float2*)&g_h0f[(size_t)r2 * UG + uc] = v;
}

// ---------------- epilogue ---------------------------------------------------
__global__ void k_out(const float* __restrict__ Wout, const float* __restrict__ bout,
                      float* __restrict__ dout, int out_size) {
    int b = blockIdx.x;
    int tid = threadIdx.x; // 256
    __shared__ float red[256];
    float s = 0.f;
    for (int uu = tid; uu < UG; uu += 256) s += g_hmax[b * UG + uu] * Wout[uu];
    red[tid] = s;
    __syncthreads();
    for (int o = 128; o > 0; o >>= 1) {
        if (tid < o) red[tid] += red[tid + o];
        __syncthreads();
    }
    if (tid == 0 && b < out_size) dout[b] = eluf(red[0] + bout[0]);
    for (int uu = tid; uu < UG; uu += 256) {
        int idx = B + b * UG + uu;
        if (idx < out_size) dout[idx] = g_h0f[b * UG + uu];
    }
}

// ---------------- launch ------------------------------------------------------
extern "C" void kernel_launch(void* const* d_in, const int* in_sizes, int n_in,
                              void* d_out, int out_size) {
    const float* motion = (const float*)d_in[0];
    const float* robot  = (const float*)d_in[1];
    const float* action = (const float*)d_in[3];
    const float* osc    = (const float*)d_in[4];
    const float* mu     = (const float*)d_in[5];
    const float* mean   = (const float*)d_in[6];
    const float* state  = (const float*)d_in[7];
    const float* W_mot  = (const float*)d_in[8];
    const float* b_mot  = (const float*)d_in[9];
    const float* W_rob  = (const float*)d_in[10];
    const float* b_rob  = (const float*)d_in[11];
    const float* W_comb = (const float*)d_in[12];
    const float* b_comb = (const float*)d_in[13];
    const float* W_oscr = (const float*)d_in[14];
    const float* b_oscr = (const float*)d_in[15];
    const float* W_osci = (const float*)d_in[16];
    const float* b_osci = (const float*)d_in[17];
    const float* gru_k  = (const float*)d_in[18];
    const float* gru_rk = (const float*)d_in[19];
    const float* gru_b  = (const float*)d_in[20];
    const float* W_out  = (const float*)d_in[21];
    const float* b_out  = (const float*)d_in[22];
    float* out = (float*)d_out;

    static bool attr_set = false;
    if (!attr_set) {
        cudaFuncSetAttribute(k_xmma, cudaFuncAttributeMaxDynamicSharedMemorySize, SMEM_GEMM);
        cudaFuncSetAttribute(k_gru, cudaFuncAttributeMaxDynamicSharedMemorySize, SMEM_GRU);
        attr_set = true;
    }

    k_reset<<<1, 1>>>();
    k_msrs<<<B, 256>>>(motion, robot, W_mot, b_mot, W_rob, b_rob);
    k_h0<<<B, 512>>>(state, W_comb, b_comb);
    k_act<<<ROWS, 256>>>(action, mu, mean);
    k_inp2<<<ROWS / 8, 256>>>(osc, W_oscr, b_oscr);
    k_inp3<<<ROWS / 8, 256>>>(W_osci, b_osci);
    k_trb<<<dim3(XN / 32, XK / 32), dim3(32, 8)>>>(gru_k);
    k_trw<<<dim3(XN / 32, UG / 32), dim3(32, 8)>>>(gru_rk);
    k_xmma<<<dim3(XN / 128, ROWS / 128), 256, SMEM_GEMM>>>(gru_b);
    k_gru<<<NBLK, 128, SMEM_GRU>>>(gru_b);
    k_out<<<B, 256>>>(W_out, b_out, out, out_size);
}

// round 6
// speedup vs baseline: 2.9828x; 1.0275x over previous
#include <cuda_runtime.h>
#include <cuda_bf16.h>
#include <cstdint>
#include <math.h>

namespace {
constexpr int B  = 128;
constexpr int T  = 512;
constexpr int A  = 256;
constexpr int UG = 512;
constexpr int ROWS = B * T;       // 65536
constexpr int XK = 768;           // x feature width
constexpr int XN = 1536;          // 3 * UG
}

// ---------------- scratch (device globals; no allocation allowed) ------------
__device__ __nv_bfloat16 g_xh[(size_t)ROWS * XK];      // bf16 hi of x
__device__ __nv_bfloat16 g_xl[(size_t)ROWS * XK];      // bf16 lo of x
__device__ __nv_bfloat16 g_bh[(size_t)XN * XK];        // gru_k^T [N,K] hi
__device__ __nv_bfloat16 g_bl[(size_t)XN * XK];        // gru_k^T [N,K] lo
__device__ __nv_bfloat16 g_rh[(size_t)XN * UG];        // gru_rk^T [1536,512] hi
__device__ __nv_bfloat16 g_rl[(size_t)XN * UG];        // gru_rk^T [1536,512] lo
__device__ float g_xp[(size_t)ROWS * XN];              // x @ gru_k + gru_b[0]
__device__ float g_h0f[B * UG];                        // h0 fp32 / final h
__device__ __nv_bfloat16 g_hh[2][B * UG];              // h ping-pong, bf16 hi
__device__ __nv_bfloat16 g_hl[2][B * UG];              // h ping-pong, bf16 lo
__device__ float g_hmax[B * UG];
__device__ float g_ms[B * 256];
__device__ float g_rs[B * 256];
__device__ unsigned g_bar4[4];                         // per-btile barrier arrivals
__device__ unsigned g_gen4[4];                         // per-btile generation

__device__ __forceinline__ float eluf(float v) { return v > 0.f ? v : (expf(v) - 1.f); }
__device__ __forceinline__ float sigm(float v) { return 1.f / (1.f + expf(-v)); }
__device__ __forceinline__ void split_bf16(float v, __nv_bfloat16& h, __nv_bfloat16& l) {
    h = __float2bfloat16(v);
    l = __float2bfloat16(v - __bfloat162float(h));
}

// ---------------- PTX helpers (plain sm_103-safe) -----------------------------
__device__ __forceinline__ uint32_t smem_u32(const void* p) {
    uint32_t a;
    asm("{ .reg .u64 t; cvta.to.shared.u64 t, %1; cvt.u32.u64 %0, t; }" : "=r"(a) : "l"(p));
    return a;
}
__device__ __forceinline__ void cpa16(uint32_t s, const void* g) {
    asm volatile("cp.async.cg.shared.global [%0], [%1], 16;" :: "r"(s), "l"(g));
}
__device__ __forceinline__ void ldm4(uint32_t* r, uint32_t a) {
    asm volatile("ldmatrix.sync.aligned.m8n8.x4.shared.b16 {%0,%1,%2,%3}, [%4];"
                 : "=r"(r[0]), "=r"(r[1]), "=r"(r[2]), "=r"(r[3]) : "r"(a));
}
__device__ __forceinline__ void mma16816(float* c, const uint32_t* a, uint32_t b0, uint32_t b1) {
    asm volatile(
        "mma.sync.aligned.m16n8k16.row.col.f32.bf16.bf16.f32 "
        "{%0,%1,%2,%3}, {%4,%5,%6,%7}, {%8,%9}, {%0,%1,%2,%3};"
        : "+f"(c[0]), "+f"(c[1]), "+f"(c[2]), "+f"(c[3])
        : "r"(a[0]), "r"(a[1]), "r"(a[2]), "r"(a[3]), "r"(b0), "r"(b1));
}
__device__ __forceinline__ unsigned atomAddRel(unsigned* p, unsigned v) {
    unsigned o;
    asm volatile("atom.release.gpu.global.add.u32 %0, [%1], %2;"
                 : "=r"(o) : "l"(p), "r"(v) : "memory");
    return o;
}
__device__ __forceinline__ void stRel(unsigned* p, unsigned v) {
    asm volatile("st.release.gpu.global.u32 [%0], %1;" :: "l"(p), "r"(v) : "memory");
}
__device__ __forceinline__ unsigned ldAcq(unsigned* p) {
    unsigned v;
    asm volatile("ld.acquire.gpu.global.u32 %0, [%1];" : "=r"(v) : "l"(p) : "memory");
    return v;
}

// ---------------- small front-end kernels -----------------------------------
__global__ void k_reset() {
    int i = threadIdx.x;
    if (i < 4) { g_bar4[i] = 0; g_gen4[i] = 0; }
}

__global__ void k_msrs(const float* __restrict__ motion, const float* __restrict__ robot,
                       const float* __restrict__ Wm, const float* __restrict__ bm,
                       const float* __restrict__ Wr, const float* __restrict__ br) {
    int b = blockIdx.x;
    int j = threadIdx.x; // 256
    __shared__ float sm[64], sr[64];
    if (j < 64) sm[j] = motion[b * 64 + j];
    else if (j < 128) sr[j - 64] = robot[b * 64 + (j - 64)];
    __syncthreads();
    float accm = bm[j], accr = br[j];
    for (int k = 0; k < 64; k++) {
        accm += sm[k] * Wm[k * 256 + j];
        accr += sr[k] * Wr[k * 256 + j];
    }
    g_ms[b * 256 + j] = eluf(accm);
    g_rs[b * 256 + j] = eluf(accr);
}

__global__ void k_h0(const float* __restrict__ state, const float* __restrict__ Wc,
                     const float* __restrict__ bc) {
    int b = blockIdx.x;
    int u = threadIdx.x; // 512
    __shared__ float s[1024];
    s[u] = (u < 256) ? g_ms[b * 256 + u] : g_rs[b * 256 + (u - 256)];
    s[512 + u] = state[b * 512 + u];
    __syncthreads();
    float acc = bc[u];
    for (int k = 0; k < 1024; k++) acc += s[k] * Wc[k * 512 + u];
    float h0 = eluf(acc);
    size_t idx = (size_t)b * 512 + u;
    g_h0f[idx] = h0;
    split_bf16(h0, g_hh[0][idx], g_hl[0][idx]);
}

__global__ void k_act(const float* __restrict__ action, const float* __restrict__ mu,
                      const float* __restrict__ mean) {
    int r = blockIdx.x;
    int t = r >> 7;
    int b = r & 127;
    int a = threadIdx.x;
    float v = action[((size_t)b * T + t) * A + a] * mu[b * A + a] + mean[b * A + a];
    size_t idx = (size_t)r * XK + a;
    split_bf16(v, g_xh[idx], g_xl[idx]);
}

// fused: inp2 = elu(osc[..., :64] @ W_oscr + b), inp3 = elu(inp2[..., 64:] @ W_osci + b)
__global__ void k_inp23(const float* __restrict__ osc,
                        const float* __restrict__ W2, const float* __restrict__ b2,
                        const float* __restrict__ W3, const float* __restrict__ b3) {
    int r0 = blockIdx.x * 8;
    int j = threadIdx.x; // 256
    __shared__ float sin_[8][64];
    __shared__ float smid[8][256];
    for (int i = threadIdx.x; i < 8 * 64; i += 256) {
        int rr = i >> 6, k = i & 63;
        int r = r0 + rr;
        int t = r >> 7, b = r & 127;
        sin_[rr][k] = osc[((size_t)b * T + t) * 128 + k];
    }
    __syncthreads();
    {
        float bj = b2[j];
        float acc[8];
#pragma unroll
        for (int i = 0; i < 8; i++) acc[i] = bj;
        for (int k = 0; k < 64; k++) {
            float w = W2[k * 256 + j];
#pragma unroll
            for (int i = 0; i < 8; i++) acc[i] += sin_[i][k] * w;
        }
#pragma unroll
        for (int i = 0; i < 8; i++) {
            float v = eluf(acc[i]);
            smid[i][j] = v;
            size_t idx = (size_t)(r0 + i) * XK + 256 + j;
            split_bf16(v, g_xh[idx], g_xl[idx]);
        }
    }
    __syncthreads();
    {
        float bj = b3[j];
        float acc[8];
#pragma unroll
        for (int i = 0; i < 8; i++) acc[i] = bj;
        for (int k = 0; k < 192; k++) {
            float w = W3[k * 256 + j];
#pragma unroll
            for (int i = 0; i < 8; i++) acc[i] += smid[i][64 + k] * w;
        }
#pragma unroll
        for (int i = 0; i < 8; i++) {
            size_t idx = (size_t)(r0 + i) * XK + 512 + j;
            split_bf16(eluf(acc[i]), g_xh[idx], g_xl[idx]);
        }
    }
}

// transpose + split gru_k [768,1536] -> g_bh/g_bl [1536,768]
__global__ void k_trb(const float* __restrict__ gk) {
    __shared__ float s[32][33];
    int n0 = blockIdx.x * 32, k0 = blockIdx.y * 32;
    int tx = threadIdx.x, ty = threadIdx.y; // 32 x 8
#pragma unroll
    for (int i = 0; i < 32; i += 8)
        s[ty + i][tx] = gk[(size_t)(k0 + ty + i) * XN + n0 + tx];
    __syncthreads();
#pragma unroll
    for (int i = 0; i < 32; i += 8) {
        size_t idx = (size_t)(n0 + ty + i) * XK + k0 + tx;
        split_bf16(s[tx][ty + i], g_bh[idx], g_bl[idx]);
    }
}

// transpose + split gru_rk [512,1536] -> g_rh/g_rl [1536,512]
__global__ void k_trw(const float* __restrict__ wr) {
    __shared__ float s[32][33];
    int n0 = blockIdx.x * 32, k0 = blockIdx.y * 32;
    int tx = threadIdx.x, ty = threadIdx.y; // 32 x 8
#pragma unroll
    for (int i = 0; i < 32; i += 8)
        s[ty + i][tx] = wr[(size_t)(k0 + ty + i) * XN + n0 + tx];
    __syncthreads();
#pragma unroll
    for (int i = 0; i < 32; i += 8) {
        size_t idx = (size_t)(n0 + ty + i) * UG + k0 + tx;
        split_bf16(s[tx][ty + i], g_rh[idx], g_rl[idx]);
    }
}

// ---------------- HMMA GEMM: g_xp = x @ gru_k + gru_b[0] ---------------------
// 3-term split-bf16, 128x128 tile, K-chunk 32, 3-stage cp.async pipeline,
// one syncthreads per chunk.
namespace {
constexpr int PITCHB = 80;
constexpr int ARRB   = 128 * PITCHB;       // 10240
constexpr int BUFB   = 4 * ARRB;           // 40960
constexpr int SMEM_GEMM = 3 * BUFB;        // 122880
constexpr int KCH = 24;
}

__global__ void __launch_bounds__(256, 1) k_xmma(const float* __restrict__ gb) {
    extern __shared__ char smem[];
    const uint32_t sb = smem_u32(smem);
    const int tid = threadIdx.x;
    const int lane = tid & 31, wid = tid >> 5;
    const int wm = wid & 3;
    const int wn = wid >> 2;
    const int m0 = blockIdx.y * 128;
    const int n0 = blockIdx.x * 128;

    const __nv_bfloat16* gptr[4] = {
        g_xh + (size_t)m0 * XK, g_xl + (size_t)m0 * XK,
        g_bh + (size_t)n0 * XK, g_bl + (size_t)n0 * XK};

    auto load_chunk = [&](int c, int buf) {
        uint32_t base = sb + buf * BUFB;
#pragma unroll
        for (int l = 0; l < 8; l++) {
            int idx = tid + 256 * l;
            int arr = idx >> 9;
            int rem = idx & 511;
            int row = rem >> 2;
            int cch = rem & 3;
            cpa16(base + arr * ARRB + row * PITCHB + cch * 16,
                  gptr[arr] + (size_t)row * XK + c * 32 + cch * 8);
        }
        asm volatile("cp.async.commit_group;" ::: "memory");
    };

    float acc[2][8][4];
#pragma unroll
    for (int i = 0; i < 2; i++)
#pragma unroll
        for (int j = 0; j < 8; j++)
#pragma unroll
            for (int q = 0; q < 4; q++) acc[i][j][q] = 0.f;

    const uint32_t aAddr = sb + (wm * 32 + (lane & 15)) * PITCHB + (lane >> 4) * 16;
    const uint32_t bAddr = sb + 2 * ARRB + (wn * 64 + (lane & 15)) * PITCHB + (lane >> 4) * 16;

    load_chunk(0, 0);
    load_chunk(1, 1);

    for (int c = 0; c < KCH; c++) {
        if (c + 1 < KCH) asm volatile("cp.async.wait_group 1;" ::: "memory");
        else             asm volatile("cp.async.wait_group 0;" ::: "memory");
        __syncthreads();
        if (c + 2 < KCH) load_chunk(c + 2, (c + 2) % 3);

        uint32_t boff = (c % 3) * BUFB;
#pragma unroll
        for (int ks = 0; ks < 2; ks++) {
            uint32_t ah[2][4], al[2][4], bh[4][4], bl[4][4];
#pragma unroll
            for (int mt = 0; mt < 2; mt++) {
                uint32_t a = aAddr + boff + mt * (16 * PITCHB) + ks * 32;
                ldm4(ah[mt], a);
                ldm4(al[mt], a + ARRB);
            }
#pragma unroll
            for (int ng = 0; ng < 4; ng++) {
                uint32_t a = bAddr + boff + ng * (16 * PITCHB) + ks * 32;
                ldm4(bh[ng], a);
                ldm4(bl[ng], a + ARRB);
            }
#pragma unroll
            for (int mt = 0; mt < 2; mt++)
#pragma unroll
                for (int ng = 0; ng < 4; ng++)
#pragma unroll
                    for (int hf = 0; hf < 2; hf++) {
                        int nt = ng * 2 + hf;
                        mma16816(acc[mt][nt], ah[mt], bh[ng][hf], bh[ng][hf + 2]);
                        mma16816(acc[mt][nt], al[mt], bh[ng][hf], bh[ng][hf + 2]);
                        mma16816(acc[mt][nt], ah[mt], bl[ng][hf], bl[ng][hf + 2]);
                    }
        }
    }

    const int qr = lane >> 2, qc = lane & 3;
#pragma unroll
    for (int mt = 0; mt < 2; mt++)
#pragma unroll
        for (int nt = 0; nt < 8; nt++) {
            int nb = n0 + wn * 64 + nt * 8 + 2 * qc;
            float b0 = gb[nb], b1 = gb[nb + 1];
#pragma unroll
            for (int rp = 0; rp < 2; rp++) {
                int m = m0 + wm * 32 + mt * 16 + qr + 8 * rp;
                float2 v = make_float2(acc[mt][nt][2 * rp] + b0,
                                       acc[mt][nt][2 * rp + 1] + b1);
                *(float2*)&g_xp[(size_t)m * XN + nb] = v;
            }
        }
}

// ---------------- persistent GRU kernel --------------------------------------
// 128 blocks, 128 threads; block owns (32 b x 16 u). h_prev/hmax in registers.
// Per-btile grid barrier (32 arrivals). xp(t+1) prefetched before the barrier.
namespace {
constexpr int PITCH = 1040;
constexpr int WSEC  = 16 * PITCH;              // 16640
constexpr int AHI_OFF = 6 * WSEC;              // 99840
constexpr int ALO_OFF = AHI_OFF + 32 * PITCH;  // 133120
constexpr int SMEM_GRU = ALO_OFF + 32 * PITCH; // 166400
constexpr int NBLK_BT = 32;                    // blocks per b-tile barrier
}

__global__ void __launch_bounds__(128, 1) k_gru(const float* __restrict__ gb) {
    extern __shared__ char smem[];
    const uint32_t sb = smem_u32(smem);
    const int tid = threadIdx.x, lane = tid & 31, wid = tid >> 5;
    const int bt = blockIdx.x & 3;
    const int ut = blockIdx.x >> 2;
    const int u0 = ut * 16;
    const int row0 = bt * 32;
    const int mt = wid & 1;
    const int uh = wid >> 1;
    const int qr = lane >> 2, qc = lane & 3;
    const int r1 = row0 + mt * 16 + qr;
    const int r2 = r1 + 8;
    const int uc = u0 + uh * 8 + 2 * qc;

    // ---- W slice -> smem (once) ----
    for (int idx = tid; idx < 6144; idx += 128) {
        int sec = idx >> 10;
        int rem = idx & 1023;
        int r = rem >> 6, ch = rem & 63;
        int g = sec >> 1;
        const __nv_bfloat16* src = (sec & 1) ? g_rl : g_rh;
        cpa16(sb + sec * WSEC + r * PITCH + ch * 16,
              src + ((size_t)(g * 512 + u0 + r)) * UG + ch * 8);
    }
    asm volatile("cp.async.commit_group;" ::: "memory");

    const float* gbr = gb + XN;
    float bzc[2], brc[2], bhc[2];
#pragma unroll
    for (int j = 0; j < 2; j++) {
        bzc[j] = gbr[uc + j];
        brc[j] = gbr[512 + uc + j];
        bhc[j] = gbr[1024 + uc + j];
    }

    float hprev[4], hmax[4];
    hprev[0] = g_h0f[(size_t)r1 * UG + uc];
    hprev[1] = g_h0f[(size_t)r1 * UG + uc + 1];
    hprev[2] = g_h0f[(size_t)r2 * UG + uc];
    hprev[3] = g_h0f[(size_t)r2 * UG + uc + 1];
#pragma unroll
    for (int i = 0; i < 4; i++) hmax[i] = -INFINITY;

    // ldmatrix bases
    const uint32_t aHi = sb + AHI_OFF + (mt * 16 + (lane & 15)) * PITCH + ((lane >> 4) & 1) * 16;
    const uint32_t aLo = aHi + 32 * PITCH;
    uint32_t bHi[3], bLo[3];
    {
        int brow = uh * 8 + (lane & 7);
        int bch = lane >> 3;               // 0..3 -> x4 spans k32
#pragma unroll
        for (int g = 0; g < 3; g++) {
            bHi[g] = sb + (2 * g) * WSEC + brow * PITCH + bch * 16;
            bLo[g] = bHi[g] + WSEC;
        }
    }

    auto stageA = [&](int par) {
        const __nv_bfloat16* shp = g_hh[par] + (size_t)row0 * UG;
        const __nv_bfloat16* slp = g_hl[par] + (size_t)row0 * UG;
        for (int idx = tid; idx < 2048; idx += 128) {
            int r = idx >> 6, ch = idx & 63;
            cpa16(sb + AHI_OFF + r * PITCH + ch * 16, shp + (size_t)r * UG + ch * 8);
            cpa16(sb + ALO_OFF + r * PITCH + ch * 16, slp + (size_t)r * UG + ch * 8);
        }
        asm volatile("cp.async.commit_group;" ::: "memory");
    };

    stageA(0);

    // xp(0) prefetch
    float2 xz[2], xr[2], xh[2];
    {
        const float* xpr1 = g_xp + (size_t)r1 * XN;
        const float* xpr2 = g_xp + (size_t)r2 * XN;
        xz[0] = *(const float2*)(xpr1 + uc);        xz[1] = *(const float2*)(xpr2 + uc);
        xr[0] = *(const float2*)(xpr1 + 512 + uc);  xr[1] = *(const float2*)(xpr2 + 512 + uc);
        xh[0] = *(const float2*)(xpr1 + 1024 + uc); xh[1] = *(const float2*)(xpr2 + 1024 + uc);
    }

    unsigned* barp = &g_bar4[bt];
    unsigned* genp = &g_gen4[bt];

    for (int t = 0; t < T; t++) {
        asm volatile("cp.async.wait_group 0;" ::: "memory");
        __syncthreads();

        float az[4] = {0.f, 0.f, 0.f, 0.f};
        float ar[4] = {0.f, 0.f, 0.f, 0.f};
        float ah2[4] = {0.f, 0.f, 0.f, 0.f};

#pragma unroll 4
        for (int j = 0; j < 16; j++) {      // k32 per iteration
            uint32_t ah0[4], ah1[4], al0[4], al1[4];
            uint32_t a = aHi + j * 64;
            ldm4(ah0, a);
            ldm4(ah1, a + 32);
            uint32_t al = aLo + j * 64;
            ldm4(al0, al);
            ldm4(al1, al + 32);
            uint32_t b4h[4], b4l[4];
            // gate z
            ldm4(b4h, bHi[0] + j * 64); ldm4(b4l, bLo[0] + j * 64);
            mma16816(az, ah0, b4h[0], b4h[1]);
            mma16816(az, al0, b4h[0], b4h[1]);
            mma16816(az, ah0, b4l[0], b4l[1]);
            mma16816(az, ah1, b4h[2], b4h[3]);
            mma16816(az, al1, b4h[2], b4h[3]);
            mma16816(az, ah1, b4l[2], b4l[3]);
            // gate r
            ldm4(b4h, bHi[1] + j * 64); ldm4(b4l, bLo[1] + j * 64);
            mma16816(ar, ah0, b4h[0], b4h[1]);
            mma16816(ar, al0, b4h[0], b4h[1]);
            mma16816(ar, ah0, b4l[0], b4l[1]);
            mma16816(ar, ah1, b4h[2], b4h[3]);
            mma16816(ar, al1, b4h[2], b4h[3]);
            mma16816(ar, ah1, b4l[2], b4l[3]);
            // gate h
            ldm4(b4h, bHi[2] + j * 64); ldm4(b4l, bLo[2] + j * 64);
            mma16816(ah2, ah0, b4h[0], b4h[1]);
            mma16816(ah2, al0, b4h[0], b4h[1]);
            mma16816(ah2, ah0, b4l[0], b4l[1]);
            mma16816(ah2, ah1, b4h[2], b4h[3]);
            mma16816(ah2, al1, b4h[2], b4h[3]);
            mma16816(ah2, ah1, b4l[2], b4l[3]);
        }

        int np = (t + 1) & 1;
        bool notlast = (t + 1 < T);
#pragma unroll
        for (int p = 0; p < 2; p++) {
            float hn[2];
#pragma unroll
            for (int j = 0; j < 2; j++) {
                int i = 2 * p + j;
                float xzv = j ? xz[p].y : xz[p].x;
                float xrv = j ? xr[p].y : xr[p].x;
                float xhv = j ? xh[p].y : xh[p].x;
                float z = sigm(xzv + az[i] + bzc[j]);
                float r = sigm(xrv + ar[i] + brc[j]);
                float hc = tanhf(xhv + r * (ah2[i] + bhc[j]));
                hn[j] = z * hprev[i] + (1.f - z) * hc;
                hprev[i] = hn[j];
                hmax[i] = fmaxf(hmax[i], hn[j]);
            }
            if (notlast) {
                int rowg = p ? r2 : r1;
                __nv_bfloat162 vh, vl;
                __nv_bfloat16 h0b, l0b, h1b, l1b;
                split_bf16(hn[0], h0b, l0b);
                split_bf16(hn[1], h1b, l1b);
                vh.x = h0b; vh.y = h1b;
                vl.x = l0b; vl.y = l1b;
                *(__nv_bfloat162*)&g_hh[np][(size_t)rowg * UG + uc] = vh;
                *(__nv_bfloat162*)&g_hl[np][(size_t)rowg * UG + uc] = vl;
            }
        }

        if (notlast) {
            // prefetch xp(t+1) while the barrier settles
            {
                const float* xp = g_xp + (size_t)(t + 1) * ((size_t)B * XN);
                const float* xpr1 = xp + (size_t)r1 * XN;
                const float* xpr2 = xp + (size_t)r2 * XN;
                xz[0] = *(const float2*)(xpr1 + uc);        xz[1] = *(const float2*)(xpr2 + uc);
                xr[0] = *(const float2*)(xpr1 + 512 + uc);  xr[1] = *(const float2*)(xpr2 + 512 + uc);
                xh[0] = *(const float2*)(xpr1 + 1024 + uc); xh[1] = *(const float2*)(xpr2 + 1024 + uc);
            }
            __syncthreads();   // all h-stores in CTA done
            if (tid == 0) {
                unsigned target = (unsigned)(t + 1) * NBLK_BT;
                unsigned old = atomAddRel(barp, 1);
                if (old == target - 1) {
                    stRel(genp, (unsigned)(t + 1));
                } else {
                    int spins = 0;
                    while (ldAcq(genp) < (unsigned)(t + 1)) {
                        if (++spins > 64) asm volatile("nanosleep.u32 64;");
                    }
                }
            }
            __syncthreads();
            stageA(np);
        }
    }

    float2 v;
    v.x = hmax[0]; v.y = hmax[1]; *(float2*)&g_hmax[(size_t)r1 * UG + uc] = v;
    v.x = hmax[2]; v.y = hmax[3]; *(float2*)&g_hmax[(size_t)r2 * UG + uc] = v;
    v.x = hprev[0]; v.y = hprev[1]; *(float2*)&g_h0f[(size_t)r1 * UG + uc] = v;
    v.x = hprev[2]; v.y = hprev[3]; *(float2*)&g_h0f[(size_t)r2 * UG + uc] = v;
}

// ---------------- epilogue ---------------------------------------------------
__global__ void k_out(const float* __restrict__ Wout, const float* __restrict__ bout,
                      float* __restrict__ dout, int out_size) {
    int b = blockIdx.x;
    int tid = threadIdx.x; // 256
    __shared__ float red[256];
    float s = 0.f;
    for (int uu = tid; uu < UG; uu += 256) s += g_hmax[b * UG + uu] * Wout[uu];
    red[tid] = s;
    __syncthreads();
    for (int o = 128; o > 0; o >>= 1) {
        if (tid < o) red[tid] += red[tid + o];
        __syncthreads();
    }
    if (tid == 0 && b < out_size) dout[b] = eluf(red[0] + bout[0]);
    for (int uu = tid; uu < UG; uu += 256) {
        int idx = B + b * UG + uu;
        if (idx < out_size) dout[idx] = g_h0f[b * UG + uu];
    }
}

// ---------------- launch ------------------------------------------------------
extern "C" void kernel_launch(void* const* d_in, const int* in_sizes, int n_in,
                              void* d_out, int out_size) {
    const float* motion = (const float*)d_in[0];
    const float* robot  = (const float*)d_in[1];
    const float* action = (const float*)d_in[3];
    const float* osc    = (const float*)d_in[4];
    const float* mu     = (const float*)d_in[5];
    const float* mean   = (const float*)d_in[6];
    const float* state  = (const float*)d_in[7];
    const float* W_mot  = (const float*)d_in[8];
    const float* b_mot  = (const float*)d_in[9];
    const float* W_rob  = (const float*)d_in[10];
    const float* b_rob  = (const float*)d_in[11];
    const float* W_comb = (const float*)d_in[12];
    const float* b_comb = (const float*)d_in[13];
    const float* W_oscr = (const float*)d_in[14];
    const float* b_oscr = (const float*)d_in[15];
    const float* W_osci = (const float*)d_in[16];
    const float* b_osci = (const float*)d_in[17];
    const float* gru_k  = (const float*)d_in[18];
    const float* gru_rk = (const float*)d_in[19];
    const float* gru_b  = (const float*)d_in[20];
    const float* W_out  = (const float*)d_in[21];
    const float* b_out  = (const float*)d_in[22];
    float* out = (float*)d_out;

    static bool attr_set = false;
    if (!attr_set) {
        cudaFuncSetAttribute(k_xmma, cudaFuncAttributeMaxDynamicSharedMemorySize, SMEM_GEMM);
        cudaFuncSetAttribute(k_gru, cudaFuncAttributeMaxDynamicSharedMemorySize, SMEM_GRU);
        attr_set = true;
    }

    k_reset<<<1, 32>>>();
    k_msrs<<<B, 256>>>(motion, robot, W_mot, b_mot, W_rob, b_rob);
    k_h0<<<B, 512>>>(state, W_comb, b_comb);
    k_act<<<ROWS, 256>>>(action, mu, mean);
    k_inp23<<<ROWS / 8, 256>>>(osc, W_oscr, b_oscr, W_osci, b_osci);
    k_trb<<<dim3(XN / 32, XK / 32), dim3(32, 8)>>>(gru_k);
    k_trw<<<dim3(XN / 32, UG / 32), dim3(32, 8)>>>(gru_rk);
    k_xmma<<<dim3(XN / 128, ROWS / 128), 256, SMEM_GEMM>>>(gru_b);
    k_gru<<<128, 128, SMEM_GRU>>>(gru_b);
    k_out<<<B, 256>>>(W_out, b_out, out, out_size);
}

// round 7
// speedup vs baseline: 3.0021x; 1.0064x over previous
#include <cuda_runtime.h>
#include <cuda_bf16.h>
#include <cstdint>
#include <math.h>

namespace {
constexpr int B  = 128;
constexpr int T  = 512;
constexpr int A  = 256;
constexpr int UG = 512;
constexpr int ROWS = B * T;       // 65536
constexpr int XK = 768;           // x feature width
constexpr int XN = 1536;          // 3 * UG
}

// ---------------- scratch (device globals; no allocation allowed) ------------
__device__ __nv_bfloat16 g_xh[(size_t)ROWS * XK];      // bf16 hi of x
__device__ __nv_bfloat16 g_xl[(size_t)ROWS * XK];      // bf16 lo of x
__device__ __nv_bfloat16 g_bh[(size_t)XN * XK];        // gru_k^T [N,K] hi
__device__ __nv_bfloat16 g_bl[(size_t)XN * XK];        // gru_k^T [N,K] lo
__device__ __nv_bfloat16 g_rh[(size_t)XN * UG];        // gru_rk^T [1536,512] hi
__device__ __nv_bfloat16 g_rl[(size_t)XN * UG];        // gru_rk^T [1536,512] lo
__device__ float g_xp[(size_t)ROWS * XN];              // x @ gru_k + gru_b[0]
__device__ float g_h0f[B * UG];                        // h0 fp32 / final h
__device__ __nv_bfloat16 g_hh[2][B * UG];              // h ping-pong, bf16 hi
__device__ __nv_bfloat16 g_hl[2][B * UG];              // h ping-pong, bf16 lo
__device__ float g_hmax[B * UG];
__device__ float g_ms[B * 256];
__device__ float g_rs[B * 256];
__device__ unsigned g_bar4[4];                         // per-btile barrier arrivals
__device__ unsigned g_gen4[4];                         // per-btile generation

__device__ __forceinline__ float eluf(float v) { return v > 0.f ? v : (expf(v) - 1.f); }
__device__ __forceinline__ float sigm(float v) { return 1.f / (1.f + expf(-v)); }
__device__ __forceinline__ void split_bf16(float v, __nv_bfloat16& h, __nv_bfloat16& l) {
    h = __float2bfloat16(v);
    l = __float2bfloat16(v - __bfloat162float(h));
}

// ---------------- PTX helpers (plain sm_103-safe) -----------------------------
__device__ __forceinline__ uint32_t smem_u32(const void* p) {
    uint32_t a;
    asm("{ .reg .u64 t; cvta.to.shared.u64 t, %1; cvt.u32.u64 %0, t; }" : "=r"(a) : "l"(p));
    return a;
}
__device__ __forceinline__ void cpa16(uint32_t s, const void* g) {
    asm volatile("cp.async.cg.shared.global [%0], [%1], 16;" :: "r"(s), "l"(g));
}
__device__ __forceinline__ void ldm4(uint32_t* r, uint32_t a) {
    asm volatile("ldmatrix.sync.aligned.m8n8.x4.shared.b16 {%0,%1,%2,%3}, [%4];"
                 : "=r"(r[0]), "=r"(r[1]), "=r"(r[2]), "=r"(r[3]) : "r"(a));
}
__device__ __forceinline__ void mma16816(float* c, const uint32_t* a, uint32_t b0, uint32_t b1) {
    asm volatile(
        "mma.sync.aligned.m16n8k16.row.col.f32.bf16.bf16.f32 "
        "{%0,%1,%2,%3}, {%4,%5,%6,%7}, {%8,%9}, {%0,%1,%2,%3};"
        : "+f"(c[0]), "+f"(c[1]), "+f"(c[2]), "+f"(c[3])
        : "r"(a[0]), "r"(a[1]), "r"(a[2]), "r"(a[3]), "r"(b0), "r"(b1));
}
__device__ __forceinline__ unsigned atomAddRel(unsigned* p, unsigned v) {
    unsigned o;
    asm volatile("atom.release.gpu.global.add.u32 %0, [%1], %2;"
                 : "=r"(o) : "l"(p), "r"(v) : "memory");
    return o;
}
__device__ __forceinline__ void stRel(unsigned* p, unsigned v) {
    asm volatile("st.release.gpu.global.u32 [%0], %1;" :: "l"(p), "r"(v) : "memory");
}
__device__ __forceinline__ unsigned ldAcq(unsigned* p) {
    unsigned v;
    asm volatile("ld.acquire.gpu.global.u32 %0, [%1];" : "=r"(v) : "l"(p) : "memory");
    return v;
}

// ---------------- small front-end kernels -----------------------------------
__global__ void k_reset() {
    int i = threadIdx.x;
    if (i < 4) { g_bar4[i] = 0; g_gen4[i] = 0; }
}

__global__ void k_msrs(const float* __restrict__ motion, const float* __restrict__ robot,
                       const float* __restrict__ Wm, const float* __restrict__ bm,
                       const float* __restrict__ Wr, const float* __restrict__ br) {
    int b = blockIdx.x;
    int j = threadIdx.x; // 256
    __shared__ float sm[64], sr[64];
    if (j < 64) sm[j] = motion[b * 64 + j];
    else if (j < 128) sr[j - 64] = robot[b * 64 + (j - 64)];
    __syncthreads();
    float accm = bm[j], accr = br[j];
    for (int k = 0; k < 64; k++) {
        accm += sm[k] * Wm[k * 256 + j];
        accr += sr[k] * Wr[k * 256 + j];
    }
    g_ms[b * 256 + j] = eluf(accm);
    g_rs[b * 256 + j] = eluf(accr);
}

__global__ void k_h0(const float* __restrict__ state, const float* __restrict__ Wc,
                     const float* __restrict__ bc) {
    int b = blockIdx.x;
    int u = threadIdx.x; // 512
    __shared__ float s[1024];
    s[u] = (u < 256) ? g_ms[b * 256 + u] : g_rs[b * 256 + (u - 256)];
    s[512 + u] = state[b * 512 + u];
    __syncthreads();
    float acc = bc[u];
    for (int k = 0; k < 1024; k++) acc += s[k] * Wc[k * 512 + u];
    float h0 = eluf(acc);
    size_t idx = (size_t)b * 512 + u;
    g_h0f[idx] = h0;
    split_bf16(h0, g_hh[0][idx], g_hl[0][idx]);
}

__global__ void k_act(const float* __restrict__ action, const float* __restrict__ mu,
                      const float* __restrict__ mean) {
    int r = blockIdx.x;
    int t = r >> 7;
    int b = r & 127;
    int a = threadIdx.x;
    float v = action[((size_t)b * T + t) * A + a] * mu[b * A + a] + mean[b * A + a];
    size_t idx = (size_t)r * XK + a;
    split_bf16(v, g_xh[idx], g_xl[idx]);
}

// fused inp2 + inp3
__global__ void k_inp23(const float* __restrict__ osc,
                        const float* __restrict__ W2, const float* __restrict__ b2,
                        const float* __restrict__ W3, const float* __restrict__ b3) {
    int r0 = blockIdx.x * 8;
    int j = threadIdx.x; // 256
    __shared__ float sin_[8][64];
    __shared__ float smid[8][256];
    for (int i = threadIdx.x; i < 8 * 64; i += 256) {
        int rr = i >> 6, k = i & 63;
        int r = r0 + rr;
        int t = r >> 7, b = r & 127;
        sin_[rr][k] = osc[((size_t)b * T + t) * 128 + k];
    }
    __syncthreads();
    {
        float bj = b2[j];
        float acc[8];
#pragma unroll
        for (int i = 0; i < 8; i++) acc[i] = bj;
        for (int k = 0; k < 64; k++) {
            float w = W2[k * 256 + j];
#pragma unroll
            for (int i = 0; i < 8; i++) acc[i] += sin_[i][k] * w;
        }
#pragma unroll
        for (int i = 0; i < 8; i++) {
            float v = eluf(acc[i]);
            smid[i][j] = v;
            size_t idx = (size_t)(r0 + i) * XK + 256 + j;
            split_bf16(v, g_xh[idx], g_xl[idx]);
        }
    }
    __syncthreads();
    {
        float bj = b3[j];
        float acc[8];
#pragma unroll
        for (int i = 0; i < 8; i++) acc[i] = bj;
        for (int k = 0; k < 192; k++) {
            float w = W3[k * 256 + j];
#pragma unroll
            for (int i = 0; i < 8; i++) acc[i] += smid[i][64 + k] * w;
        }
#pragma unroll
        for (int i = 0; i < 8; i++) {
            size_t idx = (size_t)(r0 + i) * XK + 512 + j;
            split_bf16(eluf(acc[i]), g_xh[idx], g_xl[idx]);
        }
    }
}

// transpose + split gru_k [768,1536] -> g_bh/g_bl [1536,768]
__global__ void k_trb(const float* __restrict__ gk) {
    __shared__ float s[32][33];
    int n0 = blockIdx.x * 32, k0 = blockIdx.y * 32;
    int tx = threadIdx.x, ty = threadIdx.y; // 32 x 8
#pragma unroll
    for (int i = 0; i < 32; i += 8)
        s[ty + i][tx] = gk[(size_t)(k0 + ty + i) * XN + n0 + tx];
    __syncthreads();
#pragma unroll
    for (int i = 0; i < 32; i += 8) {
        size_t idx = (size_t)(n0 + ty + i) * XK + k0 + tx;
        split_bf16(s[tx][ty + i], g_bh[idx], g_bl[idx]);
    }
}

// transpose + split gru_rk [512,1536] -> g_rh/g_rl [1536,512]
__global__ void k_trw(const float* __restrict__ wr) {
    __shared__ float s[32][33];
    int n0 = blockIdx.x * 32, k0 = blockIdx.y * 32;
    int tx = threadIdx.x, ty = threadIdx.y; // 32 x 8
#pragma unroll
    for (int i = 0; i < 32; i += 8)
        s[ty + i][tx] = wr[(size_t)(k0 + ty + i) * XN + n0 + tx];
    __syncthreads();
#pragma unroll
    for (int i = 0; i < 32; i += 8) {
        size_t idx = (size_t)(n0 + ty + i) * UG + k0 + tx;
        split_bf16(s[tx][ty + i], g_rh[idx], g_rl[idx]);
    }
}

// ---------------- HMMA GEMM: g_xp = x @ gru_k + gru_b[0] ---------------------
namespace {
constexpr int PITCHB = 80;
constexpr int ARRB   = 128 * PITCHB;       // 10240
constexpr int BUFB   = 4 * ARRB;           // 40960
constexpr int SMEM_GEMM = 3 * BUFB;        // 122880
constexpr int KCH = 24;
}

__global__ void __launch_bounds__(256, 1) k_xmma(const float* __restrict__ gb) {
    extern __shared__ char smem[];
    const uint32_t sb = smem_u32(smem);
    const int tid = threadIdx.x;
    const int lane = tid & 31, wid = tid >> 5;
    const int wm = wid & 3;
    const int wn = wid >> 2;
    const int m0 = blockIdx.y * 128;
    const int n0 = blockIdx.x * 128;

    const __nv_bfloat16* gptr[4] = {
        g_xh + (size_t)m0 * XK, g_xl + (size_t)m0 * XK,
        g_bh + (size_t)n0 * XK, g_bl + (size_t)n0 * XK};

    auto load_chunk = [&](int c, int buf) {
        uint32_t base = sb + buf * BUFB;
#pragma unroll
        for (int l = 0; l < 8; l++) {
            int idx = tid + 256 * l;
            int arr = idx >> 9;
            int rem = idx & 511;
            int row = rem >> 2;
            int cch = rem & 3;
            cpa16(base + arr * ARRB + row * PITCHB + cch * 16,
                  gptr[arr] + (size_t)row * XK + c * 32 + cch * 8);
        }
        asm volatile("cp.async.commit_group;" ::: "memory");
    };

    float acc[2][8][4];
#pragma unroll
    for (int i = 0; i < 2; i++)
#pragma unroll
        for (int j = 0; j < 8; j++)
#pragma unroll
            for (int q = 0; q < 4; q++) acc[i][j][q] = 0.f;

    const uint32_t aAddr = sb + (wm * 32 + (lane & 15)) * PITCHB + (lane >> 4) * 16;
    const uint32_t bAddr = sb + 2 * ARRB + (wn * 64 + (lane & 15)) * PITCHB + (lane >> 4) * 16;

    load_chunk(0, 0);
    load_chunk(1, 1);

    for (int c = 0; c < KCH; c++) {
        if (c + 1 < KCH) asm volatile("cp.async.wait_group 1;" ::: "memory");
        else             asm volatile("cp.async.wait_group 0;" ::: "memory");
        __syncthreads();
        if (c + 2 < KCH) load_chunk(c + 2, (c + 2) % 3);

        uint32_t boff = (c % 3) * BUFB;
#pragma unroll
        for (int ks = 0; ks < 2; ks++) {
            uint32_t ah[2][4], al[2][4], bh[4][4], bl[4][4];
#pragma unroll
            for (int mt = 0; mt < 2; mt++) {
                uint32_t a = aAddr + boff + mt * (16 * PITCHB) + ks * 32;
                ldm4(ah[mt], a);
                ldm4(al[mt], a + ARRB);
            }
#pragma unroll
            for (int ng = 0; ng < 4; ng++) {
                uint32_t a = bAddr + boff + ng * (16 * PITCHB) + ks * 32;
                ldm4(bh[ng], a);
                ldm4(bl[ng], a + ARRB);
            }
#pragma unroll
            for (int mt = 0; mt < 2; mt++)
#pragma unroll
                for (int ng = 0; ng < 4; ng++)
#pragma unroll
                    for (int hf = 0; hf < 2; hf++) {
                        int nt = ng * 2 + hf;
                        mma16816(acc[mt][nt], ah[mt], bh[ng][hf], bh[ng][hf + 2]);
                        mma16816(acc[mt][nt], al[mt], bh[ng][hf], bh[ng][hf + 2]);
                        mma16816(acc[mt][nt], ah[mt], bl[ng][hf], bl[ng][hf + 2]);
                    }
        }
    }

    const int qr = lane >> 2, qc = lane & 3;
#pragma unroll
    for (int mt = 0; mt < 2; mt++)
#pragma unroll
        for (int nt = 0; nt < 8; nt++) {
            int nb = n0 + wn * 64 + nt * 8 + 2 * qc;
            float b0 = gb[nb], b1 = gb[nb + 1];
#pragma unroll
            for (int rp = 0; rp < 2; rp++) {
                int m = m0 + wm * 32 + mt * 16 + qr + 8 * rp;
                float2 v = make_float2(acc[mt][nt][2 * rp] + b0,
                                       acc[mt][nt][2 * rp + 1] + b1);
                *(float2*)&g_xp[(size_t)m * XN + nb] = v;
            }
        }
}

// ---------------- persistent GRU kernel (256 thr, K split across warp pairs) --
// 128 blocks; block owns (32 b x 16 u). Warp = (kh, mt, uh): kh halves K=512.
// kh=0 warps keep h_prev/hmax in registers and do gate math; kh=1 warps hand
// their partial accumulators over via smem.
namespace {
constexpr int PITCH = 1040;
constexpr int WSEC  = 16 * PITCH;              // 16640
constexpr int AHI_OFF = 6 * WSEC;              // 99840
constexpr int ALO_OFF = AHI_OFF + 32 * PITCH;  // 133120
constexpr int PART_OFF = ALO_OFF + 32 * PITCH; // 166400
constexpr int SMEM_GRU = PART_OFF + 128 * 12 * 4; // 172544
constexpr int NBLK_BT = 32;
}

__global__ void __launch_bounds__(256, 1) k_gru(const float* __restrict__ gb) {
    extern __shared__ char smem[];
    float* spart = (float*)(smem + PART_OFF);
    const uint32_t sb = smem_u32(smem);
    const int tid = threadIdx.x, lane = tid & 31, wid = tid >> 5;
    const int kh = wid >> 2;               // k-half: 0 or 1
    const int mt = (wid >> 1) & 1;         // m16 tile
    const int uh = wid & 1;                // u-half (8 u)
    const int bt = blockIdx.x & 3;
    const int ut = blockIdx.x >> 2;
    const int u0 = ut * 16;
    const int row0 = bt * 32;
    const int qr = lane >> 2, qc = lane & 3;
    const int r1 = row0 + mt * 16 + qr;
    const int r2 = r1 + 8;
    const int uc = u0 + uh * 8 + 2 * qc;
    const int lowid = tid & 127;           // matching thread in the other k-half

    // ---- W slice -> smem (once): 6 sections x 16 rows x 512 bf16 ----
    for (int idx = tid; idx < 6144; idx += 256) {
        int sec = idx >> 10;
        int rem = idx & 1023;
        int r = rem >> 6, ch = rem & 63;
        int g = sec >> 1;
        const __nv_bfloat16* src = (sec & 1) ? g_rl : g_rh;
        cpa16(sb + sec * WSEC + r * PITCH + ch * 16,
              src + ((size_t)(g * 512 + u0 + r)) * UG + ch * 8);
    }
    asm volatile("cp.async.commit_group;" ::: "memory");

    const float* gbr = gb + XN;
    float bzc[2], brc[2], bhc[2];
#pragma unroll
    for (int j = 0; j < 2; j++) {
        bzc[j] = gbr[uc + j];
        brc[j] = gbr[512 + uc + j];
        bhc[j] = gbr[1024 + uc + j];
    }

    float hprev[4], hmax[4];
    if (kh == 0) {
        hprev[0] = g_h0f[(size_t)r1 * UG + uc];
        hprev[1] = g_h0f[(size_t)r1 * UG + uc + 1];
        hprev[2] = g_h0f[(size_t)r2 * UG + uc];
        hprev[3] = g_h0f[(size_t)r2 * UG + uc + 1];
#pragma unroll
        for (int i = 0; i < 4; i++) hmax[i] = -INFINITY;
    }

    // ldmatrix bases; each warp covers k-range [kh*256, kh*256+256) = 512 bytes
    const uint32_t aHi = sb + AHI_OFF + (mt * 16 + (lane & 15)) * PITCH + kh * 512 +
                         ((lane >> 4) & 1) * 16;
    const uint32_t aLo = aHi + 32 * PITCH;
    uint32_t bHi[3], bLo[3];
    {
        int brow = uh * 8 + (lane & 7);
        int bch = lane >> 3;               // 0..3 -> 64B = k32
#pragma unroll
        for (int g = 0; g < 3; g++) {
            bHi[g] = sb + (2 * g) * WSEC + brow * PITCH + kh * 512 + bch * 16;
            bLo[g] = bHi[g] + WSEC;
        }
    }

    auto stageA = [&](int par) {
        const __nv_bfloat16* shp = g_hh[par] + (size_t)row0 * UG;
        const __nv_bfloat16* slp = g_hl[par] + (size_t)row0 * UG;
        for (int idx = tid; idx < 2048; idx += 256) {
            int r = idx >> 6, ch = idx & 63;
            cpa16(sb + AHI_OFF + r * PITCH + ch * 16, shp + (size_t)r * UG + ch * 8);
            cpa16(sb + ALO_OFF + r * PITCH + ch * 16, slp + (size_t)r * UG + ch * 8);
        }
        asm volatile("cp.async.commit_group;" ::: "memory");
    };

    stageA(0);

    float2 xz[2], xr[2], xh[2];
    if (kh == 0) {
        const float* xpr1 = g_xp + (size_t)r1 * XN;
        const float* xpr2 = g_xp + (size_t)r2 * XN;
        xz[0] = *(const float2*)(xpr1 + uc);        xz[1] = *(const float2*)(xpr2 + uc);
        xr[0] = *(const float2*)(xpr1 + 512 + uc);  xr[1] = *(const float2*)(xpr2 + 512 + uc);
        xh[0] = *(const float2*)(xpr1 + 1024 + uc); xh[1] = *(const float2*)(xpr2 + 1024 + uc);
    }

    unsigned* barp = &g_bar4[bt];
    unsigned* genp = &g_gen4[bt];

    for (int t = 0; t < T; t++) {
        asm volatile("cp.async.wait_group 0;" ::: "memory");
        __syncthreads();

        float az[4] = {0.f, 0.f, 0.f, 0.f};
        float ar[4] = {0.f, 0.f, 0.f, 0.f};
        float ah2[4] = {0.f, 0.f, 0.f, 0.f};

#pragma unroll 4
        for (int j = 0; j < 8; j++) {      // k32 per iteration, 256 k per warp
            uint32_t ah0[4], ah1[4], al0[4], al1[4];
            uint32_t a = aHi + j * 64;
            ldm4(ah0, a);
            ldm4(ah1, a + 32);
            uint32_t al = aLo + j * 64;
            ldm4(al0, al);
            ldm4(al1, al + 32);
            uint32_t b4h[4], b4l[4];
            // gate z
            ldm4(b4h, bHi[0] + j * 64); ldm4(b4l, bLo[0] + j * 64);
            mma16816(az, ah0, b4h[0], b4h[1]);
            mma16816(az, al0, b4h[0], b4h[1]);
            mma16816(az, ah0, b4l[0], b4l[1]);
            mma16816(az, ah1, b4h[2], b4h[3]);
            mma16816(az, al1, b4h[2], b4h[3]);
            mma16816(az, ah1, b4l[2], b4l[3]);
            // gate r
            ldm4(b4h, bHi[1] + j * 64); ldm4(b4l, bLo[1] + j * 64);
            mma16816(ar, ah0, b4h[0], b4h[1]);
            mma16816(ar, al0, b4h[0], b4h[1]);
            mma16816(ar, ah0, b4l[0], b4l[1]);
            mma16816(ar, ah1, b4h[2], b4h[3]);
            mma16816(ar, al1, b4h[2], b4h[3]);
            mma16816(ar, ah1, b4l[2], b4l[3]);
            // gate h
            ldm4(b4h, bHi[2] + j * 64); ldm4(b4l, bLo[2] + j * 64);
            mma16816(ah2, ah0, b4h[0], b4h[1]);
            mma16816(ah2, al0, b4h[0], b4h[1]);
            mma16816(ah2, ah0, b4l[0], b4l[1]);
            mma16816(ah2, ah1, b4h[2], b4h[3]);
            mma16816(ah2, al1, b4h[2], b4h[3]);
            mma16816(ah2, ah1, b4l[2], b4l[3]);
        }

        // kh=1 warps publish partials
        if (kh == 1) {
            float* p = spart + lowid * 12;
#pragma unroll
            for (int i = 0; i < 4; i++) {
                p[i]     = az[i];
                p[4 + i] = ar[i];
                p[8 + i] = ah2[i];
            }
        }
        __syncthreads();

        int np = (t + 1) & 1;
        bool notlast = (t + 1 < T);
        if (kh == 0) {
            const float* p = spart + lowid * 12;
#pragma unroll
            for (int i = 0; i < 4; i++) {
                az[i]  += p[i];
                ar[i]  += p[4 + i];
                ah2[i] += p[8 + i];
            }
#pragma unroll
            for (int pp = 0; pp < 2; pp++) {
                float hn[2];
#pragma unroll
                for (int j = 0; j < 2; j++) {
                    int i = 2 * pp + j;
                    float xzv = j ? xz[pp].y : xz[pp].x;
                    float xrv = j ? xr[pp].y : xr[pp].x;
                    float xhv = j ? xh[pp].y : xh[pp].x;
                    float z = sigm(xzv + az[i] + bzc[j]);
                    float r = sigm(xrv + ar[i] + brc[j]);
                    float hc = tanhf(xhv + r * (ah2[i] + bhc[j]));
                    hn[j] = z * hprev[i] + (1.f - z) * hc;
                    hprev[i] = hn[j];
                    hmax[i] = fmaxf(hmax[i], hn[j]);
                }
                if (notlast) {
                    int rowg = pp ? r2 : r1;
                    __nv_bfloat162 vh, vl;
                    __nv_bfloat16 h0b, l0b, h1b, l1b;
                    split_bf16(hn[0], h0b, l0b);
                    split_bf16(hn[1], h1b, l1b);
                    vh.x = h0b; vh.y = h1b;
                    vl.x = l0b; vl.y = l1b;
                    *(__nv_bfloat162*)&g_hh[np][(size_t)rowg * UG + uc] = vh;
                    *(__nv_bfloat162*)&g_hl[np][(size_t)rowg * UG + uc] = vl;
                }
            }
            if (notlast) {
                const float* xp = g_xp + (size_t)(t + 1) * ((size_t)B * XN);
                const float* xpr1 = xp + (size_t)r1 * XN;
                const float* xpr2 = xp + (size_t)r2 * XN;
                xz[0] = *(const float2*)(xpr1 + uc);        xz[1] = *(const float2*)(xpr2 + uc);
                xr[0] = *(const float2*)(xpr1 + 512 + uc);  xr[1] = *(const float2*)(xpr2 + 512 + uc);
                xh[0] = *(const float2*)(xpr1 + 1024 + uc); xh[1] = *(const float2*)(xpr2 + 1024 + uc);
            }
        }

        if (notlast) {
            __syncthreads();   // h stores complete before barrier arrive
            if (tid == 0) {
                unsigned target = (unsigned)(t + 1) * NBLK_BT;
                unsigned old = atomAddRel(barp, 1);
                if (old == target - 1) {
                    stRel(genp, (unsigned)(t + 1));
                } else {
                    int spins = 0;
                    while (ldAcq(genp) < (unsigned)(t + 1)) {
                        if (++spins > 64) asm volatile("nanosleep.u32 64;");
                    }
                }
            }
            __syncthreads();
            stageA(np);
        }
    }

    if (kh == 0) {
        float2 v;
        v.x = hmax[0]; v.y = hmax[1]; *(float2*)&g_hmax[(size_t)r1 * UG + uc] = v;
        v.x = hmax[2]; v.y = hmax[3]; *(float2*)&g_hmax[(size_t)r2 * UG + uc] = v;
        v.x = hprev[0]; v.y = hprev[1]; *(float2*)&g_h0f[(size_t)r1 * UG + uc] = v;
        v.x = hprev[2]; v.y = hprev[3]; *(float2*)&g_h0f[(size_t)r2 * UG + uc] = v;
    }
}

// ---------------- epilogue ---------------------------------------------------
__global__ void k_out(const float* __restrict__ Wout, const float* __restrict__ bout,
                      float* __restrict__ dout, int out_size) {
    int b = blockIdx.x;
    int tid = threadIdx.x; // 256
    __shared__ float red[256];
    float s = 0.f;
    for (int uu = tid; uu < UG; uu += 256) s += g_hmax[b * UG + uu] * Wout[uu];
    red[tid] = s;
    __syncthreads();
    for (int o = 128; o > 0; o >>= 1) {
        if (tid < o) red[tid] += red[tid + o];
        __syncthreads();
    }
    if (tid == 0 && b < out_size) dout[b] = eluf(red[0] + bout[0]);
    for (int uu = tid; uu < UG; uu += 256) {
        int idx = B + b * UG + uu;
        if (idx < out_size) dout[idx] = g_h0f[b * UG + uu];
    }
}

// ---------------- launch ------------------------------------------------------
extern "C" void kernel_launch(void* const* d_in, const int* in_sizes, int n_in,
                              void* d_out, int out_size) {
    const float* motion = (const float*)d_in[0];
    const float* robot  = (const float*)d_in[1];
    const float* action = (const float*)d_in[3];
    const float* osc    = (const float*)d_in[4];
    const float* mu     = (const float*)d_in[5];
    const float* mean   = (const float*)d_in[6];
    const float* state  = (const float*)d_in[7];
    const float* W_mot  = (const float*)d_in[8];
    const float* b_mot  = (const float*)d_in[9];
    const float* W_rob  = (const float*)d_in[10];
    const float* b_rob  = (const float*)d_in[11];
    const float* W_comb = (const float*)d_in[12];
    const float* b_comb = (const float*)d_in[13];
    const float* W_oscr = (const float*)d_in[14];
    const float* b_oscr = (const float*)d_in[15];
    const float* W_osci = (const float*)d_in[16];
    const float* b_osci = (const float*)d_in[17];
    const float* gru_k  = (const float*)d_in[18];
    const float* gru_rk = (const float*)d_in[19];
    const float* gru_b  = (const float*)d_in[20];
    const float* W_out  = (const float*)d_in[21];
    const float* b_out  = (const float*)d_in[22];
    float* out = (float*)d_out;

    static bool attr_set = false;
    if (!attr_set) {
        cudaFuncSetAttribute(k_xmma, cudaFuncAttributeMaxDynamicSharedMemorySize, SMEM_GEMM);
        cudaFuncSetAttribute(k_gru, cudaFuncAttributeMaxDynamicSharedMemorySize, SMEM_GRU);
        attr_set = true;
    }

    k_reset<<<1, 32>>>();
    k_msrs<<<B, 256>>>(motion, robot, W_mot, b_mot, W_rob, b_rob);
    k_h0<<<B, 512>>>(state, W_comb, b_comb);
    k_act<<<ROWS, 256>>>(action, mu, mean);
    k_inp23<<<ROWS / 8, 256>>>(osc, W_oscr, b_oscr, W_osci, b_osci);
    k_trb<<<dim3(XN / 32, XK / 32), dim3(32, 8)>>>(gru_k);
    k_trw<<<dim3(XN / 32, UG / 32), dim3(32, 8)>>>(gru_rk);
    k_xmma<<<dim3(XN / 128, ROWS / 128), 256, SMEM_GEMM>>>(gru_b);
    k_gru<<<128, 256, SMEM_GRU>>>(gru_b);
    k_out<<<B, 256>>>(W_out, b_out, out, out_size);
}

// round 8
// speedup vs baseline: 3.6541x; 1.2172x over previous
#include <cuda_runtime.h>
#include <cuda_fp16.h>
#include <cstdint>
#include <math.h>

namespace {
constexpr int B  = 128;
constexpr int T  = 512;
constexpr int A  = 256;
constexpr int UG = 512;
constexpr int ROWS = B * T;       // 65536
constexpr int XK = 768;           // x feature width
constexpr int XN = 1536;          // 3 * UG
}

// ---------------- scratch (device globals; no allocation allowed) ------------
__device__ __half g_xh[(size_t)ROWS * XK];      // fp16 hi of x
__device__ __half g_xl[(size_t)ROWS * XK];      // fp16 lo of x
__device__ __half g_bh[(size_t)XN * XK];        // gru_k^T [N,K] fp16
__device__ __half g_rh[(size_t)XN * UG];        // gru_rk^T [1536,512] fp16
__device__ float g_xp[(size_t)ROWS * XN];       // x @ gru_k + gru_b[0]
__device__ float g_h0f[B * UG];                 // h0 fp32 / final h
__device__ __half g_hh[2][B * UG];              // h ping-pong, fp16 hi
__device__ __half g_hl[2][B * UG];              // h ping-pong, fp16 lo
__device__ float g_hmax[B * UG];
__device__ float g_ms[B * 256];
__device__ float g_rs[B * 256];
__device__ unsigned g_bar4[4];                  // per-btile barrier arrivals
__device__ unsigned g_gen4[4];                  // per-btile generation

__device__ __forceinline__ float eluf(float v) { return v > 0.f ? v : (expf(v) - 1.f); }
__device__ __forceinline__ float sigm(float v) { return 1.f / (1.f + expf(-v)); }
__device__ __forceinline__ void split_f16(float v, __half& h, __half& l) {
    h = __float2half(v);
    l = __float2half(v - __half2float(h));
}

// ---------------- PTX helpers (plain sm_103-safe) -----------------------------
__device__ __forceinline__ uint32_t smem_u32(const void* p) {
    uint32_t a;
    asm("{ .reg .u64 t; cvta.to.shared.u64 t, %1; cvt.u32.u64 %0, t; }" : "=r"(a) : "l"(p));
    return a;
}
__device__ __forceinline__ void cpa16(uint32_t s, const void* g) {
    asm volatile("cp.async.cg.shared.global [%0], [%1], 16;" :: "r"(s), "l"(g));
}
__device__ __forceinline__ void ldm4(uint32_t* r, uint32_t a) {
    asm volatile("ldmatrix.sync.aligned.m8n8.x4.shared.b16 {%0,%1,%2,%3}, [%4];"
                 : "=r"(r[0]), "=r"(r[1]), "=r"(r[2]), "=r"(r[3]) : "r"(a));
}
__device__ __forceinline__ void mma16816(float* c, const uint32_t* a, uint32_t b0, uint32_t b1) {
    asm volatile(
        "mma.sync.aligned.m16n8k16.row.col.f32.f16.f16.f32 "
        "{%0,%1,%2,%3}, {%4,%5,%6,%7}, {%8,%9}, {%0,%1,%2,%3};"
        : "+f"(c[0]), "+f"(c[1]), "+f"(c[2]), "+f"(c[3])
        : "r"(a[0]), "r"(a[1]), "r"(a[2]), "r"(a[3]), "r"(b0), "r"(b1));
}
__device__ __forceinline__ unsigned atomAddRel(unsigned* p, unsigned v) {
    unsigned o;
    asm volatile("atom.release.gpu.global.add.u32 %0, [%1], %2;"
                 : "=r"(o) : "l"(p), "r"(v) : "memory");
    return o;
}
__device__ __forceinline__ void stRel(unsigned* p, unsigned v) {
    asm volatile("st.release.gpu.global.u32 [%0], %1;" :: "l"(p), "r"(v) : "memory");
}
__device__ __forceinline__ unsigned ldAcq(unsigned* p) {
    unsigned v;
    asm volatile("ld.acquire.gpu.global.u32 %0, [%1];" : "=r"(v) : "l"(p) : "memory");
    return v;
}

// ---------------- small front-end kernels -----------------------------------
__global__ void k_reset() {
    int i = threadIdx.x;
    if (i < 4) { g_bar4[i] = 0; g_gen4[i] = 0; }
}

__global__ void k_msrs(const float* __restrict__ motion, const float* __restrict__ robot,
                       const float* __restrict__ Wm, const float* __restrict__ bm,
                       const float* __restrict__ Wr, const float* __restrict__ br) {
    int b = blockIdx.x;
    int j = threadIdx.x; // 256
    __shared__ float sm[64], sr[64];
    if (j < 64) sm[j] = motion[b * 64 + j];
    else if (j < 128) sr[j - 64] = robot[b * 64 + (j - 64)];
    __syncthreads();
    float accm = bm[j], accr = br[j];
    for (int k = 0; k < 64; k++) {
        accm += sm[k] * Wm[k * 256 + j];
        accr += sr[k] * Wr[k * 256 + j];
    }
    g_ms[b * 256 + j] = eluf(accm);
    g_rs[b * 256 + j] = eluf(accr);
}

__global__ void k_h0(const float* __restrict__ state, const float* __restrict__ Wc,
                     const float* __restrict__ bc) {
    int b = blockIdx.x;
    int u = threadIdx.x; // 512
    __shared__ float s[1024];
    s[u] = (u < 256) ? g_ms[b * 256 + u] : g_rs[b * 256 + (u - 256)];
    s[512 + u] = state[b * 512 + u];
    __syncthreads();
    float acc = bc[u];
    for (int k = 0; k < 1024; k++) acc += s[k] * Wc[k * 512 + u];
    float h0 = eluf(acc);
    size_t idx = (size_t)b * 512 + u;
    g_h0f[idx] = h0;
    split_f16(h0, g_hh[0][idx], g_hl[0][idx]);
}

__global__ void k_act(const float* __restrict__ action, const float* __restrict__ mu,
                      const float* __restrict__ mean) {
    int r = blockIdx.x;
    int t = r >> 7;
    int b = r & 127;
    int a = threadIdx.x;
    float v = action[((size_t)b * T + t) * A + a] * mu[b * A + a] + mean[b * A + a];
    size_t idx = (size_t)r * XK + a;
    split_f16(v, g_xh[idx], g_xl[idx]);
}

// fused inp2 + inp3
__global__ void k_inp23(const float* __restrict__ osc,
                        const float* __restrict__ W2, const float* __restrict__ b2,
                        const float* __restrict__ W3, const float* __restrict__ b3) {
    int r0 = blockIdx.x * 8;
    int j = threadIdx.x; // 256
    __shared__ float sin_[8][64];
    __shared__ float smid[8][256];
    for (int i = threadIdx.x; i < 8 * 64; i += 256) {
        int rr = i >> 6, k = i & 63;
        int r = r0 + rr;
        int t = r >> 7, b = r & 127;
        sin_[rr][k] = osc[((size_t)b * T + t) * 128 + k];
    }
    __syncthreads();
    {
        float bj = b2[j];
        float acc[8];
#pragma unroll
        for (int i = 0; i < 8; i++) acc[i] = bj;
        for (int k = 0; k < 64; k++) {
            float w = W2[k * 256 + j];
#pragma unroll
            for (int i = 0; i < 8; i++) acc[i] += sin_[i][k] * w;
        }
#pragma unroll
        for (int i = 0; i < 8; i++) {
            float v = eluf(acc[i]);
            smid[i][j] = v;
            size_t idx = (size_t)(r0 + i) * XK + 256 + j;
            split_f16(v, g_xh[idx], g_xl[idx]);
        }
    }
    __syncthreads();
    {
        float bj = b3[j];
        float acc[8];
#pragma unroll
        for (int i = 0; i < 8; i++) acc[i] = bj;
        for (int k = 0; k < 192; k++) {
            float w = W3[k * 256 + j];
#pragma unroll
            for (int i = 0; i < 8; i++) acc[i] += smid[i][64 + k] * w;
        }
#pragma unroll
        for (int i = 0; i < 8; i++) {
            size_t idx = (size_t)(r0 + i) * XK + 512 + j;
            split_f16(eluf(acc[i]), g_xh[idx], g_xl[idx]);
        }
    }
}

// transpose gru_k [768,1536] -> g_bh [1536,768] fp16
__global__ void k_trb(const float* __restrict__ gk) {
    __shared__ float s[32][33];
    int n0 = blockIdx.x * 32, k0 = blockIdx.y * 32;
    int tx = threadIdx.x, ty = threadIdx.y; // 32 x 8
#pragma unroll
    for (int i = 0; i < 32; i += 8)
        s[ty + i][tx] = gk[(size_t)(k0 + ty + i) * XN + n0 + tx];
    __syncthreads();
#pragma unroll
    for (int i = 0; i < 32; i += 8) {
        size_t idx = (size_t)(n0 + ty + i) * XK + k0 + tx;
        g_bh[idx] = __float2half(s[tx][ty + i]);
    }
}

// transpose gru_rk [512,1536] -> g_rh [1536,512] fp16
__global__ void k_trw(const float* __restrict__ wr) {
    __shared__ float s[32][33];
    int n0 = blockIdx.x * 32, k0 = blockIdx.y * 32;
    int tx = threadIdx.x, ty = threadIdx.y; // 32 x 8
#pragma unroll
    for (int i = 0; i < 32; i += 8)
        s[ty + i][tx] = wr[(size_t)(k0 + ty + i) * XN + n0 + tx];
    __syncthreads();
#pragma unroll
    for (int i = 0; i < 32; i += 8) {
        size_t idx = (size_t)(n0 + ty + i) * UG + k0 + tx;
        g_rh[idx] = __float2half(s[tx][ty + i]);
    }
}

// ---------------- HMMA GEMM: g_xp = x @ gru_k + gru_b[0] ---------------------
// fp16 2-term split: (AH + AL) x BH. 128x128 tile, K-chunk 32, 3-stage pipeline.
namespace {
constexpr int PITCHB = 80;
constexpr int ARRB   = 128 * PITCHB;       // 10240
constexpr int BUFB   = 3 * ARRB;           // 30720 : AH | AL | BH
constexpr int SMEM_GEMM = 3 * BUFB;        // 92160
constexpr int KCH = 24;
}

__global__ void __launch_bounds__(256, 1) k_xmma(const float* __restrict__ gb) {
    extern __shared__ char smem[];
    const uint32_t sb = smem_u32(smem);
    const int tid = threadIdx.x;
    const int lane = tid & 31, wid = tid >> 5;
    const int wm = wid & 3;
    const int wn = wid >> 2;
    const int m0 = blockIdx.y * 128;
    const int n0 = blockIdx.x * 128;

    const __half* gptr[3] = {
        g_xh + (size_t)m0 * XK, g_xl + (size_t)m0 * XK, g_bh + (size_t)n0 * XK};

    auto load_chunk = [&](int c, int buf) {
        uint32_t base = sb + buf * BUFB;
#pragma unroll
        for (int l = 0; l < 6; l++) {
            int idx = tid + 256 * l;
            int arr = idx >> 9;            // 0..2
            int rem = idx & 511;
            int row = rem >> 2;
            int cch = rem & 3;
            cpa16(base + arr * ARRB + row * PITCHB + cch * 16,
                  gptr[arr] + (size_t)row * XK + c * 32 + cch * 8);
        }
        asm volatile("cp.async.commit_group;" ::: "memory");
    };

    float acc[2][8][4];
#pragma unroll
    for (int i = 0; i < 2; i++)
#pragma unroll
        for (int j = 0; j < 8; j++)
#pragma unroll
            for (int q = 0; q < 4; q++) acc[i][j][q] = 0.f;

    const uint32_t aAddr = sb + (wm * 32 + (lane & 15)) * PITCHB + (lane >> 4) * 16;
    const uint32_t bAddr = sb + 2 * ARRB + (wn * 64 + (lane & 15)) * PITCHB + (lane >> 4) * 16;

    load_chunk(0, 0);
    load_chunk(1, 1);

    for (int c = 0; c < KCH; c++) {
        if (c + 1 < KCH) asm volatile("cp.async.wait_group 1;" ::: "memory");
        else             asm volatile("cp.async.wait_group 0;" ::: "memory");
        __syncthreads();
        if (c + 2 < KCH) load_chunk(c + 2, (c + 2) % 3);

        uint32_t boff = (c % 3) * BUFB;
#pragma unroll
        for (int ks = 0; ks < 2; ks++) {
            uint32_t ah[2][4], al[2][4], bh[4][4];
#pragma unroll
            for (int mt = 0; mt < 2; mt++) {
                uint32_t a = aAddr + boff + mt * (16 * PITCHB) + ks * 32;
                ldm4(ah[mt], a);
                ldm4(al[mt], a + ARRB);
            }
#pragma unroll
            for (int ng = 0; ng < 4; ng++) {
                uint32_t a = bAddr + boff + ng * (16 * PITCHB) + ks * 32;
                ldm4(bh[ng], a);
            }
#pragma unroll
            for (int mt = 0; mt < 2; mt++)
#pragma unroll
                for (int ng = 0; ng < 4; ng++)
#pragma unroll
                    for (int hf = 0; hf < 2; hf++) {
                        int nt = ng * 2 + hf;
                        mma16816(acc[mt][nt], ah[mt], bh[ng][hf], bh[ng][hf + 2]);
                        mma16816(acc[mt][nt], al[mt], bh[ng][hf], bh[ng][hf + 2]);
                    }
        }
    }

    const int qr = lane >> 2, qc = lane & 3;
#pragma unroll
    for (int mt = 0; mt < 2; mt++)
#pragma unroll
        for (int nt = 0; nt < 8; nt++) {
            int nb = n0 + wn * 64 + nt * 8 + 2 * qc;
            float b0 = gb[nb], b1 = gb[nb + 1];
#pragma unroll
            for (int rp = 0; rp < 2; rp++) {
                int m = m0 + wm * 32 + mt * 16 + qr + 8 * rp;
                float2 v = make_float2(acc[mt][nt][2 * rp] + b0,
                                       acc[mt][nt][2 * rp + 1] + b1);
                *(float2*)&g_xp[(size_t)m * XN + nb] = v;
            }
        }
}

// ---------------- persistent GRU kernel (256 thr, K split, fp16 2-term) -------
namespace {
constexpr int PITCH = 1040;
constexpr int WSEC  = 16 * PITCH;              // 16640 per gate (fp16, hi only)
constexpr int AHI_OFF = 3 * WSEC;              // 49920
constexpr int ALO_OFF = AHI_OFF + 32 * PITCH;  // 83200
constexpr int PART_OFF = ALO_OFF + 32 * PITCH; // 116480
constexpr int SMEM_GRU = PART_OFF + 128 * 12 * 4; // 122624
constexpr int NBLK_BT = 32;
}

__global__ void __launch_bounds__(256, 1) k_gru(const float* __restrict__ gb) {
    extern __shared__ char smem[];
    float* spart = (float*)(smem + PART_OFF);
    const uint32_t sb = smem_u32(smem);
    const int tid = threadIdx.x, lane = tid & 31, wid = tid >> 5;
    const int kh = wid >> 2;               // k-half
    const int mt = (wid >> 1) & 1;         // m16 tile
    const int uh = wid & 1;                // u-half (8 u)
    const int bt = blockIdx.x & 3;
    const int ut = blockIdx.x >> 2;
    const int u0 = ut * 16;
    const int row0 = bt * 32;
    const int qr = lane >> 2, qc = lane & 3;
    const int r1 = row0 + mt * 16 + qr;
    const int r2 = r1 + 8;
    const int uc = u0 + uh * 8 + 2 * qc;
    const int lowid = tid & 127;

    // ---- W slice -> smem (once): 3 gates x 16 n x 512 k, fp16 hi only ----
    for (int idx = tid; idx < 3072; idx += 256) {
        int sec = idx >> 10;               // gate 0..2
        int rem = idx & 1023;
        int r = rem >> 6, ch = rem & 63;
        cpa16(sb + sec * WSEC + r * PITCH + ch * 16,
              g_rh + ((size_t)(sec * 512 + u0 + r)) * UG + ch * 8);
    }
    asm volatile("cp.async.commit_group;" ::: "memory");

    const float* gbr = gb + XN;
    float bzc[2], brc[2], bhc[2];
#pragma unroll
    for (int j = 0; j < 2; j++) {
        bzc[j] = gbr[uc + j];
        brc[j] = gbr[512 + uc + j];
        bhc[j] = gbr[1024 + uc + j];
    }

    float hprev[4], hmax[4];
    if (kh == 0) {
        hprev[0] = g_h0f[(size_t)r1 * UG + uc];
        hprev[1] = g_h0f[(size_t)r1 * UG + uc + 1];
        hprev[2] = g_h0f[(size_t)r2 * UG + uc];
        hprev[3] = g_h0f[(size_t)r2 * UG + uc + 1];
#pragma unroll
        for (int i = 0; i < 4; i++) hmax[i] = -INFINITY;
    }

    const uint32_t aHi = sb + AHI_OFF + (mt * 16 + (lane & 15)) * PITCH + kh * 512 +
                         ((lane >> 4) & 1) * 16;
    const uint32_t aLo = aHi + 32 * PITCH;
    uint32_t bHi[3];
    {
        int brow = uh * 8 + (lane & 7);
        int bch = lane >> 3;
#pragma unroll
        for (int g = 0; g < 3; g++)
            bHi[g] = sb + g * WSEC + brow * PITCH + kh * 512 + bch * 16;
    }

    auto stageA = [&](int par) {
        const __half* shp = g_hh[par] + (size_t)row0 * UG;
        const __half* slp = g_hl[par] + (size_t)row0 * UG;
        for (int idx = tid; idx < 2048; idx += 256) {
            int r = idx >> 6, ch = idx & 63;
            cpa16(sb + AHI_OFF + r * PITCH + ch * 16, shp + (size_t)r * UG + ch * 8);
            cpa16(sb + ALO_OFF + r * PITCH + ch * 16, slp + (size_t)r * UG + ch * 8);
        }
        asm volatile("cp.async.commit_group;" ::: "memory");
    };

    stageA(0);

    float2 xz[2], xr[2], xh[2];
    if (kh == 0) {
        const float* xpr1 = g_xp + (size_t)r1 * XN;
        const float* xpr2 = g_xp + (size_t)r2 * XN;
        xz[0] = *(const float2*)(xpr1 + uc);        xz[1] = *(const float2*)(xpr2 + uc);
        xr[0] = *(const float2*)(xpr1 + 512 + uc);  xr[1] = *(const float2*)(xpr2 + 512 + uc);
        xh[0] = *(const float2*)(xpr1 + 1024 + uc); xh[1] = *(const float2*)(xpr2 + 1024 + uc);
    }

    unsigned* barp = &g_bar4[bt];
    unsigned* genp = &g_gen4[bt];

    for (int t = 0; t < T; t++) {
        asm volatile("cp.async.wait_group 0;" ::: "memory");
        __syncthreads();

        float az[4] = {0.f, 0.f, 0.f, 0.f};
        float ar[4] = {0.f, 0.f, 0.f, 0.f};
        float ah2[4] = {0.f, 0.f, 0.f, 0.f};

#pragma unroll 4
        for (int j = 0; j < 8; j++) {      // k32 per iter, 256 k per warp
            uint32_t ah0[4], ah1[4], al0[4], al1[4];
            uint32_t a = aHi + j * 64;
            ldm4(ah0, a);
            ldm4(ah1, a + 32);
            uint32_t al = aLo + j * 64;
            ldm4(al0, al);
            ldm4(al1, al + 32);
            uint32_t b4h[4];
            // gate z
            ldm4(b4h, bHi[0] + j * 64);
            mma16816(az, ah0, b4h[0], b4h[1]);
            mma16816(az, al0, b4h[0], b4h[1]);
            mma16816(az, ah1, b4h[2], b4h[3]);
            mma16816(az, al1, b4h[2], b4h[3]);
            // gate r
            ldm4(b4h, bHi[1] + j * 64);
            mma16816(ar, ah0, b4h[0], b4h[1]);
            mma16816(ar, al0, b4h[0], b4h[1]);
            mma16816(ar, ah1, b4h[2], b4h[3]);
            mma16816(ar, al1, b4h[2], b4h[3]);
            // gate h
            ldm4(b4h, bHi[2] + j * 64);
            mma16816(ah2, ah0, b4h[0], b4h[1]);
            mma16816(ah2, al0, b4h[0], b4h[1]);
            mma16816(ah2, ah1, b4h[2], b4h[3]);
            mma16816(ah2, al1, b4h[2], b4h[3]);
        }

        if (kh == 1) {
            float* p = spart + lowid * 12;
#pragma unroll
            for (int i = 0; i < 4; i++) {
                p[i]     = az[i];
                p[4 + i] = ar[i];
                p[8 + i] = ah2[i];
            }
        }
        __syncthreads();

        int np = (t + 1) & 1;
        bool notlast = (t + 1 < T);
        if (kh == 0) {
            const float* p = spart + lowid * 12;
#pragma unroll
            for (int i = 0; i < 4; i++) {
                az[i]  += p[i];
                ar[i]  += p[4 + i];
                ah2[i] += p[8 + i];
            }
#pragma unroll
            for (int pp = 0; pp < 2; pp++) {
                float hn[2];
#pragma unroll
                for (int j = 0; j < 2; j++) {
                    int i = 2 * pp + j;
                    float xzv = j ? xz[pp].y : xz[pp].x;
                    float xrv = j ? xr[pp].y : xr[pp].x;
                    float xhv = j ? xh[pp].y : xh[pp].x;
                    float z = sigm(xzv + az[i] + bzc[j]);
                    float r = sigm(xrv + ar[i] + brc[j]);
                    float hc = tanhf(xhv + r * (ah2[i] + bhc[j]));
                    hn[j] = z * hprev[i] + (1.f - z) * hc;
                    hprev[i] = hn[j];
                    hmax[i] = fmaxf(hmax[i], hn[j]);
                }
                if (notlast) {
                    int rowg = pp ? r2 : r1;
                    __half2 vh, vl;
                    __half h0b, l0b, h1b, l1b;
                    split_f16(hn[0], h0b, l0b);
                    split_f16(hn[1], h1b, l1b);
                    vh.x = h0b; vh.y = h1b;
                    vl.x = l0b; vl.y = l1b;
                    *(__half2*)&g_hh[np][(size_t)rowg * UG + uc] = vh;
                    *(__half2*)&g_hl[np][(size_t)rowg * UG + uc] = vl;
                }
            }
            if (notlast) {
                const float* xp = g_xp + (size_t)(t + 1) * ((size_t)B * XN);
                const float* xpr1 = xp + (size_t)r1 * XN;
                const float* xpr2 = xp + (size_t)r2 * XN;
                xz[0] = *(const float2*)(xpr1 + uc);        xz[1] = *(const float2*)(xpr2 + uc);
                xr[0] = *(const float2*)(xpr1 + 512 + uc);  xr[1] = *(const float2*)(xpr2 + 512 + uc);
                xh[0] = *(const float2*)(xpr1 + 1024 + uc); xh[1] = *(const float2*)(xpr2 + 1024 + uc);
            }
        }

        if (notlast) {
            __syncthreads();
            if (tid == 0) {
                unsigned target = (unsigned)(t + 1) * NBLK_BT;
                unsigned old = atomAddRel(barp, 1);
                if (old == target - 1) {
                    stRel(genp, (unsigned)(t + 1));
                } else {
                    int spins = 0;
                    while (ldAcq(genp) < (unsigned)(t + 1)) {
                        if (++spins > 64) asm volatile("nanosleep.u32 64;");
                    }
                }
            }
            __syncthreads();
            stageA(np);
        }
    }

    if (kh == 0) {
        float2 v;
        v.x = hmax[0]; v.y = hmax[1]; *(float2*)&g_hmax[(size_t)r1 * UG + uc] = v;
        v.x = hmax[2]; v.y = hmax[3]; *(float2*)&g_hmax[(size_t)r2 * UG + uc] = v;
        v.x = hprev[0]; v.y = hprev[1]; *(float2*)&g_h0f[(size_t)r1 * UG + uc] = v;
        v.x = hprev[2]; v.y = hprev[3]; *(float2*)&g_h0f[(size_t)r2 * UG + uc] = v;
    }
}

// ---------------- epilogue ---------------------------------------------------
__global__ void k_out(const float* __restrict__ Wout, const float* __restrict__ bout,
                      float* __restrict__ dout, int out_size) {
    int b = blockIdx.x;
    int tid = threadIdx.x; // 256
    __shared__ float red[256];
    float s = 0.f;
    for (int uu = tid; uu < UG; uu += 256) s += g_hmax[b * UG + uu] * Wout[uu];
    red[tid] = s;
    __syncthreads();
    for (int o = 128; o > 0; o >>= 1) {
        if (tid < o) red[tid] += red[tid + o];
        __syncthreads();
    }
    if (tid == 0 && b < out_size) dout[b] = eluf(red[0] + bout[0]);
    for (int uu = tid; uu < UG; uu += 256) {
        int idx = B + b * UG + uu;
        if (idx < out_size) dout[idx] = g_h0f[b * UG + uu];
    }
}

// ---------------- launch ------------------------------------------------------
extern "C" void kernel_launch(void* const* d_in, const int* in_sizes, int n_in,
                              void* d_out, int out_size) {
    const float* motion = (const float*)d_in[0];
    const float* robot  = (const float*)d_in[1];
    const float* action = (const float*)d_in[3];
    const float* osc    = (const float*)d_in[4];
    const float* mu     = (const float*)d_in[5];
    const float* mean   = (const float*)d_in[6];
    const float* state  = (const float*)d_in[7];
    const float* W_mot  = (const float*)d_in[8];
    const float* b_mot  = (const float*)d_in[9];
    const float* W_rob  = (const float*)d_in[10];
    const float* b_rob  = (const float*)d_in[11];
    const float* W_comb = (const float*)d_in[12];
    const float* b_comb = (const float*)d_in[13];
    const float* W_oscr = (const float*)d_in[14];
    const float* b_oscr = (const float*)d_in[15];
    const float* W_osci = (const float*)d_in[16];
    const float* b_osci = (const float*)d_in[17];
    const float* gru_k  = (const float*)d_in[18];
    const float* gru_rk = (const float*)d_in[19];
    const float* gru_b  = (const float*)d_in[20];
    const float* W_out  = (const float*)d_in[21];
    const float* b_out  = (const float*)d_in[22];
    float* out = (float*)d_out;

    static bool attr_set = false;
    if (!attr_set) {
        cudaFuncSetAttribute(k_xmma, cudaFuncAttributeMaxDynamicSharedMemorySize, SMEM_GEMM);
        cudaFuncSetAttribute(k_gru, cudaFuncAttributeMaxDynamicSharedMemorySize, SMEM_GRU);
        attr_set = true;
    }

    k_reset<<<1, 32>>>();
    k_msrs<<<B, 256>>>(motion, robot, W_mot, b_mot, W_rob, b_rob);
    k_h0<<<B, 512>>>(state, W_comb, b_comb);
    k_act<<<ROWS, 256>>>(action, mu, mean);
    k_inp23<<<ROWS / 8, 256>>>(osc, W_oscr, b_oscr, W_osci, b_osci);
    k_trb<<<dim3(XN / 32, XK / 32), dim3(32, 8)>>>(gru_k);
    k_trw<<<dim3(XN / 32, UG / 32), dim3(32, 8)>>>(gru_rk);
    k_xmma<<<dim3(XN / 128, ROWS / 128), 256, SMEM_GEMM>>>(gru_b);
    k_gru<<<128, 256, SMEM_GRU>>>(gru_b);
    k_out<<<B, 256>>>(W_out, b_out, out, out_size);
}

// round 9
// speedup vs baseline: 4.0978x; 1.1214x over previous
#include <cuda_runtime.h>
#include <cuda_fp16.h>
#include <cstdint>
#include <math.h>

namespace {
constexpr int B  = 128;
constexpr int T  = 512;
constexpr int A  = 256;
constexpr int UG = 512;
constexpr int ROWS = B * T;       // 65536
constexpr int XK = 768;           // x feature width
constexpr int XN = 1536;          // 3 * UG
}

// ---------------- scratch (device globals; no allocation allowed) ------------
__device__ __half g_xh[(size_t)ROWS * XK];      // fp16 hi of x
__device__ __half g_xl[(size_t)ROWS * XK];      // fp16 lo of x
__device__ __half g_bh[(size_t)XN * XK];        // gru_k^T [N,K] fp16
__device__ __half g_rh[(size_t)XN * UG];        // gru_rk^T [1536,512] fp16
__device__ float g_xp[(size_t)ROWS * XN];       // x @ gru_k + gru_b[0]
__device__ float g_h0f[B * UG];                 // h0 fp32 / final h
__device__ __half g_hh[2][B * UG];              // h ping-pong, fp16 hi
__device__ __half g_hl[2][B * UG];              // h ping-pong, fp16 lo
__device__ float g_hmax[B * UG];
__device__ float g_ms[B * 256];
__device__ float g_rs[B * 256];
__device__ unsigned g_barp[4][32];              // per-btile barrier arrivals (padded)
__device__ unsigned g_genp[4][32];              // per-btile generation (padded)
__device__ unsigned g_tcnt[T];                  // completed xp n-tiles per timestep

__device__ __forceinline__ float eluf(float v) { return v > 0.f ? v : (expf(v) - 1.f); }
__device__ __forceinline__ float sigm(float v) { return 1.f / (1.f + expf(-v)); }
__device__ __forceinline__ void split_f16(float v, __half& h, __half& l) {
    h = __float2half(v);
    l = __float2half(v - __half2float(h));
}

// ---------------- PTX helpers (plain sm_103-safe) -----------------------------
__device__ __forceinline__ uint32_t smem_u32(const void* p) {
    uint32_t a;
    asm("{ .reg .u64 t; cvta.to.shared.u64 t, %1; cvt.u32.u64 %0, t; }" : "=r"(a) : "l"(p));
    return a;
}
__device__ __forceinline__ void cpa16(uint32_t s, const void* g) {
    asm volatile("cp.async.cg.shared.global [%0], [%1], 16;" :: "r"(s), "l"(g));
}
__device__ __forceinline__ void ldm4(uint32_t* r, uint32_t a) {
    asm volatile("ldmatrix.sync.aligned.m8n8.x4.shared.b16 {%0,%1,%2,%3}, [%4];"
                 : "=r"(r[0]), "=r"(r[1]), "=r"(r[2]), "=r"(r[3]) : "r"(a));
}
__device__ __forceinline__ void mma16816(float* c, const uint32_t* a, uint32_t b0, uint32_t b1) {
    asm volatile(
        "mma.sync.aligned.m16n8k16.row.col.f32.f16.f16.f32 "
        "{%0,%1,%2,%3}, {%4,%5,%6,%7}, {%8,%9}, {%0,%1,%2,%3};"
        : "+f"(c[0]), "+f"(c[1]), "+f"(c[2]), "+f"(c[3])
        : "r"(a[0]), "r"(a[1]), "r"(a[2]), "r"(a[3]), "r"(b0), "r"(b1));
}
__device__ __forceinline__ unsigned atomAddRel(unsigned* p, unsigned v) {
    unsigned o;
    asm volatile("atom.release.gpu.global.add.u32 %0, [%1], %2;"
                 : "=r"(o) : "l"(p), "r"(v) : "memory");
    return o;
}
__device__ __forceinline__ void stRel(unsigned* p, unsigned v) {
    asm volatile("st.release.gpu.global.u32 [%0], %1;" :: "l"(p), "r"(v) : "memory");
}
__device__ __forceinline__ unsigned ldAcq(unsigned* p) {
    unsigned v;
    asm volatile("ld.acquire.gpu.global.u32 %0, [%1];" : "=r"(v) : "l"(p) : "memory");
    return v;
}
#define BARNAMED(id, cnt) asm volatile("bar.sync %0, %1;" :: "r"(id), "r"(cnt) : "memory")

// ---------------- small front-end kernels -----------------------------------
__global__ void k_reset() {
    int i = threadIdx.x; // 512
    g_tcnt[i] = 0;
    if (i < 4) { g_barp[i][0] = 0; g_genp[i][0] = 0; }
}

__global__ void k_msrs(const float* __restrict__ motion, const float* __restrict__ robot,
                       const float* __restrict__ Wm, const float* __restrict__ bm,
                       const float* __restrict__ Wr, const float* __restrict__ br) {
    int b = blockIdx.x;
    int j = threadIdx.x; // 256
    __shared__ float sm[64], sr[64];
    if (j < 64) sm[j] = motion[b * 64 + j];
    else if (j < 128) sr[j - 64] = robot[b * 64 + (j - 64)];
    __syncthreads();
    float accm = bm[j], accr = br[j];
    for (int k = 0; k < 64; k++) {
        accm += sm[k] * Wm[k * 256 + j];
        accr += sr[k] * Wr[k * 256 + j];
    }
    g_ms[b * 256 + j] = eluf(accm);
    g_rs[b * 256 + j] = eluf(accr);
}

__global__ void k_h0(const float* __restrict__ state, const float* __restrict__ Wc,
                     const float* __restrict__ bc) {
    int b = blockIdx.x;
    int u = threadIdx.x; // 512
    __shared__ float s[1024];
    s[u] = (u < 256) ? g_ms[b * 256 + u] : g_rs[b * 256 + (u - 256)];
    s[512 + u] = state[b * 512 + u];
    __syncthreads();
    float acc = bc[u];
    for (int k = 0; k < 1024; k++) acc += s[k] * Wc[k * 512 + u];
    float h0 = eluf(acc);
    size_t idx = (size_t)b * 512 + u;
    g_h0f[idx] = h0;
    split_f16(h0, g_hh[0][idx], g_hl[0][idx]);
}

__global__ void k_act(const float* __restrict__ action, const float* __restrict__ mu,
                      const float* __restrict__ mean) {
    int r = blockIdx.x;
    int t = r >> 7;
    int b = r & 127;
    int a = threadIdx.x;
    float v = action[((size_t)b * T + t) * A + a] * mu[b * A + a] + mean[b * A + a];
    size_t idx = (size_t)r * XK + a;
    split_f16(v, g_xh[idx], g_xl[idx]);
}

// fused inp2 + inp3
__global__ void k_inp23(const float* __restrict__ osc,
                        const float* __restrict__ W2, const float* __restrict__ b2,
                        const float* __restrict__ W3, const float* __restrict__ b3) {
    int r0 = blockIdx.x * 8;
    int j = threadIdx.x; // 256
    __shared__ float sin_[8][64];
    __shared__ float smid[8][256];
    for (int i = threadIdx.x; i < 8 * 64; i += 256) {
        int rr = i >> 6, k = i & 63;
        int r = r0 + rr;
        int t = r >> 7, b = r & 127;
        sin_[rr][k] = osc[((size_t)b * T + t) * 128 + k];
    }
    __syncthreads();
    {
        float bj = b2[j];
        float acc[8];
#pragma unroll
        for (int i = 0; i < 8; i++) acc[i] = bj;
        for (int k = 0; k < 64; k++) {
            float w = W2[k * 256 + j];
#pragma unroll
            for (int i = 0; i < 8; i++) acc[i] += sin_[i][k] * w;
        }
#pragma unroll
        for (int i = 0; i < 8; i++) {
            float v = eluf(acc[i]);
            smid[i][j] = v;
            size_t idx = (size_t)(r0 + i) * XK + 256 + j;
            split_f16(v, g_xh[idx], g_xl[idx]);
        }
    }
    __syncthreads();
    {
        float bj = b3[j];
        float acc[8];
#pragma unroll
        for (int i = 0; i < 8; i++) acc[i] = bj;
        for (int k = 0; k < 192; k++) {
            float w = W3[k * 256 + j];
#pragma unroll
            for (int i = 0; i < 8; i++) acc[i] += smid[i][64 + k] * w;
        }
#pragma unroll
        for (int i = 0; i < 8; i++) {
            size_t idx = (size_t)(r0 + i) * XK + 512 + j;
            split_f16(eluf(acc[i]), g_xh[idx], g_xl[idx]);
        }
    }
}

// transpose gru_k [768,1536] -> g_bh [1536,768] fp16
__global__ void k_trb(const float* __restrict__ gk) {
    __shared__ float s[32][33];
    int n0 = blockIdx.x * 32, k0 = blockIdx.y * 32;
    int tx = threadIdx.x, ty = threadIdx.y; // 32 x 8
#pragma unroll
    for (int i = 0; i < 32; i += 8)
        s[ty + i][tx] = gk[(size_t)(k0 + ty + i) * XN + n0 + tx];
    __syncthreads();
#pragma unroll
    for (int i = 0; i < 32; i += 8) {
        size_t idx = (size_t)(n0 + ty + i) * XK + k0 + tx;
        g_bh[idx] = __float2half(s[tx][ty + i]);
    }
}

// transpose gru_rk [512,1536] -> g_rh [1536,512] fp16
__global__ void k_trw(const float* __restrict__ wr) {
    __shared__ float s[32][33];
    int n0 = blockIdx.x * 32, k0 = blockIdx.y * 32;
    int tx = threadIdx.x, ty = threadIdx.y; // 32 x 8
#pragma unroll
    for (int i = 0; i < 32; i += 8)
        s[ty + i][tx] = wr[(size_t)(k0 + ty + i) * XN + n0 + tx];
    __syncthreads();
#pragma unroll
    for (int i = 0; i < 32; i += 8) {
        size_t idx = (size_t)(n0 + ty + i) * UG + k0 + tx;
        g_rh[idx] = __float2half(s[tx][ty + i]);
    }
}

// ---------------- FUSED persistent kernel -------------------------------------
// 128 blocks x 384 threads.
//   warps 0-7  (tid 0..255):  xp production (tile 128x128, fp16 2-term, 3-stage)
//   warps 8-11 (tid 256..383): GRU recurrence (block owns 32 b x 16 u, full-K warps)
// Producers bump g_tcnt[t] (12 n-tiles per t); recurrence acquires it before use.
namespace {
// production smem (same as R7 k_xmma)
constexpr int PITCHB = 80;
constexpr int ARRB   = 128 * PITCHB;       // 10240
constexpr int BUFB   = 3 * ARRB;           // 30720 : AH | AL | BH
constexpr int PROD_BYTES = 3 * BUFB;       // 92160
constexpr int KCH = 24;
constexpr int NJOBS = T * (XN / 128);      // 6144, 12 per t
// recurrence smem (after production region)
constexpr int PITCH = 1040;
constexpr int WSEC  = 16 * PITCH;              // 16640 per gate
constexpr int W_OFF = PROD_BYTES;              // 92160
constexpr int AHI_OFF = W_OFF + 3 * WSEC;      // 142080
constexpr int ALO_OFF = AHI_OFF + 32 * PITCH;  // 175360
constexpr int SMEM_FUSED = ALO_OFF + 32 * PITCH; // 208640
constexpr int NBLK_BT = 32;
}

__global__ void __launch_bounds__(384, 1) k_fused(const float* __restrict__ gb) {
    extern __shared__ char smem[];
    const uint32_t sb = smem_u32(smem);
    const int tid = threadIdx.x;

    if (tid < 256) {
        // ================= PRODUCTION =================
        const int lane = tid & 31, wid = tid >> 5;
        const int wm = wid & 3;
        const int wn = wid >> 2;
        const uint32_t aAddr = sb + (wm * 32 + (lane & 15)) * PITCHB + (lane >> 4) * 16;
        const uint32_t bAddr = sb + 2 * ARRB + (wn * 64 + (lane & 15)) * PITCHB + (lane >> 4) * 16;

        for (int job = blockIdx.x; job < NJOBS; job += 128) {
            const int t = job / 12, nt = job % 12;
            const int m0 = t * 128;
            const int n0 = nt * 128;
            const __half* gp0 = g_xh + (size_t)m0 * XK;
            const __half* gp1 = g_xl + (size_t)m0 * XK;
            const __half* gp2 = g_bh + (size_t)n0 * XK;

            auto load_chunk = [&](int c, int buf) {
                uint32_t base = sb + buf * BUFB;
#pragma unroll
                for (int l = 0; l < 6; l++) {
                    int idx = tid + 256 * l;
                    int arr = idx >> 9;
                    int rem = idx & 511;
                    int row = rem >> 2;
                    int cch = rem & 3;
                    const __half* g = (arr == 0) ? gp0 : (arr == 1) ? gp1 : gp2;
                    cpa16(base + arr * ARRB + row * PITCHB + cch * 16,
                          g + (size_t)row * XK + c * 32 + cch * 8);
                }
                asm volatile("cp.async.commit_group;" ::: "memory");
            };

            float acc[2][8][4];
#pragma unroll
            for (int i = 0; i < 2; i++)
#pragma unroll
                for (int jj = 0; jj < 8; jj++)
#pragma unroll
                    for (int q = 0; q < 4; q++) acc[i][jj][q] = 0.f;

            load_chunk(0, 0);
            load_chunk(1, 1);

            for (int c = 0; c < KCH; c++) {
                if (c + 1 < KCH) asm volatile("cp.async.wait_group 1;" ::: "memory");
                else             asm volatile("cp.async.wait_group 0;" ::: "memory");
                BARNAMED(2, 256);
                if (c + 2 < KCH) load_chunk(c + 2, (c + 2) % 3);

                uint32_t boff = (c % 3) * BUFB;
#pragma unroll
                for (int ks = 0; ks < 2; ks++) {
                    uint32_t ah[2][4], al[2][4], bh[4][4];
#pragma unroll
                    for (int mt = 0; mt < 2; mt++) {
                        uint32_t a = aAddr + boff + mt * (16 * PITCHB) + ks * 32;
                        ldm4(ah[mt], a);
                        ldm4(al[mt], a + ARRB);
                    }
#pragma unroll
                    for (int ng = 0; ng < 4; ng++) {
                        uint32_t a = bAddr + boff + ng * (16 * PITCHB) + ks * 32;
                        ldm4(bh[ng], a);
                    }
#pragma unroll
                    for (int mt = 0; mt < 2; mt++)
#pragma unroll
                        for (int ng = 0; ng < 4; ng++)
#pragma unroll
                            for (int hf = 0; hf < 2; hf++) {
                                int ntl = ng * 2 + hf;
                                mma16816(acc[mt][ntl], ah[mt], bh[ng][hf], bh[ng][hf + 2]);
                                mma16816(acc[mt][ntl], al[mt], bh[ng][hf], bh[ng][hf + 2]);
                            }
                }
            }

            const int qr = lane >> 2, qc = lane & 3;
#pragma unroll
            for (int mt = 0; mt < 2; mt++)
#pragma unroll
                for (int ntl = 0; ntl < 8; ntl++) {
                    int nb = n0 + wn * 64 + ntl * 8 + 2 * qc;
                    float b0 = gb[nb], b1 = gb[nb + 1];
#pragma unroll
                    for (int rp = 0; rp < 2; rp++) {
                        int m = m0 + wm * 32 + mt * 16 + qr + 8 * rp;
                        float2 v = make_float2(acc[mt][ntl][2 * rp] + b0,
                                               acc[mt][ntl][2 * rp + 1] + b1);
                        *(float2*)&g_xp[(size_t)m * XN + nb] = v;
                    }
                }

            __threadfence();
            BARNAMED(2, 256);
            if (tid == 0) atomAddRel(&g_tcnt[t], 1u);
        }
    } else {
        // ================= RECURRENCE =================
        const int ltid = tid - 256;            // 0..127
        const int lane = ltid & 31, lwid = ltid >> 5;  // 4 warps
        const int mt = lwid & 1;               // m16 tile within 32 rows
        const int uh = lwid >> 1;              // u-half (8 u)
        const int bt = blockIdx.x & 3;
        const int ut = blockIdx.x >> 2;
        const int u0 = ut * 16;
        const int row0 = bt * 32;
        const int qr = lane >> 2, qc = lane & 3;
        const int r1 = row0 + mt * 16 + qr;
        const int r2 = r1 + 8;
        const int uc = u0 + uh * 8 + 2 * qc;

        // W slice -> smem (once): 3 gates x 16 n x 512 k fp16
        for (int idx = ltid; idx < 3072; idx += 128) {
            int sec = idx >> 10;               // gate 0..2
            int rem = idx & 1023;
            int r = rem >> 6, ch = rem & 63;
            cpa16(sb + W_OFF + sec * WSEC + r * PITCH + ch * 16,
                  g_rh + ((size_t)(sec * 512 + u0 + r)) * UG + ch * 8);
        }
        asm volatile("cp.async.commit_group;" ::: "memory");

        const float* gbr = gb + XN;
        float bzc[2], brc[2], bhc[2];
#pragma unroll
        for (int j = 0; j < 2; j++) {
            bzc[j] = gbr[uc + j];
            brc[j] = gbr[512 + uc + j];
            bhc[j] = gbr[1024 + uc + j];
        }

        float hprev[4], hmax[4];
        hprev[0] = g_h0f[(size_t)r1 * UG + uc];
        hprev[1] = g_h0f[(size_t)r1 * UG + uc + 1];
        hprev[2] = g_h0f[(size_t)r2 * UG + uc];
        hprev[3] = g_h0f[(size_t)r2 * UG + uc + 1];
#pragma unroll
        for (int i = 0; i < 4; i++) hmax[i] = -INFINITY;

        const uint32_t aHi = sb + AHI_OFF + (mt * 16 + (lane & 15)) * PITCH +
                             ((lane >> 4) & 1) * 16;
        const uint32_t aLo = aHi + (ALO_OFF - AHI_OFF);
        uint32_t bHi[3];
        {
            int brow = uh * 8 + (lane & 7);
            int bch = lane >> 3;               // 0..3 -> 64B = k32
#pragma unroll
            for (int g = 0; g < 3; g++)
                bHi[g] = sb + W_OFF + g * WSEC + brow * PITCH + bch * 16;
        }

        auto stageA = [&](int par) {
            const __half* shp = g_hh[par] + (size_t)row0 * UG;
            const __half* slp = g_hl[par] + (size_t)row0 * UG;
            for (int idx = ltid; idx < 2048; idx += 128) {
                int r = idx >> 6, ch = idx & 63;
                cpa16(sb + AHI_OFF + r * PITCH + ch * 16, shp + (size_t)r * UG + ch * 8);
                cpa16(sb + ALO_OFF + r * PITCH + ch * 16, slp + (size_t)r * UG + ch * 8);
            }
            asm volatile("cp.async.commit_group;" ::: "memory");
        };

        stageA(0);

        // wait for xp(0) to be produced, then prefetch
        {
            int spins = 0;
            while (ldAcq(&g_tcnt[0]) < 12u) {
                if (++spins > 16) asm volatile("nanosleep.u32 128;");
            }
        }
        float2 xz[2], xr[2], xh[2];
        {
            const float* xpr1 = g_xp + (size_t)r1 * XN;
            const float* xpr2 = g_xp + (size_t)r2 * XN;
            xz[0] = *(const float2*)(xpr1 + uc);        xz[1] = *(const float2*)(xpr2 + uc);
            xr[0] = *(const float2*)(xpr1 + 512 + uc);  xr[1] = *(const float2*)(xpr2 + 512 + uc);
            xh[0] = *(const float2*)(xpr1 + 1024 + uc); xh[1] = *(const float2*)(xpr2 + 1024 + uc);
        }

        unsigned* barp = &g_barp[bt][0];
        unsigned* genp = &g_genp[bt][0];

        for (int t = 0; t < T; t++) {
            asm volatile("cp.async.wait_group 0;" ::: "memory");
            BARNAMED(1, 128);

            float az[4] = {0.f, 0.f, 0.f, 0.f};
            float ar[4] = {0.f, 0.f, 0.f, 0.f};
            float ah2[4] = {0.f, 0.f, 0.f, 0.f};

#pragma unroll 4
            for (int j = 0; j < 16; j++) {     // k32 per iter, full K=512
                uint32_t ah0[4], ah1[4], al0[4], al1[4];
                uint32_t a = aHi + j * 64;
                ldm4(ah0, a);
                ldm4(ah1, a + 32);
                uint32_t al = aLo + j * 64;
                ldm4(al0, al);
                ldm4(al1, al + 32);
                uint32_t b4h[4];
                // gate z
                ldm4(b4h, bHi[0] + j * 64);
                mma16816(az, ah0, b4h[0], b4h[1]);
                mma16816(az, al0, b4h[0], b4h[1]);
                mma16816(az, ah1, b4h[2], b4h[3]);
                mma16816(az, al1, b4h[2], b4h[3]);
                // gate r
                ldm4(b4h, bHi[1] + j * 64);
                mma16816(ar, ah0, b4h[0], b4h[1]);
                mma16816(ar, al0, b4h[0], b4h[1]);
                mma16816(ar, ah1, b4h[2], b4h[3]);
                mma16816(ar, al1, b4h[2], b4h[3]);
                // gate h
                ldm4(b4h, bHi[2] + j * 64);
                mma16816(ah2, ah0, b4h[0], b4h[1]);
                mma16816(ah2, al0, b4h[0], b4h[1]);
                mma16816(ah2, ah1, b4h[2], b4h[3]);
                mma16816(ah2, al1, b4h[2], b4h[3]);
            }

            int np = (t + 1) & 1;
            bool notlast = (t + 1 < T);
#pragma unroll
            for (int pp = 0; pp < 2; pp++) {
                float hn[2];
#pragma unroll
                for (int j = 0; j < 2; j++) {
                    int i = 2 * pp + j;
                    float xzv = j ? xz[pp].y : xz[pp].x;
                    float xrv = j ? xr[pp].y : xr[pp].x;
                    float xhv = j ? xh[pp].y : xh[pp].x;
                    float z = sigm(xzv + az[i] + bzc[j]);
                    float r = sigm(xrv + ar[i] + brc[j]);
                    float hc = tanhf(xhv + r * (ah2[i] + bhc[j]));
                    hn[j] = z * hprev[i] + (1.f - z) * hc;
                    hprev[i] = hn[j];
                    hmax[i] = fmaxf(hmax[i], hn[j]);
                }
                if (notlast) {
                    int rowg = pp ? r2 : r1;
                    __half2 vh, vl;
                    __half h0b, l0b, h1b, l1b;
                    split_f16(hn[0], h0b, l0b);
                    split_f16(hn[1], h1b, l1b);
                    vh.x = h0b; vh.y = h1b;
                    vl.x = l0b; vl.y = l1b;
                    *(__half2*)&g_hh[np][(size_t)rowg * UG + uc] = vh;
                    *(__half2*)&g_hl[np][(size_t)rowg * UG + uc] = vl;
                }
            }

            if (notlast) {
                // wait for xp(t+1) production, then prefetch it
                {
                    int spins = 0;
                    while (ldAcq(&g_tcnt[t + 1]) < 12u) {
                        if (++spins > 16) asm volatile("nanosleep.u32 128;");
                    }
                }
                {
                    const float* xp = g_xp + (size_t)(t + 1) * ((size_t)B * XN);
                    const float* xpr1 = xp + (size_t)r1 * XN;
                    const float* xpr2 = xp + (size_t)r2 * XN;
                    xz[0] = *(const float2*)(xpr1 + uc);        xz[1] = *(const float2*)(xpr2 + uc);
                    xr[0] = *(const float2*)(xpr1 + 512 + uc);  xr[1] = *(const float2*)(xpr2 + 512 + uc);
                    xh[0] = *(const float2*)(xpr1 + 1024 + uc); xh[1] = *(const float2*)(xpr2 + 1024 + uc);
                }
                BARNAMED(1, 128);          // h stores complete
                if (ltid == 0) {
                    unsigned target = (unsigned)(t + 1) * NBLK_BT;
                    unsigned old = atomAddRel(barp, 1);
                    if (old == target - 1) {
                        stRel(genp, (unsigned)(t + 1));
                    } else {
                        int spins = 0;
                        while (ldAcq(genp) < (unsigned)(t + 1)) {
                            if (++spins > 64) asm volatile("nanosleep.u32 64;");
                        }
                    }
                }
                BARNAMED(1, 128);
                stageA(np);
            }
        }

        float2 v;
        v.x = hmax[0]; v.y = hmax[1]; *(float2*)&g_hmax[(size_t)r1 * UG + uc] = v;
        v.x = hmax[2]; v.y = hmax[3]; *(float2*)&g_hmax[(size_t)r2 * UG + uc] = v;
        v.x = hprev[0]; v.y = hprev[1]; *(float2*)&g_h0f[(size_t)r1 * UG + uc] = v;
        v.x = hprev[2]; v.y = hprev[3]; *(float2*)&g_h0f[(size_t)r2 * UG + uc] = v;
    }
}

// ---------------- epilogue ---------------------------------------------------
__global__ void k_out(const float* __restrict__ Wout, const float* __restrict__ bout,
                      float* __restrict__ dout, int out_size) {
    int b = blockIdx.x;
    int tid = threadIdx.x; // 256
    __shared__ float red[256];
    float s = 0.f;
    for (int uu = tid; uu < UG; uu += 256) s += g_hmax[b * UG + uu] * Wout[uu];
    red[tid] = s;
    __syncthreads();
    for (int o = 128; o > 0; o >>= 1) {
        if (tid < o) red[tid] += red[tid + o];
        __syncthreads();
    }
    if (tid == 0 && b < out_size) dout[b] = eluf(red[0] + bout[0]);
    for (int uu = tid; uu < UG; uu += 256) {
        int idx = B + b * UG + uu;
        if (idx < out_size) dout[idx] = g_h0f[b * UG + uu];
    }
}

// ---------------- launch ------------------------------------------------------
extern "C" void kernel_launch(void* const* d_in, const int* in_sizes, int n_in,
                              void* d_out, int out_size) {
    const float* motion = (const float*)d_in[0];
    const float* robot  = (const float*)d_in[1];
    const float* action = (const float*)d_in[3];
    const float* osc    = (const float*)d_in[4];
    const float* mu     = (const float*)d_in[5];
    const float* mean   = (const float*)d_in[6];
    const float* state  = (const float*)d_in[7];
    const float* W_mot  = (const float*)d_in[8];
    const float* b_mot  = (const float*)d_in[9];
    const float* W_rob  = (const float*)d_in[10];
    const float* b_rob  = (const float*)d_in[11];
    const float* W_comb = (const float*)d_in[12];
    const float* b_comb = (const float*)d_in[13];
    const float* W_oscr = (const float*)d_in[14];
    const float* b_oscr = (const float*)d_in[15];
    const float* W_osci = (const float*)d_in[16];
    const float* b_osci = (const float*)d_in[17];
    const float* gru_k  = (const float*)d_in[18];
    const float* gru_rk = (const float*)d_in[19];
    const float* gru_b  = (const float*)d_in[20];
    const float* W_out  = (const float*)d_in[21];
    const float* b_out  = (const float*)d_in[22];
    float* out = (float*)d_out;

    static bool attr_set = false;
    if (!attr_set) {
        cudaFuncSetAttribute(k_fused, cudaFuncAttributeMaxDynamicSharedMemorySize, SMEM_FUSED);
        attr_set = true;
    }

    k_reset<<<1, 512>>>();
    k_msrs<<<B, 256>>>(motion, robot, W_mot, b_mot, W_rob, b_rob);
    k_h0<<<B, 512>>>(state, W_comb, b_comb);
    k_act<<<ROWS, 256>>>(action, mu, mean);
    k_inp23<<<ROWS / 8, 256>>>(osc, W_oscr, b_oscr, W_osci, b_osci);
    k_trb<<<dim3(XN / 32, XK / 32), dim3(32, 8)>>>(gru_k);
    k_trw<<<dim3(XN / 32, UG / 32), dim3(32, 8)>>>(gru_rk);
    k_fused<<<128, 384, SMEM_FUSED>>>(gru_b);
    k_out<<<B, 256>>>(W_out, b_out, out, out_size);
}

// round 10
// speedup vs baseline: 4.3025x; 1.0500x over previous
#include <cuda_runtime.h>
#include <cuda_fp16.h>
#include <cstdint>
#include <math.h>

namespace {
constexpr int B  = 128;
constexpr int T  = 512;
constexpr int A  = 256;
constexpr int UG = 512;
constexpr int ROWS = B * T;       // 65536
constexpr int XK = 768;           // x feature width
constexpr int XN = 1536;          // 3 * UG
}

// ---------------- scratch (device globals; no allocation allowed) ------------
__device__ __half g_xh[(size_t)ROWS * XK];      // fp16 x
__device__ __half g_bh[(size_t)XN * XK];        // gru_k^T [N,K] fp16
__device__ __half g_rh[(size_t)XN * UG];        // gru_rk^T [1536,512] fp16
__device__ float g_xp[(size_t)ROWS * XN];       // x @ gru_k + gru_b[0]
__device__ float g_h0f[B * UG];                 // h0 fp32 / final h
__device__ __half g_hh[2][B * UG];              // h ping-pong, fp16 hi
__device__ __half g_hl[2][B * UG];              // h ping-pong, fp16 lo
__device__ float g_hmax[B * UG];
__device__ float g_ms[B * 256];
__device__ float g_rs[B * 256];
__device__ unsigned g_barp[4][32];              // per-btile barrier arrivals (padded)
__device__ unsigned g_genp[4][32];              // per-btile generation (padded)
__device__ unsigned g_tcnt[T];                  // completed xp n-tiles per timestep

__device__ __forceinline__ float eluf(float v) { return v > 0.f ? v : (expf(v) - 1.f); }
__device__ __forceinline__ float sigm(float v) { return 1.f / (1.f + expf(-v)); }
__device__ __forceinline__ void split_f16(float v, __half& h, __half& l) {
    h = __float2half(v);
    l = __float2half(v - __half2float(h));
}

// ---------------- PTX helpers (plain sm_103-safe) -----------------------------
__device__ __forceinline__ uint32_t smem_u32(const void* p) {
    uint32_t a;
    asm("{ .reg .u64 t; cvta.to.shared.u64 t, %1; cvt.u32.u64 %0, t; }" : "=r"(a) : "l"(p));
    return a;
}
__device__ __forceinline__ void cpa16(uint32_t s, const void* g) {
    asm volatile("cp.async.cg.shared.global [%0], [%1], 16;" :: "r"(s), "l"(g));
}
__device__ __forceinline__ void ldm4(uint32_t* r, uint32_t a) {
    asm volatile("ldmatrix.sync.aligned.m8n8.x4.shared.b16 {%0,%1,%2,%3}, [%4];"
                 : "=r"(r[0]), "=r"(r[1]), "=r"(r[2]), "=r"(r[3]) : "r"(a));
}
__device__ __forceinline__ void mma16816(float* c, const uint32_t* a, uint32_t b0, uint32_t b1) {
    asm volatile(
        "mma.sync.aligned.m16n8k16.row.col.f32.f16.f16.f32 "
        "{%0,%1,%2,%3}, {%4,%5,%6,%7}, {%8,%9}, {%0,%1,%2,%3};"
        : "+f"(c[0]), "+f"(c[1]), "+f"(c[2]), "+f"(c[3])
        : "r"(a[0]), "r"(a[1]), "r"(a[2]), "r"(a[3]), "r"(b0), "r"(b1));
}
__device__ __forceinline__ unsigned atomAddRel(unsigned* p, unsigned v) {
    unsigned o;
    asm volatile("atom.release.gpu.global.add.u32 %0, [%1], %2;"
                 : "=r"(o) : "l"(p), "r"(v) : "memory");
    return o;
}
__device__ __forceinline__ void stRel(unsigned* p, unsigned v) {
    asm volatile("st.release.gpu.global.u32 [%0], %1;" :: "l"(p), "r"(v) : "memory");
}
__device__ __forceinline__ unsigned ldAcq(unsigned* p) {
    unsigned v;
    asm volatile("ld.acquire.gpu.global.u32 %0, [%1];" : "=r"(v) : "l"(p) : "memory");
    return v;
}
#define BARNAMED(id, cnt) asm volatile("bar.sync %0, %1;" :: "r"(id), "r"(cnt) : "memory")

// ---------------- small front-end kernels -----------------------------------
__global__ void k_reset() {
    int i = threadIdx.x; // 512
    g_tcnt[i] = 0;
    if (i < 4) { g_barp[i][0] = 0; g_genp[i][0] = 0; }
}

__global__ void k_msrs(const float* __restrict__ motion, const float* __restrict__ robot,
                       const float* __restrict__ Wm, const float* __restrict__ bm,
                       const float* __restrict__ Wr, const float* __restrict__ br) {
    int b = blockIdx.x;
    int j = threadIdx.x; // 256
    __shared__ float sm[64], sr[64];
    if (j < 64) sm[j] = motion[b * 64 + j];
    else if (j < 128) sr[j - 64] = robot[b * 64 + (j - 64)];
    __syncthreads();
    float accm = bm[j], accr = br[j];
    for (int k = 0; k < 64; k++) {
        accm += sm[k] * Wm[k * 256 + j];
        accr += sr[k] * Wr[k * 256 + j];
    }
    g_ms[b * 256 + j] = eluf(accm);
    g_rs[b * 256 + j] = eluf(accr);
}

__global__ void k_h0(const float* __restrict__ state, const float* __restrict__ Wc,
                     const float* __restrict__ bc) {
    int b = blockIdx.x;
    int u = threadIdx.x; // 512
    __shared__ float s[1024];
    s[u] = (u < 256) ? g_ms[b * 256 + u] : g_rs[b * 256 + (u - 256)];
    s[512 + u] = state[b * 512 + u];
    __syncthreads();
    float acc = bc[u];
    for (int k = 0; k < 1024; k++) acc += s[k] * Wc[k * 512 + u];
    float h0 = eluf(acc);
    size_t idx = (size_t)b * 512 + u;
    g_h0f[idx] = h0;
    split_f16(h0, g_hh[0][idx], g_hl[0][idx]);
}

__global__ void k_act(const float* __restrict__ action, const float* __restrict__ mu,
                      const float* __restrict__ mean) {
    int r = blockIdx.x;
    int t = r >> 7;
    int b = r & 127;
    int a = threadIdx.x;
    float v = action[((size_t)b * T + t) * A + a] * mu[b * A + a] + mean[b * A + a];
    g_xh[(size_t)r * XK + a] = __float2half(v);
}

// fused inp2 + inp3
__global__ void k_inp23(const float* __restrict__ osc,
                        const float* __restrict__ W2, const float* __restrict__ b2,
                        const float* __restrict__ W3, const float* __restrict__ b3) {
    int r0 = blockIdx.x * 8;
    int j = threadIdx.x; // 256
    __shared__ float sin_[8][64];
    __shared__ float smid[8][256];
    for (int i = threadIdx.x; i < 8 * 64; i += 256) {
        int rr = i >> 6, k = i & 63;
        int r = r0 + rr;
        int t = r >> 7, b = r & 127;
        sin_[rr][k] = osc[((size_t)b * T + t) * 128 + k];
    }
    __syncthreads();
    {
        float bj = b2[j];
        float acc[8];
#pragma unroll
        for (int i = 0; i < 8; i++) acc[i] = bj;
        for (int k = 0; k < 64; k++) {
            float w = W2[k * 256 + j];
#pragma unroll
            for (int i = 0; i < 8; i++) acc[i] += sin_[i][k] * w;
        }
#pragma unroll
        for (int i = 0; i < 8; i++) {
            float v = eluf(acc[i]);
            smid[i][j] = v;
            g_xh[(size_t)(r0 + i) * XK + 256 + j] = __float2half(v);
        }
    }
    __syncthreads();
    {
        float bj = b3[j];
        float acc[8];
#pragma unroll
        for (int i = 0; i < 8; i++) acc[i] = bj;
        for (int k = 0; k < 192; k++) {
            float w = W3[k * 256 + j];
#pragma unroll
            for (int i = 0; i < 8; i++) acc[i] += smid[i][64 + k] * w;
        }
#pragma unroll
        for (int i = 0; i < 8; i++)
            g_xh[(size_t)(r0 + i) * XK + 512 + j] = __float2half(eluf(acc[i]));
    }
}

// transpose gru_k [768,1536] -> g_bh [1536,768] fp16
__global__ void k_trb(const float* __restrict__ gk) {
    __shared__ float s[32][33];
    int n0 = blockIdx.x * 32, k0 = blockIdx.y * 32;
    int tx = threadIdx.x, ty = threadIdx.y; // 32 x 8
#pragma unroll
    for (int i = 0; i < 32; i += 8)
        s[ty + i][tx] = gk[(size_t)(k0 + ty + i) * XN + n0 + tx];
    __syncthreads();
#pragma unroll
    for (int i = 0; i < 32; i += 8) {
        size_t idx = (size_t)(n0 + ty + i) * XK + k0 + tx;
        g_bh[idx] = __float2half(s[tx][ty + i]);
    }
}

// transpose gru_rk [512,1536] -> g_rh [1536,512] fp16
__global__ void k_trw(const float* __restrict__ wr) {
    __shared__ float s[32][33];
    int n0 = blockIdx.x * 32, k0 = blockIdx.y * 32;
    int tx = threadIdx.x, ty = threadIdx.y; // 32 x 8
#pragma unroll
    for (int i = 0; i < 32; i += 8)
        s[ty + i][tx] = wr[(size_t)(k0 + ty + i) * XN + n0 + tx];
    __syncthreads();
#pragma unroll
    for (int i = 0; i < 32; i += 8) {
        size_t idx = (size_t)(n0 + ty + i) * UG + k0 + tx;
        g_rh[idx] = __float2half(s[tx][ty + i]);
    }
}

// ---------------- FUSED persistent kernel -------------------------------------
// 128 blocks x 384 threads.
//   warps 0-7  (tid 0..255):  xp production (tile 128x128, fp16 1-term, 3-stage)
//   warps 8-11 (tid 256..383): GRU recurrence (block owns 32 b x 16 u)
namespace {
constexpr int PITCHB = 80;
constexpr int ARRB   = 128 * PITCHB;       // 10240
constexpr int BUFB   = 2 * ARRB;           // 20480 : A | B
constexpr int PROD_BYTES = 3 * BUFB;       // 61440
constexpr int KCH = 24;
constexpr int NJOBS = T * (XN / 128);      // 6144, 12 per t
constexpr int PITCH = 1040;
constexpr int WSEC  = 16 * PITCH;              // 16640 per gate
constexpr int W_OFF = PROD_BYTES;              // 61440
constexpr int AHI_OFF = W_OFF + 3 * WSEC;      // 111360
constexpr int ALO_OFF = AHI_OFF + 32 * PITCH;  // 144640
constexpr int SMEM_FUSED = ALO_OFF + 32 * PITCH; // 177920
constexpr int NBLK_BT = 32;
}

__global__ void __launch_bounds__(384, 1) k_fused(const float* __restrict__ gb) {
    extern __shared__ char smem[];
    const uint32_t sb = smem_u32(smem);
    const int tid = threadIdx.x;

    if (tid < 256) {
        // ================= PRODUCTION (1-term fp16) =================
        const int lane = tid & 31, wid = tid >> 5;
        const int wm = wid & 3;
        const int wn = wid >> 2;
        const uint32_t aAddr = sb + (wm * 32 + (lane & 15)) * PITCHB + (lane >> 4) * 16;
        const uint32_t bAddr = sb + ARRB + (wn * 64 + (lane & 15)) * PITCHB + (lane >> 4) * 16;

        for (int job = blockIdx.x; job < NJOBS; job += 128) {
            const int t = job / 12, nt = job % 12;
            const int m0 = t * 128;
            const int n0 = nt * 128;
            const __half* gp0 = g_xh + (size_t)m0 * XK;
            const __half* gp1 = g_bh + (size_t)n0 * XK;

            auto load_chunk = [&](int c, int buf) {
                uint32_t base = sb + buf * BUFB;
#pragma unroll
                for (int l = 0; l < 4; l++) {
                    int idx = tid + 256 * l;
                    int arr = idx >> 9;            // 0..1
                    int rem = idx & 511;
                    int row = rem >> 2;
                    int cch = rem & 3;
                    const __half* g = arr ? gp1 : gp0;
                    cpa16(base + arr * ARRB + row * PITCHB + cch * 16,
                          g + (size_t)row * XK + c * 32 + cch * 8);
                }
                asm volatile("cp.async.commit_group;" ::: "memory");
            };

            float acc[2][8][4];
#pragma unroll
            for (int i = 0; i < 2; i++)
#pragma unroll
                for (int jj = 0; jj < 8; jj++)
#pragma unroll
                    for (int q = 0; q < 4; q++) acc[i][jj][q] = 0.f;

            load_chunk(0, 0);
            load_chunk(1, 1);

            for (int c = 0; c < KCH; c++) {
                if (c + 1 < KCH) asm volatile("cp.async.wait_group 1;" ::: "memory");
                else             asm volatile("cp.async.wait_group 0;" ::: "memory");
                BARNAMED(2, 256);
                if (c + 2 < KCH) load_chunk(c + 2, (c + 2) % 3);

                uint32_t boff = (c % 3) * BUFB;
#pragma unroll
                for (int ks = 0; ks < 2; ks++) {
                    uint32_t ah[2][4], bh[4][4];
#pragma unroll
                    for (int mt = 0; mt < 2; mt++)
                        ldm4(ah[mt], aAddr + boff + mt * (16 * PITCHB) + ks * 32);
#pragma unroll
                    for (int ng = 0; ng < 4; ng++)
                        ldm4(bh[ng], bAddr + boff + ng * (16 * PITCHB) + ks * 32);
#pragma unroll
                    for (int mt = 0; mt < 2; mt++)
#pragma unroll
                        for (int ng = 0; ng < 4; ng++)
#pragma unroll
                            for (int hf = 0; hf < 2; hf++)
                                mma16816(acc[mt][ng * 2 + hf], ah[mt],
                                         bh[ng][hf], bh[ng][hf + 2]);
                }
            }

            const int qr = lane >> 2, qc = lane & 3;
#pragma unroll
            for (int mt = 0; mt < 2; mt++)
#pragma unroll
                for (int ntl = 0; ntl < 8; ntl++) {
                    int nb = n0 + wn * 64 + ntl * 8 + 2 * qc;
                    float b0 = gb[nb], b1 = gb[nb + 1];
#pragma unroll
                    for (int rp = 0; rp < 2; rp++) {
                        int m = m0 + wm * 32 + mt * 16 + qr + 8 * rp;
                        float2 v = make_float2(acc[mt][ntl][2 * rp] + b0,
                                               acc[mt][ntl][2 * rp + 1] + b1);
                        *(float2*)&g_xp[(size_t)m * XN + nb] = v;
                    }
                }

            __threadfence();
            BARNAMED(2, 256);
            if (tid == 0) atomAddRel(&g_tcnt[t], 1u);
        }
    } else {
        // ================= RECURRENCE (2-term h) =================
        const int ltid = tid - 256;            // 0..127
        const int lane = ltid & 31, lwid = ltid >> 5;
        const int mt = lwid & 1;
        const int uh = lwid >> 1;
        const int bt = blockIdx.x & 3;
        const int ut = blockIdx.x >> 2;
        const int u0 = ut * 16;
        const int row0 = bt * 32;
        const int qr = lane >> 2, qc = lane & 3;
        const int r1 = row0 + mt * 16 + qr;
        const int r2 = r1 + 8;
        const int uc = u0 + uh * 8 + 2 * qc;

        for (int idx = ltid; idx < 3072; idx += 128) {
            int sec = idx >> 10;
            int rem = idx & 1023;
            int r = rem >> 6, ch = rem & 63;
            cpa16(sb + W_OFF + sec * WSEC + r * PITCH + ch * 16,
                  g_rh + ((size_t)(sec * 512 + u0 + r)) * UG + ch * 8);
        }
        asm volatile("cp.async.commit_group;" ::: "memory");

        const float* gbr = gb + XN;
        float bzc[2], brc[2], bhc[2];
#pragma unroll
        for (int j = 0; j < 2; j++) {
            bzc[j] = gbr[uc + j];
            brc[j] = gbr[512 + uc + j];
            bhc[j] = gbr[1024 + uc + j];
        }

        float hprev[4], hmax[4];
        hprev[0] = g_h0f[(size_t)r1 * UG + uc];
        hprev[1] = g_h0f[(size_t)r1 * UG + uc + 1];
        hprev[2] = g_h0f[(size_t)r2 * UG + uc];
        hprev[3] = g_h0f[(size_t)r2 * UG + uc + 1];
#pragma unroll
        for (int i = 0; i < 4; i++) hmax[i] = -INFINITY;

        const uint32_t aHi = sb + AHI_OFF + (mt * 16 + (lane & 15)) * PITCH +
                             ((lane >> 4) & 1) * 16;
        const uint32_t aLo = aHi + (ALO_OFF - AHI_OFF);
        uint32_t bHi[3];
        {
            int brow = uh * 8 + (lane & 7);
            int bch = lane >> 3;
#pragma unroll
            for (int g = 0; g < 3; g++)
                bHi[g] = sb + W_OFF + g * WSEC + brow * PITCH + bch * 16;
        }

        auto stageA = [&](int par) {
            const __half* shp = g_hh[par] + (size_t)row0 * UG;
            const __half* slp = g_hl[par] + (size_t)row0 * UG;
            for (int idx = ltid; idx < 2048; idx += 128) {
                int r = idx >> 6, ch = idx & 63;
                cpa16(sb + AHI_OFF + r * PITCH + ch * 16, shp + (size_t)r * UG + ch * 8);
                cpa16(sb + ALO_OFF + r * PITCH + ch * 16, slp + (size_t)r * UG + ch * 8);
            }
            asm volatile("cp.async.commit_group;" ::: "memory");
        };

        stageA(0);

        {
            int spins = 0;
            while (ldAcq(&g_tcnt[0]) < 12u) {
                if (++spins > 16) asm volatile("nanosleep.u32 128;");
            }
        }
        float2 xz[2], xr[2], xh[2];
        {
            const float* xpr1 = g_xp + (size_t)r1 * XN;
            const float* xpr2 = g_xp + (size_t)r2 * XN;
            xz[0] = *(const float2*)(xpr1 + uc);        xz[1] = *(const float2*)(xpr2 + uc);
            xr[0] = *(const float2*)(xpr1 + 512 + uc);  xr[1] = *(const float2*)(xpr2 + 512 + uc);
            xh[0] = *(const float2*)(xpr1 + 1024 + uc); xh[1] = *(const float2*)(xpr2 + 1024 + uc);
        }

        unsigned* barp = &g_barp[bt][0];
        unsigned* genp = &g_genp[bt][0];

        for (int t = 0; t < T; t++) {
            asm volatile("cp.async.wait_group 0;" ::: "memory");
            BARNAMED(1, 128);

            float az[4] = {0.f, 0.f, 0.f, 0.f};
            float ar[4] = {0.f, 0.f, 0.f, 0.f};
            float ah2[4] = {0.f, 0.f, 0.f, 0.f};

#pragma unroll 4
            for (int j = 0; j < 16; j++) {
                uint32_t ah0[4], ah1[4], al0[4], al1[4];
                uint32_t a = aHi + j * 64;
                ldm4(ah0, a);
                ldm4(ah1, a + 32);
                uint32_t al = aLo + j * 64;
                ldm4(al0, al);
                ldm4(al1, al + 32);
                uint32_t b4h[4];
                ldm4(b4h, bHi[0] + j * 64);
                mma16816(az, ah0, b4h[0], b4h[1]);
                mma16816(az, al0, b4h[0], b4h[1]);
                mma16816(az, ah1, b4h[2], b4h[3]);
                mma16816(az, al1, b4h[2], b4h[3]);
                ldm4(b4h, bHi[1] + j * 64);
                mma16816(ar, ah0, b4h[0], b4h[1]);
                mma16816(ar, al0, b4h[0], b4h[1]);
                mma16816(ar, ah1, b4h[2], b4h[3]);
                mma16816(ar, al1, b4h[2], b4h[3]);
                ldm4(b4h, bHi[2] + j * 64);
                mma16816(ah2, ah0, b4h[0], b4h[1]);
                mma16816(ah2, al0, b4h[0], b4h[1]);
                mma16816(ah2, ah1, b4h[2], b4h[3]);
                mma16816(ah2, al1, b4h[2], b4h[3]);
            }

            int np = (t + 1) & 1;
            bool notlast = (t + 1 < T);
#pragma unroll
            for (int pp = 0; pp < 2; pp++) {
                float hn[2];
#pragma unroll
                for (int j = 0; j < 2; j++) {
                    int i = 2 * pp + j;
                    float xzv = j ? xz[pp].y : xz[pp].x;
                    float xrv = j ? xr[pp].y : xr[pp].x;
                    float xhv = j ? xh[pp].y : xh[pp].x;
                    float z = sigm(xzv + az[i] + bzc[j]);
                    float r = sigm(xrv + ar[i] + brc[j]);
                    float hc = tanhf(xhv + r * (ah2[i] + bhc[j]));
                    hn[j] = z * hprev[i] + (1.f - z) * hc;
                    hprev[i] = hn[j];
                    hmax[i] = fmaxf(hmax[i], hn[j]);
                }
                if (notlast) {
                    int rowg = pp ? r2 : r1;
                    __half2 vh, vl;
                    __half h0b, l0b, h1b, l1b;
                    split_f16(hn[0], h0b, l0b);
                    split_f16(hn[1], h1b, l1b);
                    vh.x = h0b; vh.y = h1b;
                    vl.x = l0b; vl.y = l1b;
                    *(__half2*)&g_hh[np][(size_t)rowg * UG + uc] = vh;
                    *(__half2*)&g_hl[np][(size_t)rowg * UG + uc] = vl;
                }
            }

            if (notlast) {
                {
                    int spins = 0;
                    while (ldAcq(&g_tcnt[t + 1]) < 12u) {
                        if (++spins > 16) asm volatile("nanosleep.u32 128;");
                    }
                }
                {
                    const float* xp = g_xp + (size_t)(t + 1) * ((size_t)B * XN);
                    const float* xpr1 = xp + (size_t)r1 * XN;
                    const float* xpr2 = xp + (size_t)r2 * XN;
                    xz[0] = *(const float2*)(xpr1 + uc);        xz[1] = *(const float2*)(xpr2 + uc);
                    xr[0] = *(const float2*)(xpr1 + 512 + uc);  xr[1] = *(const float2*)(xpr2 + 512 + uc);
                    xh[0] = *(const float2*)(xpr1 + 1024 + uc); xh[1] = *(const float2*)(xpr2 + 1024 + uc);
                }
                BARNAMED(1, 128);
                if (ltid == 0) {
                    unsigned target = (unsigned)(t + 1) * NBLK_BT;
                    unsigned old = atomAddRel(barp, 1);
                    if (old == target - 1) {
                        stRel(genp, (unsigned)(t + 1));
                    } else {
                        int spins = 0;
                        while (ldAcq(genp) < (unsigned)(t + 1)) {
                            if (++spins > 64) asm volatile("nanosleep.u32 64;");
                        }
                    }
                }
                BARNAMED(1, 128);
                stageA(np);
            }
        }

        float2 v;
        v.x = hmax[0]; v.y = hmax[1]; *(float2*)&g_hmax[(size_t)r1 * UG + uc] = v;
        v.x = hmax[2]; v.y = hmax[3]; *(float2*)&g_hmax[(size_t)r2 * UG + uc] = v;
        v.x = hprev[0]; v.y = hprev[1]; *(float2*)&g_h0f[(size_t)r1 * UG + uc] = v;
        v.x = hprev[2]; v.y = hprev[3]; *(float2*)&g_h0f[(size_t)r2 * UG + uc] = v;
    }
}

// ---------------- epilogue ---------------------------------------------------
__global__ void k_out(const float* __restrict__ Wout, const float* __restrict__ bout,
                      float* __restrict__ dout, int out_size) {
    int b = blockIdx.x;
    int tid = threadIdx.x; // 256
    __shared__ float red[256];
    float s = 0.f;
    for (int uu = tid; uu < UG; uu += 256) s += g_hmax[b * UG + uu] * Wout[uu];
    red[tid] = s;
    __syncthreads();
    for (int o = 128; o > 0; o >>= 1) {
        if (tid < o) red[tid] += red[tid + o];
        __syncthreads();
    }
    if (tid == 0 && b < out_size) dout[b] = eluf(red[0] + bout[0]);
    for (int uu = tid; uu < UG; uu += 256) {
        int idx = B + b * UG + uu;
        if (idx < out_size) dout[idx] = g_h0f[b * UG + uu];
    }
}

// ---------------- launch ------------------------------------------------------
extern "C" void kernel_launch(void* const* d_in, const int* in_sizes, int n_in,
                              void* d_out, int out_size) {
    const float* motion = (const float*)d_in[0];
    const float* robot  = (const float*)d_in[1];
    const float* action = (const float*)d_in[3];
    const float* osc    = (const float*)d_in[4];
    const float* mu     = (const float*)d_in[5];
    const float* mean   = (const float*)d_in[6];
    const float* state  = (const float*)d_in[7];
    const float* W_mot  = (const float*)d_in[8];
    const float* b_mot  = (const float*)d_in[9];
    const float* W_rob  = (const float*)d_in[10];
    const float* b_rob  = (const float*)d_in[11];
    const float* W_comb = (const float*)d_in[12];
    const float* b_comb = (const float*)d_in[13];
    const float* W_oscr = (const float*)d_in[14];
    const float* b_oscr = (const float*)d_in[15];
    const float* W_osci = (const float*)d_in[16];
    const float* b_osci = (const float*)d_in[17];
    const float* gru_k  = (const float*)d_in[18];
    const float* gru_rk = (const float*)d_in[19];
    const float* gru_b  = (const float*)d_in[20];
    const float* W_out  = (const float*)d_in[21];
    const float* b_out  = (const float*)d_in[22];
    float* out = (float*)d_out;

    static bool attr_set = false;
    if (!attr_set) {
        cudaFuncSetAttribute(k_fused, cudaFuncAttributeMaxDynamicSharedMemorySize, SMEM_FUSED);
        attr_set = true;
    }

    k_reset<<<1, 512>>>();
    k_msrs<<<B, 256>>>(motion, robot, W_mot, b_mot, W_rob, b_rob);
    k_h0<<<B, 512>>>(state, W_comb, b_comb);
    k_act<<<ROWS, 256>>>(action, mu, mean);
    k_inp23<<<ROWS / 8, 256>>>(osc, W_oscr, b_oscr, W_osci, b_osci);
    k_trb<<<dim3(XN / 32, XK / 32), dim3(32, 8)>>>(gru_k);
    k_trw<<<dim3(XN / 32, UG / 32), dim3(32, 8)>>>(gru_rk);
    k_fused<<<128, 384, SMEM_FUSED>>>(gru_b);
    k_out<<<B, 256>>>(W_out, b_out, out, out_size);
}

// round 11
// speedup vs baseline: 4.3078x; 1.0012x over previous
#include <cuda_runtime.h>
#include <cuda_fp16.h>
#include <cstdint>
#include <math.h>

namespace {
constexpr int B  = 128;
constexpr int T  = 512;
constexpr int A  = 256;
constexpr int UG = 512;
constexpr int ROWS = B * T;       // 65536
constexpr int XK = 768;           // x feature width
constexpr int XN = 1536;          // 3 * UG
}

// ---------------- scratch (device globals; no allocation allowed) ------------
__device__ __half g_xh[(size_t)ROWS * XK];      // fp16 x
__device__ __half g_bh[(size_t)XN * XK];        // gru_k^T [N,K] fp16
__device__ __half g_rh[(size_t)XN * UG];        // gru_rk^T [1536,512] fp16
__device__ float g_xp[(size_t)ROWS * XN];       // x @ gru_k + gru_b[0]
__device__ float g_h0f[B * UG];                 // h0 fp32 / final h
__device__ __half g_hh[2][B * UG];              // h ping-pong, fp16 hi
__device__ __half g_hl[2][B * UG];              // h ping-pong, fp16 lo
__device__ float g_hmax[B * UG];
__device__ float g_ms[B * 256];
__device__ float g_rs[B * 256];
__device__ unsigned g_barp[4][32];              // per-btile barrier arrivals (padded)
__device__ unsigned g_genp[4][32];              // per-btile generation (padded)
__device__ unsigned g_tcnt[T];                  // completed xp n-tiles per timestep

__device__ __forceinline__ float eluf(float v) { return v > 0.f ? v : (expf(v) - 1.f); }
__device__ __forceinline__ float sigm(float v) { return 1.f / (1.f + expf(-v)); }
__device__ __forceinline__ void split_f16(float v, __half& h, __half& l) {
    h = __float2half(v);
    l = __float2half(v - __half2float(h));
}

// ---------------- PTX helpers (plain sm_103-safe) -----------------------------
__device__ __forceinline__ uint32_t smem_u32(const void* p) {
    uint32_t a;
    asm("{ .reg .u64 t; cvta.to.shared.u64 t, %1; cvt.u32.u64 %0, t; }" : "=r"(a) : "l"(p));
    return a;
}
__device__ __forceinline__ void cpa16(uint32_t s, const void* g) {
    asm volatile("cp.async.cg.shared.global [%0], [%1], 16;" :: "r"(s), "l"(g));
}
__device__ __forceinline__ void ldm4(uint32_t* r, uint32_t a) {
    asm volatile("ldmatrix.sync.aligned.m8n8.x4.shared.b16 {%0,%1,%2,%3}, [%4];"
                 : "=r"(r[0]), "=r"(r[1]), "=r"(r[2]), "=r"(r[3]) : "r"(a));
}
__device__ __forceinline__ void mma16816(float* c, const uint32_t* a, uint32_t b0, uint32_t b1) {
    asm volatile(
        "mma.sync.aligned.m16n8k16.row.col.f32.f16.f16.f32 "
        "{%0,%1,%2,%3}, {%4,%5,%6,%7}, {%8,%9}, {%0,%1,%2,%3};"
        : "+f"(c[0]), "+f"(c[1]), "+f"(c[2]), "+f"(c[3])
        : "r"(a[0]), "r"(a[1]), "r"(a[2]), "r"(a[3]), "r"(b0), "r"(b1));
}
__device__ __forceinline__ unsigned atomAddRel(unsigned* p, unsigned v) {
    unsigned o;
    asm volatile("atom.release.gpu.global.add.u32 %0, [%1], %2;"
                 : "=r"(o) : "l"(p), "r"(v) : "memory");
    return o;
}
__device__ __forceinline__ void stRel(unsigned* p, unsigned v) {
    asm volatile("st.release.gpu.global.u32 [%0], %1;" :: "l"(p), "r"(v) : "memory");
}
__device__ __forceinline__ unsigned ldAcq(unsigned* p) {
    unsigned v;
    asm volatile("ld.acquire.gpu.global.u32 %0, [%1];" : "=r"(v) : "l"(p) : "memory");
    return v;
}
#define BARNAMED(id, cnt) asm volatile("bar.sync %0, %1;" :: "r"(id), "r"(cnt) : "memory")

// ---------------- small front-end kernels -----------------------------------
__global__ void k_reset() {
    int i = threadIdx.x; // 512
    g_tcnt[i] = 0;
    if (i < 4) { g_barp[i][0] = 0; g_genp[i][0] = 0; }
}

__global__ void k_msrs(const float* __restrict__ motion, const float* __restrict__ robot,
                       const float* __restrict__ Wm, const float* __restrict__ bm,
                       const float* __restrict__ Wr, const float* __restrict__ br) {
    int b = blockIdx.x;
    int j = threadIdx.x; // 256
    __shared__ float sm[64], sr[64];
    if (j < 64) sm[j] = motion[b * 64 + j];
    else if (j < 128) sr[j - 64] = robot[b * 64 + (j - 64)];
    __syncthreads();
    float accm = bm[j], accr = br[j];
    for (int k = 0; k < 64; k++) {
        accm += sm[k] * Wm[k * 256 + j];
        accr += sr[k] * Wr[k * 256 + j];
    }
    g_ms[b * 256 + j] = eluf(accm);
    g_rs[b * 256 + j] = eluf(accr);
}

__global__ void k_h0(const float* __restrict__ state, const float* __restrict__ Wc,
                     const float* __restrict__ bc) {
    int b = blockIdx.x;
    int u = threadIdx.x; // 512
    __shared__ float s[1024];
    s[u] = (u < 256) ? g_ms[b * 256 + u] : g_rs[b * 256 + (u - 256)];
    s[512 + u] = state[b * 512 + u];
    __syncthreads();
    float acc = bc[u];
    for (int k = 0; k < 1024; k++) acc += s[k] * Wc[k * 512 + u];
    float h0 = eluf(acc);
    size_t idx = (size_t)b * 512 + u;
    g_h0f[idx] = h0;
    split_f16(h0, g_hh[0][idx], g_hl[0][idx]);
}

__global__ void k_act(const float* __restrict__ action, const float* __restrict__ mu,
                      const float* __restrict__ mean) {
    int r = blockIdx.x;
    int t = r >> 7;
    int b = r & 127;
    int a = threadIdx.x;
    float v = action[((size_t)b * T + t) * A + a] * mu[b * A + a] + mean[b * A + a];
    g_xh[(size_t)r * XK + a] = __float2half(v);
}

// fused inp2 + inp3
__global__ void k_inp23(const float* __restrict__ osc,
                        const float* __restrict__ W2, const float* __restrict__ b2,
                        const float* __restrict__ W3, const float* __restrict__ b3) {
    int r0 = blockIdx.x * 8;
    int j = threadIdx.x; // 256
    __shared__ float sin_[8][64];
    __shared__ float smid[8][256];
    for (int i = threadIdx.x; i < 8 * 64; i += 256) {
        int rr = i >> 6, k = i & 63;
        int r = r0 + rr;
        int t = r >> 7, b = r & 127;
        sin_[rr][k] = osc[((size_t)b * T + t) * 128 + k];
    }
    __syncthreads();
    {
        float bj = b2[j];
        float acc[8];
#pragma unroll
        for (int i = 0; i < 8; i++) acc[i] = bj;
        for (int k = 0; k < 64; k++) {
            float w = W2[k * 256 + j];
#pragma unroll
            for (int i = 0; i < 8; i++) acc[i] += sin_[i][k] * w;
        }
#pragma unroll
        for (int i = 0; i < 8; i++) {
            float v = eluf(acc[i]);
            smid[i][j] = v;
            g_xh[(size_t)(r0 + i) * XK + 256 + j] = __float2half(v);
        }
    }
    __syncthreads();
    {
        float bj = b3[j];
        float acc[8];
#pragma unroll
        for (int i = 0; i < 8; i++) acc[i] = bj;
        for (int k = 0; k < 192; k++) {
            float w = W3[k * 256 + j];
#pragma unroll
            for (int i = 0; i < 8; i++) acc[i] += smid[i][64 + k] * w;
        }
#pragma unroll
        for (int i = 0; i < 8; i++)
            g_xh[(size_t)(r0 + i) * XK + 512 + j] = __float2half(eluf(acc[i]));
    }
}

// transpose gru_k [768,1536] -> g_bh [1536,768] fp16
__global__ void k_trb(const float* __restrict__ gk) {
    __shared__ float s[32][33];
    int n0 = blockIdx.x * 32, k0 = blockIdx.y * 32;
    int tx = threadIdx.x, ty = threadIdx.y; // 32 x 8
#pragma unroll
    for (int i = 0; i < 32; i += 8)
        s[ty + i][tx] = gk[(size_t)(k0 + ty + i) * XN + n0 + tx];
    __syncthreads();
#pragma unroll
    for (int i = 0; i < 32; i += 8) {
        size_t idx = (size_t)(n0 + ty + i) * XK + k0 + tx;
        g_bh[idx] = __float2half(s[tx][ty + i]);
    }
}

// transpose gru_rk [512,1536] -> g_rh [1536,512] fp16
__global__ void k_trw(const float* __restrict__ wr) {
    __shared__ float s[32][33];
    int n0 = blockIdx.x * 32, k0 = blockIdx.y * 32;
    int tx = threadIdx.x, ty = threadIdx.y; // 32 x 8
#pragma unroll
    for (int i = 0; i < 32; i += 8)
        s[ty + i][tx] = wr[(size_t)(k0 + ty + i) * XN + n0 + tx];
    __syncthreads();
#pragma unroll
    for (int i = 0; i < 32; i += 8) {
        size_t idx = (size_t)(n0 + ty + i) * UG + k0 + tx;
        g_rh[idx] = __float2half(s[tx][ty + i]);
    }
}

// ---------------- FUSED persistent kernel -------------------------------------
// 128 blocks x 384 threads.
//   warps 0-7  (tid 0..255):  xp production (tile 128x128, fp16 1-term, 3-stage)
//   warps 8-11 (tid 256..383): GRU recurrence (block owns 32 b x 16 u)
// Recurrence gate precision: z,r = 1-term (h-hi only); h-candidate = 2-term.
namespace {
constexpr int PITCHB = 80;
constexpr int ARRB   = 128 * PITCHB;       // 10240
constexpr int BUFB   = 2 * ARRB;           // 20480 : A | B
constexpr int PROD_BYTES = 3 * BUFB;       // 61440
constexpr int KCH = 24;
constexpr int NJOBS = T * (XN / 128);      // 6144, 12 per t
constexpr int PITCH = 1040;
constexpr int WSEC  = 16 * PITCH;              // 16640 per gate
constexpr int W_OFF = PROD_BYTES;              // 61440
constexpr int AHI_OFF = W_OFF + 3 * WSEC;      // 111360
constexpr int ALO_OFF = AHI_OFF + 32 * PITCH;  // 144640
constexpr int SMEM_FUSED = ALO_OFF + 32 * PITCH; // 177920
constexpr int NBLK_BT = 32;
}

__global__ void __launch_bounds__(384, 1) k_fused(const float* __restrict__ gb) {
    extern __shared__ char smem[];
    const uint32_t sb = smem_u32(smem);
    const int tid = threadIdx.x;

    if (tid < 256) {
        // ================= PRODUCTION (1-term fp16) =================
        const int lane = tid & 31, wid = tid >> 5;
        const int wm = wid & 3;
        const int wn = wid >> 2;
        const uint32_t aAddr = sb + (wm * 32 + (lane & 15)) * PITCHB + (lane >> 4) * 16;
        const uint32_t bAddr = sb + ARRB + (wn * 64 + (lane & 15)) * PITCHB + (lane >> 4) * 16;

        for (int job = blockIdx.x; job < NJOBS; job += 128) {
            const int t = job / 12, nt = job % 12;
            const int m0 = t * 128;
            const int n0 = nt * 128;
            const __half* gp0 = g_xh + (size_t)m0 * XK;
            const __half* gp1 = g_bh + (size_t)n0 * XK;

            auto load_chunk = [&](int c, int buf) {
                uint32_t base = sb + buf * BUFB;
#pragma unroll
                for (int l = 0; l < 4; l++) {
                    int idx = tid + 256 * l;
                    int arr = idx >> 9;            // 0..1
                    int rem = idx & 511;
                    int row = rem >> 2;
                    int cch = rem & 3;
                    const __half* g = arr ? gp1 : gp0;
                    cpa16(base + arr * ARRB + row * PITCHB + cch * 16,
                          g + (size_t)row * XK + c * 32 + cch * 8);
                }
                asm volatile("cp.async.commit_group;" ::: "memory");
            };

            float acc[2][8][4];
#pragma unroll
            for (int i = 0; i < 2; i++)
#pragma unroll
                for (int jj = 0; jj < 8; jj++)
#pragma unroll
                    for (int q = 0; q < 4; q++) acc[i][jj][q] = 0.f;

            load_chunk(0, 0);
            load_chunk(1, 1);

            for (int c = 0; c < KCH; c++) {
                if (c + 1 < KCH) asm volatile("cp.async.wait_group 1;" ::: "memory");
                else             asm volatile("cp.async.wait_group 0;" ::: "memory");
                BARNAMED(2, 256);
                if (c + 2 < KCH) load_chunk(c + 2, (c + 2) % 3);

                uint32_t boff = (c % 3) * BUFB;
#pragma unroll
                for (int ks = 0; ks < 2; ks++) {
                    uint32_t ah[2][4], bh[4][4];
#pragma unroll
                    for (int mt = 0; mt < 2; mt++)
                        ldm4(ah[mt], aAddr + boff + mt * (16 * PITCHB) + ks * 32);
#pragma unroll
                    for (int ng = 0; ng < 4; ng++)
                        ldm4(bh[ng], bAddr + boff + ng * (16 * PITCHB) + ks * 32);
#pragma unroll
                    for (int mt = 0; mt < 2; mt++)
#pragma unroll
                        for (int ng = 0; ng < 4; ng++)
#pragma unroll
                            for (int hf = 0; hf < 2; hf++)
                                mma16816(acc[mt][ng * 2 + hf], ah[mt],
                                         bh[ng][hf], bh[ng][hf + 2]);
                }
            }

            const int qr = lane >> 2, qc = lane & 3;
#pragma unroll
            for (int mt = 0; mt < 2; mt++)
#pragma unroll
                for (int ntl = 0; ntl < 8; ntl++) {
                    int nb = n0 + wn * 64 + ntl * 8 + 2 * qc;
                    float b0 = gb[nb], b1 = gb[nb + 1];
#pragma unroll
                    for (int rp = 0; rp < 2; rp++) {
                        int m = m0 + wm * 32 + mt * 16 + qr + 8 * rp;
                        float2 v = make_float2(acc[mt][ntl][2 * rp] + b0,
                                               acc[mt][ntl][2 * rp + 1] + b1);
                        *(float2*)&g_xp[(size_t)m * XN + nb] = v;
                    }
                }

            __threadfence();
            BARNAMED(2, 256);
            if (tid == 0) atomAddRel(&g_tcnt[t], 1u);
        }
    } else {
        // ================= RECURRENCE (z,r 1-term; h 2-term) =================
        const int ltid = tid - 256;            // 0..127
        const int lane = ltid & 31, lwid = ltid >> 5;
        const int mt = lwid & 1;
        const int uh = lwid >> 1;
        const int bt = blockIdx.x & 3;
        const int ut = blockIdx.x >> 2;
        const int u0 = ut * 16;
        const int row0 = bt * 32;
        const int qr = lane >> 2, qc = lane & 3;
        const int r1 = row0 + mt * 16 + qr;
        const int r2 = r1 + 8;
        const int uc = u0 + uh * 8 + 2 * qc;

        for (int idx = ltid; idx < 3072; idx += 128) {
            int sec = idx >> 10;
            int rem = idx & 1023;
            int r = rem >> 6, ch = rem & 63;
            cpa16(sb + W_OFF + sec * WSEC + r * PITCH + ch * 16,
                  g_rh + ((size_t)(sec * 512 + u0 + r)) * UG + ch * 8);
        }
        asm volatile("cp.async.commit_group;" ::: "memory");

        const float* gbr = gb + XN;
        float bzc[2], brc[2], bhc[2];
#pragma unroll
        for (int j = 0; j < 2; j++) {
            bzc[j] = gbr[uc + j];
            brc[j] = gbr[512 + uc + j];
            bhc[j] = gbr[1024 + uc + j];
        }

        float hprev[4], hmax[4];
        hprev[0] = g_h0f[(size_t)r1 * UG + uc];
        hprev[1] = g_h0f[(size_t)r1 * UG + uc + 1];
        hprev[2] = g_h0f[(size_t)r2 * UG + uc];
        hprev[3] = g_h0f[(size_t)r2 * UG + uc + 1];
#pragma unroll
        for (int i = 0; i < 4; i++) hmax[i] = -INFINITY;

        const uint32_t aHi = sb + AHI_OFF + (mt * 16 + (lane & 15)) * PITCH +
                             ((lane >> 4) & 1) * 16;
        const uint32_t aLo = aHi + (ALO_OFF - AHI_OFF);
        uint32_t bHi[3];
        {
            int brow = uh * 8 + (lane & 7);
            int bch = lane >> 3;
#pragma unroll
            for (int g = 0; g < 3; g++)
                bHi[g] = sb + W_OFF + g * WSEC + brow * PITCH + bch * 16;
        }

        auto stageA = [&](int par) {
            const __half* shp = g_hh[par] + (size_t)row0 * UG;
            const __half* slp = g_hl[par] + (size_t)row0 * UG;
            for (int idx = ltid; idx < 2048; idx += 128) {
                int r = idx >> 6, ch = idx & 63;
                cpa16(sb + AHI_OFF + r * PITCH + ch * 16, shp + (size_t)r * UG + ch * 8);
                cpa16(sb + ALO_OFF + r * PITCH + ch * 16, slp + (size_t)r * UG + ch * 8);
            }
            asm volatile("cp.async.commit_group;" ::: "memory");
        };

        stageA(0);

        {
            int spins = 0;
            while (ldAcq(&g_tcnt[0]) < 12u) {
                if (++spins > 16) asm volatile("nanosleep.u32 128;");
            }
        }
        float2 xz[2], xr[2], xh[2];
        {
            const float* xpr1 = g_xp + (size_t)r1 * XN;
            const float* xpr2 = g_xp + (size_t)r2 * XN;
            xz[0] = *(const float2*)(xpr1 + uc);        xz[1] = *(const float2*)(xpr2 + uc);
            xr[0] = *(const float2*)(xpr1 + 512 + uc);  xr[1] = *(const float2*)(xpr2 + 512 + uc);
            xh[0] = *(const float2*)(xpr1 + 1024 + uc); xh[1] = *(const float2*)(xpr2 + 1024 + uc);
        }

        unsigned* barp = &g_barp[bt][0];
        unsigned* genp = &g_genp[bt][0];

        for (int t = 0; t < T; t++) {
            asm volatile("cp.async.wait_group 0;" ::: "memory");
            BARNAMED(1, 128);

            float az[4] = {0.f, 0.f, 0.f, 0.f};
            float ar[4] = {0.f, 0.f, 0.f, 0.f};
            float ah2[4] = {0.f, 0.f, 0.f, 0.f};

#pragma unroll 4
            for (int j = 0; j < 16; j++) {
                uint32_t ah0[4], ah1[4], al0[4], al1[4];
                uint32_t a = aHi + j * 64;
                ldm4(ah0, a);
                ldm4(ah1, a + 32);
                uint32_t al = aLo + j * 64;
                ldm4(al0, al);
                ldm4(al1, al + 32);
                uint32_t b4h[4];
                // gate z (1-term)
                ldm4(b4h, bHi[0] + j * 64);
                mma16816(az, ah0, b4h[0], b4h[1]);
                mma16816(az, ah1, b4h[2], b4h[3]);
                // gate r (1-term)
                ldm4(b4h, bHi[1] + j * 64);
                mma16816(ar, ah0, b4h[0], b4h[1]);
                mma16816(ar, ah1, b4h[2], b4h[3]);
                // gate h (2-term)
                ldm4(b4h, bHi[2] + j * 64);
                mma16816(ah2, ah0, b4h[0], b4h[1]);
                mma16816(ah2, al0, b4h[0], b4h[1]);
                mma16816(ah2, ah1, b4h[2], b4h[3]);
                mma16816(ah2, al1, b4h[2], b4h[3]);
            }

            int np = (t + 1) & 1;
            bool notlast = (t + 1 < T);
#pragma unroll
            for (int pp = 0; pp < 2; pp++) {
                float hn[2];
#pragma unroll
                for (int j = 0; j < 2; j++) {
                    int i = 2 * pp + j;
                    float xzv = j ? xz[pp].y : xz[pp].x;
                    float xrv = j ? xr[pp].y : xr[pp].x;
                    float xhv = j ? xh[pp].y : xh[pp].x;
                    float z = sigm(xzv + az[i] + bzc[j]);
                    float r = sigm(xrv + ar[i] + brc[j]);
                    float hc = tanhf(xhv + r * (ah2[i] + bhc[j]));
                    hn[j] = z * hprev[i] + (1.f - z) * hc;
                    hprev[i] = hn[j];
                    hmax[i] = fmaxf(hmax[i], hn[j]);
                }
                if (notlast) {
                    int rowg = pp ? r2 : r1;
                    __half2 vh, vl;
                    __half h0b, l0b, h1b, l1b;
                    split_f16(hn[0], h0b, l0b);
                    split_f16(hn[1], h1b, l1b);
                    vh.x = h0b; vh.y = h1b;
                    vl.x = l0b; vl.y = l1b;
                    *(__half2*)&g_hh[np][(size_t)rowg * UG + uc] = vh;
                    *(__half2*)&g_hl[np][(size_t)rowg * UG + uc] = vl;
                }
            }

            if (notlast) {
                {
                    int spins = 0;
                    while (ldAcq(&g_tcnt[t + 1]) < 12u) {
                        if (++spins > 16) asm volatile("nanosleep.u32 128;");
                    }
                }
                {
                    const float* xp = g_xp + (size_t)(t + 1) * ((size_t)B * XN);
                    const float* xpr1 = xp + (size_t)r1 * XN;
                    const float* xpr2 = xp + (size_t)r2 * XN;
                    xz[0] = *(const float2*)(xpr1 + uc);        xz[1] = *(const float2*)(xpr2 + uc);
                    xr[0] = *(const float2*)(xpr1 + 512 + uc);  xr[1] = *(const float2*)(xpr2 + 512 + uc);
                    xh[0] = *(const float2*)(xpr1 + 1024 + uc); xh[1] = *(const float2*)(xpr2 + 1024 + uc);
                }
                BARNAMED(1, 128);
                if (ltid == 0) {
                    unsigned target = (unsigned)(t + 1) * NBLK_BT;
                    unsigned old = atomAddRel(barp, 1);
                    if (old == target - 1) {
                        stRel(genp, (unsigned)(t + 1));
                    } else {
                        int spins = 0;
                        while (ldAcq(genp) < (unsigned)(t + 1)) {
                            if (++spins > 64) asm volatile("nanosleep.u32 64;");
                        }
                    }
                }
                BARNAMED(1, 128);
                stageA(np);
            }
        }

        float2 v;
        v.x = hmax[0]; v.y = hmax[1]; *(float2*)&g_hmax[(size_t)r1 * UG + uc] = v;
        v.x = hmax[2]; v.y = hmax[3]; *(float2*)&g_hmax[(size_t)r2 * UG + uc] = v;
        v.x = hprev[0]; v.y = hprev[1]; *(float2*)&g_h0f[(size_t)r1 * UG + uc] = v;
        v.x = hprev[2]; v.y = hprev[3]; *(float2*)&g_h0f[(size_t)r2 * UG + uc] = v;
    }
}

// ---------------- epilogue ---------------------------------------------------
__global__ void k_out(const float* __restrict__ Wout, const float* __restrict__ bout,
                      float* __restrict__ dout, int out_size) {
    int b = blockIdx.x;
    int tid = threadIdx.x; // 256
    __shared__ float red[256];
    float s = 0.f;
    for (int uu = tid; uu < UG; uu += 256) s += g_hmax[b * UG + uu] * Wout[uu];
    red[tid] = s;
    __syncthreads();
    for (int o = 128; o > 0; o >>= 1) {
        if (tid < o) red[tid] += red[tid + o];
        __syncthreads();
    }
    if (tid == 0 && b < out_size) dout[b] = eluf(red[0] + bout[0]);
    for (int uu = tid; uu < UG; uu += 256) {
        int idx = B + b * UG + uu;
        if (idx < out_size) dout[idx] = g_h0f[b * UG + uu];
    }
}

// ---------------- launch ------------------------------------------------------
extern "C" void kernel_launch(void* const* d_in, const int* in_sizes, int n_in,
                              void* d_out, int out_size) {
    const float* motion = (const float*)d_in[0];
    const float* robot  = (const float*)d_in[1];
    const float* action = (const float*)d_in[3];
    const float* osc    = (const float*)d_in[4];
    const float* mu     = (const float*)d_in[5];
    const float* mean   = (const float*)d_in[6];
    const float* state  = (const float*)d_in[7];
    const float* W_mot  = (const float*)d_in[8];
    const float* b_mot  = (const float*)d_in[9];
    const float* W_rob  = (const float*)d_in[10];
    const float* b_rob  = (const float*)d_in[11];
    const float* W_comb = (const float*)d_in[12];
    const float* b_comb = (const float*)d_in[13];
    const float* W_oscr = (const float*)d_in[14];
    const float* b_oscr = (const float*)d_in[15];
    const float* W_osci = (const float*)d_in[16];
    const float* b_osci = (const float*)d_in[17];
    const float* gru_k  = (const float*)d_in[18];
    const float* gru_rk = (const float*)d_in[19];
    const float* gru_b  = (const float*)d_in[20];
    const float* W_out  = (const float*)d_in[21];
    const float* b_out  = (const float*)d_in[22];
    float* out = (float*)d_out;

    static bool attr_set = false;
    if (!attr_set) {
        cudaFuncSetAttribute(k_fused, cudaFuncAttributeMaxDynamicSharedMemorySize, SMEM_FUSED);
        attr_set = true;
    }

    k_reset<<<1, 512>>>();
    k_msrs<<<B, 256>>>(motion, robot, W_mot, b_mot, W_rob, b_rob);
    k_h0<<<B, 512>>>(state, W_comb, b_comb);
    k_act<<<ROWS, 256>>>(action, mu, mean);
    k_inp23<<<ROWS / 8, 256>>>(osc, W_oscr, b_oscr, W_osci, b_osci);
    k_trb<<<dim3(XN / 32, XK / 32), dim3(32, 8)>>>(gru_k);
    k_trw<<<dim3(XN / 32, UG / 32), dim3(32, 8)>>>(gru_rk);
    k_fused<<<128, 384, SMEM_FUSED>>>(gru_b);
    k_out<<<B, 256>>>(W_out, b_out, out, out_size);
}

// round 12
// speedup vs baseline: 4.6531x; 1.0802x over previous
#include <cuda_runtime.h>
#include <cuda_fp16.h>
#include <cstdint>
#include <math.h>

namespace {
constexpr int B  = 128;
constexpr int T  = 512;
constexpr int A  = 256;
constexpr int UG = 512;
constexpr int ROWS = B * T;       // 65536
constexpr int XK = 768;           // x feature width
constexpr int XN = 1536;          // 3 * UG
}

// ---------------- scratch (device globals; no allocation allowed) ------------
__device__ __half g_xh[(size_t)ROWS * XK];      // fp16 x
__device__ __half g_bh[(size_t)XN * XK];        // gru_k^T [N,K] fp16
__device__ __half g_rh[(size_t)XN * UG];        // gru_rk^T [1536,512] fp16
__device__ float g_xp[(size_t)ROWS * XN];       // x @ gru_k + gru_b[0]
__device__ float g_h0f[B * UG];                 // h0 fp32 / final h
__device__ __half g_hh[2][B * UG];              // h ping-pong, fp16 hi
__device__ __half g_hl[2][B * UG];              // h ping-pong, fp16 lo
__device__ float g_hmax[B * UG];
__device__ float g_ms[B * 256];
__device__ float g_rs[B * 256];
__device__ unsigned g_barp[8][32];              // per-btile barrier arrivals (padded)
__device__ unsigned g_genp[8][32];              // per-btile generation (padded)
__device__ unsigned g_tcnt[T];                  // completed xp n-tiles per timestep

__device__ __forceinline__ float eluf(float v) { return v > 0.f ? v : (expf(v) - 1.f); }
__device__ __forceinline__ float sigm(float v) { return 1.f / (1.f + expf(-v)); }
__device__ __forceinline__ void split_f16(float v, __half& h, __half& l) {
    h = __float2half(v);
    l = __float2half(v - __half2float(h));
}

// ---------------- PTX helpers (plain sm_103-safe) -----------------------------
__device__ __forceinline__ uint32_t smem_u32(const void* p) {
    uint32_t a;
    asm("{ .reg .u64 t; cvta.to.shared.u64 t, %1; cvt.u32.u64 %0, t; }" : "=r"(a) : "l"(p));
    return a;
}
__device__ __forceinline__ void cpa16(uint32_t s, const void* g) {
    asm volatile("cp.async.cg.shared.global [%0], [%1], 16;" :: "r"(s), "l"(g));
}
__device__ __forceinline__ void ldm4(uint32_t* r, uint32_t a) {
    asm volatile("ldmatrix.sync.aligned.m8n8.x4.shared.b16 {%0,%1,%2,%3}, [%4];"
                 : "=r"(r[0]), "=r"(r[1]), "=r"(r[2]), "=r"(r[3]) : "r"(a));
}
__device__ __forceinline__ void mma16816(float* c, const uint32_t* a, uint32_t b0, uint32_t b1) {
    asm volatile(
        "mma.sync.aligned.m16n8k16.row.col.f32.f16.f16.f32 "
        "{%0,%1,%2,%3}, {%4,%5,%6,%7}, {%8,%9}, {%0,%1,%2,%3};"
        : "+f"(c[0]), "+f"(c[1]), "+f"(c[2]), "+f"(c[3])
        : "r"(a[0]), "r"(a[1]), "r"(a[2]), "r"(a[3]), "r"(b0), "r"(b1));
}
__device__ __forceinline__ unsigned atomAddRel(unsigned* p, unsigned v) {
    unsigned o;
    asm volatile("atom.release.gpu.global.add.u32 %0, [%1], %2;"
                 : "=r"(o) : "l"(p), "r"(v) : "memory");
    return o;
}
__device__ __forceinline__ void stRel(unsigned* p, unsigned v) {
    asm volatile("st.release.gpu.global.u32 [%0], %1;" :: "l"(p), "r"(v) : "memory");
}
__device__ __forceinline__ unsigned ldAcq(unsigned* p) {
    unsigned v;
    asm volatile("ld.acquire.gpu.global.u32 %0, [%1];" : "=r"(v) : "l"(p) : "memory");
    return v;
}
#define BARNAMED(id, cnt) asm volatile("bar.sync %0, %1;" :: "r"(id), "r"(cnt) : "memory")

// ---------------- small front-end kernels -----------------------------------
__global__ void k_reset() {
    int i = threadIdx.x; // 512
    g_tcnt[i] = 0;
    if (i < 8) { g_barp[i][0] = 0; g_genp[i][0] = 0; }
}

__global__ void k_msrs(const float* __restrict__ motion, const float* __restrict__ robot,
                       const float* __restrict__ Wm, const float* __restrict__ bm,
                       const float* __restrict__ Wr, const float* __restrict__ br) {
    int b = blockIdx.x;
    int j = threadIdx.x; // 256
    __shared__ float sm[64], sr[64];
    if (j < 64) sm[j] = motion[b * 64 + j];
    else if (j < 128) sr[j - 64] = robot[b * 64 + (j - 64)];
    __syncthreads();
    float accm = bm[j], accr = br[j];
    for (int k = 0; k < 64; k++) {
        accm += sm[k] * Wm[k * 256 + j];
        accr += sr[k] * Wr[k * 256 + j];
    }
    g_ms[b * 256 + j] = eluf(accm);
    g_rs[b * 256 + j] = eluf(accr);
}

__global__ void k_h0(const float* __restrict__ state, const float* __restrict__ Wc,
                     const float* __restrict__ bc) {
    int b = blockIdx.x;
    int u = threadIdx.x; // 512
    __shared__ float s[1024];
    s[u] = (u < 256) ? g_ms[b * 256 + u] : g_rs[b * 256 + (u - 256)];
    s[512 + u] = state[b * 512 + u];
    __syncthreads();
    float acc = bc[u];
    for (int k = 0; k < 1024; k++) acc += s[k] * Wc[k * 512 + u];
    float h0 = eluf(acc);
    size_t idx = (size_t)b * 512 + u;
    g_h0f[idx] = h0;
    split_f16(h0, g_hh[0][idx], g_hl[0][idx]);
}

__global__ void k_act(const float* __restrict__ action, const float* __restrict__ mu,
                      const float* __restrict__ mean) {
    int r = blockIdx.x;
    int t = r >> 7;
    int b = r & 127;
    int a = threadIdx.x;
    float v = action[((size_t)b * T + t) * A + a] * mu[b * A + a] + mean[b * A + a];
    g_xh[(size_t)r * XK + a] = __float2half(v);
}

// fused inp2 + inp3
__global__ void k_inp23(const float* __restrict__ osc,
                        const float* __restrict__ W2, const float* __restrict__ b2,
                        const float* __restrict__ W3, const float* __restrict__ b3) {
    int r0 = blockIdx.x * 8;
    int j = threadIdx.x; // 256
    __shared__ float sin_[8][64];
    __shared__ float smid[8][256];
    for (int i = threadIdx.x; i < 8 * 64; i += 256) {
        int rr = i >> 6, k = i & 63;
        int r = r0 + rr;
        int t = r >> 7, b = r & 127;
        sin_[rr][k] = osc[((size_t)b * T + t) * 128 + k];
    }
    __syncthreads();
    {
        float bj = b2[j];
        float acc[8];
#pragma unroll
        for (int i = 0; i < 8; i++) acc[i] = bj;
        for (int k = 0; k < 64; k++) {
            float w = W2[k * 256 + j];
#pragma unroll
            for (int i = 0; i < 8; i++) acc[i] += sin_[i][k] * w;
        }
#pragma unroll
        for (int i = 0; i < 8; i++) {
            float v = eluf(acc[i]);
            smid[i][j] = v;
            g_xh[(size_t)(r0 + i) * XK + 256 + j] = __float2half(v);
        }
    }
    __syncthreads();
    {
        float bj = b3[j];
        float acc[8];
#pragma unroll
        for (int i = 0; i < 8; i++) acc[i] = bj;
        for (int k = 0; k < 192; k++) {
            float w = W3[k * 256 + j];
#pragma unroll
            for (int i = 0; i < 8; i++) acc[i] += smid[i][64 + k] * w;
        }
#pragma unroll
        for (int i = 0; i < 8; i++)
            g_xh[(size_t)(r0 + i) * XK + 512 + j] = __float2half(eluf(acc[i]));
    }
}

// transpose gru_k [768,1536] -> g_bh [1536,768] fp16
__global__ void k_trb(const float* __restrict__ gk) {
    __shared__ float s[32][33];
    int n0 = blockIdx.x * 32, k0 = blockIdx.y * 32;
    int tx = threadIdx.x, ty = threadIdx.y; // 32 x 8
#pragma unroll
    for (int i = 0; i < 32; i += 8)
        s[ty + i][tx] = gk[(size_t)(k0 + ty + i) * XN + n0 + tx];
    __syncthreads();
#pragma unroll
    for (int i = 0; i < 32; i += 8) {
        size_t idx = (size_t)(n0 + ty + i) * XK + k0 + tx;
        g_bh[idx] = __float2half(s[tx][ty + i]);
    }
}

// transpose gru_rk [512,1536] -> g_rh [1536,512] fp16
__global__ void k_trw(const float* __restrict__ wr) {
    __shared__ float s[32][33];
    int n0 = blockIdx.x * 32, k0 = blockIdx.y * 32;
    int tx = threadIdx.x, ty = threadIdx.y; // 32 x 8
#pragma unroll
    for (int i = 0; i < 32; i += 8)
        s[ty + i][tx] = wr[(size_t)(k0 + ty + i) * XN + n0 + tx];
    __syncthreads();
#pragma unroll
    for (int i = 0; i < 32; i += 8) {
        size_t idx = (size_t)(n0 + ty + i) * UG + k0 + tx;
        g_rh[idx] = __float2half(s[tx][ty + i]);
    }
}

// ---------------- FUSED persistent kernel -------------------------------------
// 128 blocks x 384 threads.
//   warps 0-7  (tid 0..255):  xp production (tile 128x128, fp16 1-term, 3-stage)
//   warps 8-11 (tid 256..383): GRU recurrence (block owns 16 b x 32 u)
// Recurrence tiles: 8 b-tiles (16 rows) x 16 u-tiles (32 u) -> 16-block barriers.
// Gate precision: z,r = 1-term (h-hi); h-candidate = 2-term.
namespace {
constexpr int PITCHB = 80;
constexpr int ARRB   = 128 * PITCHB;       // 10240
constexpr int BUFB   = 2 * ARRB;           // 20480 : A | B
constexpr int PROD_BYTES = 3 * BUFB;       // 61440
constexpr int KCH = 24;
constexpr int NJOBS = T * (XN / 128);      // 6144, 12 per t
constexpr int PITCH = 1040;
constexpr int WSEC  = 32 * PITCH;              // 33280 per gate (32 u rows)
constexpr int W_OFF = PROD_BYTES;              // 61440
constexpr int AHI_OFF = W_OFF + 3 * WSEC;      // 161280
constexpr int ALO_OFF = AHI_OFF + 16 * PITCH;  // 177920
constexpr int SMEM_FUSED = ALO_OFF + 16 * PITCH; // 194560
constexpr int NBLK_BT = 16;
}

__global__ void __launch_bounds__(384, 1) k_fused(const float* __restrict__ gb) {
    extern __shared__ char smem[];
    const uint32_t sb = smem_u32(smem);
    const int tid = threadIdx.x;

    if (tid < 256) {
        // ================= PRODUCTION (1-term fp16) =================
        const int lane = tid & 31, wid = tid >> 5;
        const int wm = wid & 3;
        const int wn = wid >> 2;
        const uint32_t aAddr = sb + (wm * 32 + (lane & 15)) * PITCHB + (lane >> 4) * 16;
        const uint32_t bAddr = sb + ARRB + (wn * 64 + (lane & 15)) * PITCHB + (lane >> 4) * 16;

        for (int job = blockIdx.x; job < NJOBS; job += 128) {
            const int t = job / 12, nt = job % 12;
            const int m0 = t * 128;
            const int n0 = nt * 128;
            const __half* gp0 = g_xh + (size_t)m0 * XK;
            const __half* gp1 = g_bh + (size_t)n0 * XK;

            auto load_chunk = [&](int c, int buf) {
                uint32_t base = sb + buf * BUFB;
#pragma unroll
                for (int l = 0; l < 4; l++) {
                    int idx = tid + 256 * l;
                    int arr = idx >> 9;            // 0..1
                    int rem = idx & 511;
                    int row = rem >> 2;
                    int cch = rem & 3;
                    const __half* g = arr ? gp1 : gp0;
                    cpa16(base + arr * ARRB + row * PITCHB + cch * 16,
                          g + (size_t)row * XK + c * 32 + cch * 8);
                }
                asm volatile("cp.async.commit_group;" ::: "memory");
            };

            float acc[2][8][4];
#pragma unroll
            for (int i = 0; i < 2; i++)
#pragma unroll
                for (int jj = 0; jj < 8; jj++)
#pragma unroll
                    for (int q = 0; q < 4; q++) acc[i][jj][q] = 0.f;

            load_chunk(0, 0);
            load_chunk(1, 1);

            for (int c = 0; c < KCH; c++) {
                if (c + 1 < KCH) asm volatile("cp.async.wait_group 1;" ::: "memory");
                else             asm volatile("cp.async.wait_group 0;" ::: "memory");
                BARNAMED(2, 256);
                if (c + 2 < KCH) load_chunk(c + 2, (c + 2) % 3);

                uint32_t boff = (c % 3) * BUFB;
#pragma unroll
                for (int ks = 0; ks < 2; ks++) {
                    uint32_t ah[2][4], bh[4][4];
#pragma unroll
                    for (int mt = 0; mt < 2; mt++)
                        ldm4(ah[mt], aAddr + boff + mt * (16 * PITCHB) + ks * 32);
#pragma unroll
                    for (int ng = 0; ng < 4; ng++)
                        ldm4(bh[ng], bAddr + boff + ng * (16 * PITCHB) + ks * 32);
#pragma unroll
                    for (int mt = 0; mt < 2; mt++)
#pragma unroll
                        for (int ng = 0; ng < 4; ng++)
#pragma unroll
                            for (int hf = 0; hf < 2; hf++)
                                mma16816(acc[mt][ng * 2 + hf], ah[mt],
                                         bh[ng][hf], bh[ng][hf + 2]);
                }
            }

            const int qr = lane >> 2, qc = lane & 3;
#pragma unroll
            for (int mt = 0; mt < 2; mt++)
#pragma unroll
                for (int ntl = 0; ntl < 8; ntl++) {
                    int nb = n0 + wn * 64 + ntl * 8 + 2 * qc;
                    float b0 = gb[nb], b1 = gb[nb + 1];
#pragma unroll
                    for (int rp = 0; rp < 2; rp++) {
                        int m = m0 + wm * 32 + mt * 16 + qr + 8 * rp;
                        float2 v = make_float2(acc[mt][ntl][2 * rp] + b0,
                                               acc[mt][ntl][2 * rp + 1] + b1);
                        *(float2*)&g_xp[(size_t)m * XN + nb] = v;
                    }
                }

            BARNAMED(2, 256);
            if (tid == 0) atomAddRel(&g_tcnt[t], 1u);
        }
    } else {
        // ================= RECURRENCE (16 b x 32 u per block) =================
        const int ltid = tid - 256;            // 0..127
        const int lane = ltid & 31, lwid = ltid >> 5;  // 4 warps
        const int uh = lwid;                   // u-group (8 u each)
        const int bt = blockIdx.x & 7;         // 8 b-tiles of 16 rows
        const int ut = blockIdx.x >> 3;        // 16 u-tiles of 32 u
        const int u0 = ut * 32;
        const int row0 = bt * 16;
        const int qr = lane >> 2, qc = lane & 3;
        const int r1 = row0 + qr;
        const int r2 = r1 + 8;
        const int uc = u0 + uh * 8 + 2 * qc;

        // W slice -> smem (once): 3 gates x 32 u-rows x 512 k fp16
        for (int idx = ltid; idx < 6144; idx += 128) {
            int sec = idx >> 11;               // gate 0..2
            int rem = idx & 2047;
            int r = rem >> 6, ch = rem & 63;
            cpa16(sb + W_OFF + sec * WSEC + r * PITCH + ch * 16,
                  g_rh + ((size_t)(sec * 512 + u0 + r)) * UG + ch * 8);
        }
        asm volatile("cp.async.commit_group;" ::: "memory");

        const float* gbr = gb + XN;
        float bzc[2], brc[2], bhc[2];
#pragma unroll
        for (int j = 0; j < 2; j++) {
            bzc[j] = gbr[uc + j];
            brc[j] = gbr[512 + uc + j];
            bhc[j] = gbr[1024 + uc + j];
        }

        float hprev[4], hmax[4];
        hprev[0] = g_h0f[(size_t)r1 * UG + uc];
        hprev[1] = g_h0f[(size_t)r1 * UG + uc + 1];
        hprev[2] = g_h0f[(size_t)r2 * UG + uc];
        hprev[3] = g_h0f[(size_t)r2 * UG + uc + 1];
#pragma unroll
        for (int i = 0; i < 4; i++) hmax[i] = -INFINITY;

        const uint32_t aHi = sb + AHI_OFF + (lane & 15) * PITCH + ((lane >> 4) & 1) * 16;
        const uint32_t aLo = aHi + 16 * PITCH;
        uint32_t bHi[3];
        {
            int brow = uh * 8 + (lane & 7);
            int bch = lane >> 3;               // 0..3 -> 64B = k32
#pragma unroll
            for (int g = 0; g < 3; g++)
                bHi[g] = sb + W_OFF + g * WSEC + brow * PITCH + bch * 16;
        }

        auto stageA = [&](int par) {
            const __half* shp = g_hh[par] + (size_t)row0 * UG;
            const __half* slp = g_hl[par] + (size_t)row0 * UG;
            for (int idx = ltid; idx < 1024; idx += 128) {
                int r = idx >> 6, ch = idx & 63;
                cpa16(sb + AHI_OFF + r * PITCH + ch * 16, shp + (size_t)r * UG + ch * 8);
                cpa16(sb + ALO_OFF + r * PITCH + ch * 16, slp + (size_t)r * UG + ch * 8);
            }
            asm volatile("cp.async.commit_group;" ::: "memory");
        };

        stageA(0);

        {
            int spins = 0;
            while (ldAcq(&g_tcnt[0]) < 12u) {
                if (++spins > 16) asm volatile("nanosleep.u32 128;");
            }
        }
        float2 xz[2], xr[2], xh[2];
        {
            const float* xpr1 = g_xp + (size_t)r1 * XN;
            const float* xpr2 = g_xp + (size_t)r2 * XN;
            xz[0] = *(const float2*)(xpr1 + uc);        xz[1] = *(const float2*)(xpr2 + uc);
            xr[0] = *(const float2*)(xpr1 + 512 + uc);  xr[1] = *(const float2*)(xpr2 + 512 + uc);
            xh[0] = *(const float2*)(xpr1 + 1024 + uc); xh[1] = *(const float2*)(xpr2 + 1024 + uc);
        }

        unsigned* barp = &g_barp[bt][0];
        unsigned* genp = &g_genp[bt][0];

        for (int t = 0; t < T; t++) {
            asm volatile("cp.async.wait_group 0;" ::: "memory");
            BARNAMED(1, 128);

            float az[4] = {0.f, 0.f, 0.f, 0.f};
            float ar[4] = {0.f, 0.f, 0.f, 0.f};
            float ah2[4] = {0.f, 0.f, 0.f, 0.f};

#pragma unroll 4
            for (int j = 0; j < 16; j++) {
                uint32_t ah0[4], ah1[4], al0[4], al1[4];
                uint32_t a = aHi + j * 64;
                ldm4(ah0, a);
                ldm4(ah1, a + 32);
                uint32_t al = aLo + j * 64;
                ldm4(al0, al);
                ldm4(al1, al + 32);
                uint32_t b4h[4];
                // gate z (1-term)
                ldm4(b4h, bHi[0] + j * 64);
                mma16816(az, ah0, b4h[0], b4h[1]);
                mma16816(az, ah1, b4h[2], b4h[3]);
                // gate r (1-term)
                ldm4(b4h, bHi[1] + j * 64);
                mma16816(ar, ah0, b4h[0], b4h[1]);
                mma16816(ar, ah1, b4h[2], b4h[3]);
                // gate h (2-term)
                ldm4(b4h, bHi[2] + j * 64);
                mma16816(ah2, ah0, b4h[0], b4h[1]);
                mma16816(ah2, al0, b4h[0], b4h[1]);
                mma16816(ah2, ah1, b4h[2], b4h[3]);
                mma16816(ah2, al1, b4h[2], b4h[3]);
            }

            int np = (t + 1) & 1;
            bool notlast = (t + 1 < T);
#pragma unroll
            for (int pp = 0; pp < 2; pp++) {
                float hn[2];
#pragma unroll
                for (int j = 0; j < 2; j++) {
                    int i = 2 * pp + j;
                    float xzv = j ? xz[pp].y : xz[pp].x;
                    float xrv = j ? xr[pp].y : xr[pp].x;
                    float xhv = j ? xh[pp].y : xh[pp].x;
                    float z = sigm(xzv + az[i] + bzc[j]);
                    float r = sigm(xrv + ar[i] + brc[j]);
                    float hc = tanhf(xhv + r * (ah2[i] + bhc[j]));
                    hn[j] = z * hprev[i] + (1.f - z) * hc;
                    hprev[i] = hn[j];
                    hmax[i] = fmaxf(hmax[i], hn[j]);
                }
                if (notlast) {
                    int rowg = pp ? r2 : r1;
                    __half2 vh, vl;
                    __half h0b, l0b, h1b, l1b;
                    split_f16(hn[0], h0b, l0b);
                    split_f16(hn[1], h1b, l1b);
                    vh.x = h0b; vh.y = h1b;
                    vl.x = l0b; vl.y = l1b;
                    *(__half2*)&g_hh[np][(size_t)rowg * UG + uc] = vh;
                    *(__half2*)&g_hl[np][(size_t)rowg * UG + uc] = vl;
                }
            }

            if (notlast) {
                // xp(t+1): wait for production, prefetch (overlaps barrier)
                {
                    int spins = 0;
                    while (ldAcq(&g_tcnt[t + 1]) < 12u) {
                        if (++spins > 16) asm volatile("nanosleep.u32 128;");
                    }
                }
                {
                    const float* xp = g_xp + (size_t)(t + 1) * ((size_t)B * XN);
                    const float* xpr1 = xp + (size_t)r1 * XN;
                    const float* xpr2 = xp + (size_t)r2 * XN;
                    xz[0] = *(const float2*)(xpr1 + uc);        xz[1] = *(const float2*)(xpr2 + uc);
                    xr[0] = *(const float2*)(xpr1 + 512 + uc);  xr[1] = *(const float2*)(xpr2 + 512 + uc);
                    xh[0] = *(const float2*)(xpr1 + 1024 + uc); xh[1] = *(const float2*)(xpr2 + 1024 + uc);
                }
                BARNAMED(1, 128);          // h stores visible before arrive
                if (ltid == 0) {
                    unsigned target = (unsigned)(t + 1) * NBLK_BT;
                    unsigned old = atomAddRel(barp, 1);
                    if (old == target - 1) stRel(genp, (unsigned)(t + 1));
                }
                // all threads poll generation directly (no second bar)
                {
                    int spins = 0;
                    while (ldAcq(genp) < (unsigned)(t + 1)) {
                        if (++spins > 64) asm volatile("nanosleep.u32 64;");
                    }
                }
                stageA(np);
            }
        }

        float2 v;
        v.x = hmax[0]; v.y = hmax[1]; *(float2*)&g_hmax[(size_t)r1 * UG + uc] = v;
        v.x = hmax[2]; v.y = hmax[3]; *(float2*)&g_hmax[(size_t)r2 * UG + uc] = v;
        v.x = hprev[0]; v.y = hprev[1]; *(float2*)&g_h0f[(size_t)r1 * UG + uc] = v;
        v.x = hprev[2]; v.y = hprev[3]; *(float2*)&g_h0f[(size_t)r2 * UG + uc] = v;
    }
}

// ---------------- epilogue ---------------------------------------------------
__global__ void k_out(const float* __restrict__ Wout, const float* __restrict__ bout,
                      float* __restrict__ dout, int out_size) {
    int b = blockIdx.x;
    int tid = threadIdx.x; // 256
    __shared__ float red[256];
    float s = 0.f;
    for (int uu = tid; uu < UG; uu += 256) s += g_hmax[b * UG + uu] * Wout[uu];
    red[tid] = s;
    __syncthreads();
    for (int o = 128; o > 0; o >>= 1) {
        if (tid < o) red[tid] += red[tid + o];
        __syncthreads();
    }
    if (tid == 0 && b < out_size) dout[b] = eluf(red[0] + bout[0]);
    for (int uu = tid; uu < UG; uu += 256) {
        int idx = B + b * UG + uu;
        if (idx < out_size) dout[idx] = g_h0f[b * UG + uu];
    }
}

// ---------------- launch ------------------------------------------------------
extern "C" void kernel_launch(void* const* d_in, const int* in_sizes, int n_in,
                              void* d_out, int out_size) {
    const float* motion = (const float*)d_in[0];
    const float* robot  = (const float*)d_in[1];
    const float* action = (const float*)d_in[3];
    const float* osc    = (const float*)d_in[4];
    const float* mu     = (const float*)d_in[5];
    const float* mean   = (const float*)d_in[6];
    const float* state  = (const float*)d_in[7];
    const float* W_mot  = (const float*)d_in[8];
    const float* b_mot  = (const float*)d_in[9];
    const float* W_rob  = (const float*)d_in[10];
    const float* b_rob  = (const float*)d_in[11];
    const float* W_comb = (const float*)d_in[12];
    const float* b_comb = (const float*)d_in[13];
    const float* W_oscr = (const float*)d_in[14];
    const float* b_oscr = (const float*)d_in[15];
    const float* W_osci = (const float*)d_in[16];
    const float* b_osci = (const float*)d_in[17];
    const float* gru_k  = (const float*)d_in[18];
    const float* gru_rk = (const float*)d_in[19];
    const float* gru_b  = (const float*)d_in[20];
    const float* W_out  = (const float*)d_in[21];
    const float* b_out  = (const float*)d_in[22];
    float* out = (float*)d_out;

    static bool attr_set = false;
    if (!attr_set) {
        cudaFuncSetAttribute(k_fused, cudaFuncAttributeMaxDynamicSharedMemorySize, SMEM_FUSED);
        attr_set = true;
    }

    k_reset<<<1, 512>>>();
    k_msrs<<<B, 256>>>(motion, robot, W_mot, b_mot, W_rob, b_rob);
    k_h0<<<B, 512>>>(state, W_comb, b_comb);
    k_act<<<ROWS, 256>>>(action, mu, mean);
    k_inp23<<<ROWS / 8, 256>>>(osc, W_oscr, b_oscr, W_osci, b_osci);
    k_trb<<<dim3(XN / 32, XK / 32), dim3(32, 8)>>>(gru_k);
    k_trw<<<dim3(XN / 32, UG / 32), dim3(32, 8)>>>(gru_rk);
    k_fused<<<128, 384, SMEM_FUSED>>>(gru_b);
    k_out<<<B, 256>>>(W_out, b_out, out, out_size);
}

// round 13
// speedup vs baseline: 5.1294x; 1.1024x over previous
#include <cuda_runtime.h>
#include <cuda_fp16.h>
#include <cstdint>
#include <math.h>

namespace {
constexpr int B  = 128;
constexpr int T  = 512;
constexpr int A  = 256;
constexpr int UG = 512;
constexpr int ROWS = B * T;       // 65536
constexpr int XK = 768;           // x feature width
constexpr int XN = 1536;          // 3 * UG
}

// ---------------- scratch (device globals; no allocation allowed) ------------
__device__ __half g_xh[(size_t)ROWS * XK];      // fp16 x
__device__ __half g_bh[(size_t)XN * XK];        // gru_k^T [N,K] fp16
__device__ __half g_rh[(size_t)XN * UG];        // gru_rk^T [1536,512] fp16
__device__ float g_xp[(size_t)ROWS * XN];       // x @ gru_k + gru_b[0]
__device__ float g_h0f[B * UG];                 // h0 fp32 / final h
__device__ __half g_hh[2][B * UG];              // h ping-pong, fp16 hi
__device__ __half g_hl[2][B * UG];              // h ping-pong, fp16 lo
__device__ float g_hmax[B * UG];
__device__ unsigned g_barp[8][32];              // per-btile barrier arrivals (padded)
__device__ unsigned g_genp[8][32];              // per-btile generation (padded)
__device__ unsigned g_tcnt[T];                  // completed xp n-tiles per timestep

__device__ __forceinline__ float eluf(float v) { return v > 0.f ? v : (expf(v) - 1.f); }
__device__ __forceinline__ float sigm(float v) { return 1.f / (1.f + expf(-v)); }
__device__ __forceinline__ void split_f16(float v, __half& h, __half& l) {
    h = __float2half(v);
    l = __float2half(v - __half2float(h));
}

// ---------------- PTX helpers (plain sm_103-safe) -----------------------------
__device__ __forceinline__ uint32_t smem_u32(const void* p) {
    uint32_t a;
    asm("{ .reg .u64 t; cvta.to.shared.u64 t, %1; cvt.u32.u64 %0, t; }" : "=r"(a) : "l"(p));
    return a;
}
__device__ __forceinline__ void cpa16(uint32_t s, const void* g) {
    asm volatile("cp.async.cg.shared.global [%0], [%1], 16;" :: "r"(s), "l"(g));
}
__device__ __forceinline__ void ldm4(uint32_t* r, uint32_t a) {
    asm volatile("ldmatrix.sync.aligned.m8n8.x4.shared.b16 {%0,%1,%2,%3}, [%4];"
                 : "=r"(r[0]), "=r"(r[1]), "=r"(r[2]), "=r"(r[3]) : "r"(a));
}
__device__ __forceinline__ void mma16816(float* c, const uint32_t* a, uint32_t b0, uint32_t b1) {
    asm volatile(
        "mma.sync.aligned.m16n8k16.row.col.f32.f16.f16.f32 "
        "{%0,%1,%2,%3}, {%4,%5,%6,%7}, {%8,%9}, {%0,%1,%2,%3};"
        : "+f"(c[0]), "+f"(c[1]), "+f"(c[2]), "+f"(c[3])
        : "r"(a[0]), "r"(a[1]), "r"(a[2]), "r"(a[3]), "r"(b0), "r"(b1));
}
__device__ __forceinline__ unsigned atomAddRel(unsigned* p, unsigned v) {
    unsigned o;
    asm volatile("atom.release.gpu.global.add.u32 %0, [%1], %2;"
                 : "=r"(o) : "l"(p), "r"(v) : "memory");
    return o;
}
__device__ __forceinline__ void stRel(unsigned* p, unsigned v) {
    asm volatile("st.release.gpu.global.u32 [%0], %1;" :: "l"(p), "r"(v) : "memory");
}
__device__ __forceinline__ unsigned ldAcq(unsigned* p) {
    unsigned v;
    asm volatile("ld.acquire.gpu.global.u32 %0, [%1];" : "=r"(v) : "l"(p) : "memory");
    return v;
}
#define BARNAMED(id, cnt) asm volatile("bar.sync %0, %1;" :: "r"(id), "r"(cnt) : "memory")

// ---------------- front-end kernels -------------------------------------------
__global__ void k_reset() {
    int i = threadIdx.x; // 512
    g_tcnt[i] = 0;
    if (i < 8) { g_barp[i][0] = 0; g_genp[i][0] = 0; }
}

// fused msrs + h0: one block per batch row b, 512 threads
__global__ void k_init(const float* __restrict__ motion, const float* __restrict__ robot,
                       const float* __restrict__ state,
                       const float* __restrict__ Wm, const float* __restrict__ bm,
                       const float* __restrict__ Wr, const float* __restrict__ br,
                       const float* __restrict__ Wc, const float* __restrict__ bc) {
    int b = blockIdx.x;
    int tid = threadIdx.x; // 512
    __shared__ float inbuf[128];
    __shared__ float s[1024];    // [ms(256) | rs(256) | state(512)]
    if (tid < 64) inbuf[tid] = motion[b * 64 + tid];
    else if (tid < 128) inbuf[tid] = robot[b * 64 + (tid - 64)];
    s[512 + tid] = state[b * 512 + tid];
    __syncthreads();
    {
        int half = tid >> 8;     // 0: ms, 1: rs
        int j = tid & 255;
        const float* W = half ? Wr : Wm;
        const float* bb = half ? br : bm;
        const float* in = inbuf + half * 64;
        float acc = bb[j];
        for (int k = 0; k < 64; k++) acc += in[k] * W[k * 256 + j];
        s[half * 256 + j] = eluf(acc);
    }
    __syncthreads();
    float acc = bc[tid];
    for (int k = 0; k < 1024; k++) acc += s[k] * Wc[k * 512 + tid];
    float h0 = eluf(acc);
    size_t idx = (size_t)b * 512 + tid;
    g_h0f[idx] = h0;
    split_f16(h0, g_hh[0][idx], g_hl[0][idx]);
}

// fused act + inp2 + inp3: 8 rows per block, 256 threads
__global__ void k_front(const float* __restrict__ action, const float* __restrict__ mu,
                        const float* __restrict__ mean, const float* __restrict__ osc,
                        const float* __restrict__ W2, const float* __restrict__ b2,
                        const float* __restrict__ W3, const float* __restrict__ b3) {
    int r0 = blockIdx.x * 8;
    int j = threadIdx.x; // 256
    __shared__ float sin_[8][64];
    __shared__ float smid[8][256];
    // act for these rows
#pragma unroll
    for (int i = 0; i < 8; i++) {
        int r = r0 + i;
        int t = r >> 7, b = r & 127;
        float v = action[((size_t)b * T + t) * A + j] * mu[b * A + j] + mean[b * A + j];
        g_xh[(size_t)r * XK + j] = __float2half(v);
    }
    for (int i = threadIdx.x; i < 8 * 64; i += 256) {
        int rr = i >> 6, k = i & 63;
        int r = r0 + rr;
        int t = r >> 7, b = r & 127;
        sin_[rr][k] = osc[((size_t)b * T + t) * 128 + k];
    }
    __syncthreads();
    {
        float bj = b2[j];
        float acc[8];
#pragma unroll
        for (int i = 0; i < 8; i++) acc[i] = bj;
        for (int k = 0; k < 64; k++) {
            float w = W2[k * 256 + j];
#pragma unroll
            for (int i = 0; i < 8; i++) acc[i] += sin_[i][k] * w;
        }
#pragma unroll
        for (int i = 0; i < 8; i++) {
            float v = eluf(acc[i]);
            smid[i][j] = v;
            g_xh[(size_t)(r0 + i) * XK + 256 + j] = __float2half(v);
        }
    }
    __syncthreads();
    {
        float bj = b3[j];
        float acc[8];
#pragma unroll
        for (int i = 0; i < 8; i++) acc[i] = bj;
        for (int k = 0; k < 192; k++) {
            float w = W3[k * 256 + j];
#pragma unroll
            for (int i = 0; i < 8; i++) acc[i] += smid[i][64 + k] * w;
        }
#pragma unroll
        for (int i = 0; i < 8; i++)
            g_xh[(size_t)(r0 + i) * XK + 512 + j] = __float2half(eluf(acc[i]));
    }
}

// transpose gru_k [768,1536] -> g_bh [1536,768] fp16
__global__ void k_trb(const float* __restrict__ gk) {
    __shared__ float s[32][33];
    int n0 = blockIdx.x * 32, k0 = blockIdx.y * 32;
    int tx = threadIdx.x, ty = threadIdx.y; // 32 x 8
#pragma unroll
    for (int i = 0; i < 32; i += 8)
        s[ty + i][tx] = gk[(size_t)(k0 + ty + i) * XN + n0 + tx];
    __syncthreads();
#pragma unroll
    for (int i = 0; i < 32; i += 8) {
        size_t idx = (size_t)(n0 + ty + i) * XK + k0 + tx;
        g_bh[idx] = __float2half(s[tx][ty + i]);
    }
}

// transpose gru_rk [512,1536] -> g_rh [1536,512] fp16
__global__ void k_trw(const float* __restrict__ wr) {
    __shared__ float s[32][33];
    int n0 = blockIdx.x * 32, k0 = blockIdx.y * 32;
    int tx = threadIdx.x, ty = threadIdx.y; // 32 x 8
#pragma unroll
    for (int i = 0; i < 32; i += 8)
        s[ty + i][tx] = wr[(size_t)(k0 + ty + i) * XN + n0 + tx];
    __syncthreads();
#pragma unroll
    for (int i = 0; i < 32; i += 8) {
        size_t idx = (size_t)(n0 + ty + i) * UG + k0 + tx;
        g_rh[idx] = __float2half(s[tx][ty + i]);
    }
}

// ---------------- FUSED persistent kernel -------------------------------------
// 128 blocks x 384 threads.
//   warps 0-7  (tid 0..255):  xp production (tile 128x128, fp16 1-term, 3-stage)
//   warps 8-11 (tid 256..383): GRU recurrence (block owns 16 b x 32 u)
// 8 b-tiles x 16 u-tiles -> 16-block barriers. z,r = 1-term; h-cand = 2-term.
// Per-step chain: early barrier arrive; stageA split into 2 k-half groups.
namespace {
constexpr int PITCHB = 80;
constexpr int ARRB   = 128 * PITCHB;       // 10240
constexpr int BUFB   = 2 * ARRB;           // 20480 : A | B
constexpr int PROD_BYTES = 3 * BUFB;       // 61440
constexpr int KCH = 24;
constexpr int NJOBS = T * (XN / 128);      // 6144, 12 per t
constexpr int PITCH = 1040;
constexpr int WSEC  = 32 * PITCH;              // 33280 per gate (32 u rows)
constexpr int W_OFF = PROD_BYTES;              // 61440
constexpr int AHI_OFF = W_OFF + 3 * WSEC;      // 161280
constexpr int ALO_OFF = AHI_OFF + 16 * PITCH;  // 177920
constexpr int SMEM_FUSED = ALO_OFF + 16 * PITCH; // 194560
constexpr int NBLK_BT = 16;
}

__global__ void __launch_bounds__(384, 1) k_fused(const float* __restrict__ gb) {
    extern __shared__ char smem[];
    const uint32_t sb = smem_u32(smem);
    const int tid = threadIdx.x;

    if (tid < 256) {
        // ================= PRODUCTION (1-term fp16) =================
        const int lane = tid & 31, wid = tid >> 5;
        const int wm = wid & 3;
        const int wn = wid >> 2;
        const uint32_t aAddr = sb + (wm * 32 + (lane & 15)) * PITCHB + (lane >> 4) * 16;
        const uint32_t bAddr = sb + ARRB + (wn * 64 + (lane & 15)) * PITCHB + (lane >> 4) * 16;

        for (int job = blockIdx.x; job < NJOBS; job += 128) {
            const int t = job / 12, nt = job % 12;
            const int m0 = t * 128;
            const int n0 = nt * 128;
            const __half* gp0 = g_xh + (size_t)m0 * XK;
            const __half* gp1 = g_bh + (size_t)n0 * XK;

            auto load_chunk = [&](int c, int buf) {
                uint32_t base = sb + buf * BUFB;
#pragma unroll
                for (int l = 0; l < 4; l++) {
                    int idx = tid + 256 * l;
                    int arr = idx >> 9;            // 0..1
                    int rem = idx & 511;
                    int row = rem >> 2;
                    int cch = rem & 3;
                    const __half* g = arr ? gp1 : gp0;
                    cpa16(base + arr * ARRB + row * PITCHB + cch * 16,
                          g + (size_t)row * XK + c * 32 + cch * 8);
                }
                asm volatile("cp.async.commit_group;" ::: "memory");
            };

            float acc[2][8][4];
#pragma unroll
            for (int i = 0; i < 2; i++)
#pragma unroll
                for (int jj = 0; jj < 8; jj++)
#pragma unroll
                    for (int q = 0; q < 4; q++) acc[i][jj][q] = 0.f;

            load_chunk(0, 0);
            load_chunk(1, 1);

            for (int c = 0; c < KCH; c++) {
                if (c + 1 < KCH) asm volatile("cp.async.wait_group 1;" ::: "memory");
                else             asm volatile("cp.async.wait_group 0;" ::: "memory");
                BARNAMED(2, 256);
                if (c + 2 < KCH) load_chunk(c + 2, (c + 2) % 3);

                uint32_t boff = (c % 3) * BUFB;
#pragma unroll
                for (int ks = 0; ks < 2; ks++) {
                    uint32_t ah[2][4], bh[4][4];
#pragma unroll
                    for (int mt = 0; mt < 2; mt++)
                        ldm4(ah[mt], aAddr + boff + mt * (16 * PITCHB) + ks * 32);
#pragma unroll
                    for (int ng = 0; ng < 4; ng++)
                        ldm4(bh[ng], bAddr + boff + ng * (16 * PITCHB) + ks * 32);
#pragma unroll
                    for (int mt = 0; mt < 2; mt++)
#pragma unroll
                        for (int ng = 0; ng < 4; ng++)
#pragma unroll
                            for (int hf = 0; hf < 2; hf++)
                                mma16816(acc[mt][ng * 2 + hf], ah[mt],
                                         bh[ng][hf], bh[ng][hf + 2]);
                }
            }

            const int qr = lane >> 2, qc = lane & 3;
#pragma unroll
            for (int mt = 0; mt < 2; mt++)
#pragma unroll
                for (int ntl = 0; ntl < 8; ntl++) {
                    int nb = n0 + wn * 64 + ntl * 8 + 2 * qc;
                    float b0 = gb[nb], b1 = gb[nb + 1];
#pragma unroll
                    for (int rp = 0; rp < 2; rp++) {
                        int m = m0 + wm * 32 + mt * 16 + qr + 8 * rp;
                        float2 v = make_float2(acc[mt][ntl][2 * rp] + b0,
                                               acc[mt][ntl][2 * rp + 1] + b1);
                        *(float2*)&g_xp[(size_t)m * XN + nb] = v;
                    }
                }

            BARNAMED(2, 256);
            if (tid == 0) atomAddRel(&g_tcnt[t], 1u);
        }
    } else {
        // ================= RECURRENCE (16 b x 32 u per block) =================
        const int ltid = tid - 256;            // 0..127
        const int lane = ltid & 31, lwid = ltid >> 5;  // 4 warps
        const int uh = lwid;                   // u-group (8 u each)
        const int bt = blockIdx.x & 7;         // 8 b-tiles of 16 rows
        const int ut = blockIdx.x >> 3;        // 16 u-tiles of 32 u
        const int u0 = ut * 32;
        const int row0 = bt * 16;
        const int qr = lane >> 2, qc = lane & 3;
        const int r1 = row0 + qr;
        const int r2 = r1 + 8;
        const int uc = u0 + uh * 8 + 2 * qc;

        // W slice -> smem (once): 3 gates x 32 u-rows x 512 k fp16 (1 group)
        for (int idx = ltid; idx < 6144; idx += 128) {
            int sec = idx >> 11;               // gate 0..2
            int rem = idx & 2047;
            int r = rem >> 6, ch = rem & 63;
            cpa16(sb + W_OFF + sec * WSEC + r * PITCH + ch * 16,
                  g_rh + ((size_t)(sec * 512 + u0 + r)) * UG + ch * 8);
        }
        asm volatile("cp.async.commit_group;" ::: "memory");

        const float* gbr = gb + XN;
        float bzc[2], brc[2], bhc[2];
#pragma unroll
        for (int j = 0; j < 2; j++) {
            bzc[j] = gbr[uc + j];
            brc[j] = gbr[512 + uc + j];
            bhc[j] = gbr[1024 + uc + j];
        }

        float hprev[4], hmax[4];
        hprev[0] = g_h0f[(size_t)r1 * UG + uc];
        hprev[1] = g_h0f[(size_t)r1 * UG + uc + 1];
        hprev[2] = g_h0f[(size_t)r2 * UG + uc];
        hprev[3] = g_h0f[(size_t)r2 * UG + uc + 1];
#pragma unroll
        for (int i = 0; i < 4; i++) hmax[i] = -INFINITY;

        const uint32_t aHi = sb + AHI_OFF + (lane & 15) * PITCH + ((lane >> 4) & 1) * 16;
        const uint32_t aLo = aHi + 16 * PITCH;
        uint32_t bHi[3];
        {
            int brow = uh * 8 + (lane & 7);
            int bch = lane >> 3;               // 0..3 -> 64B = k32
#pragma unroll
            for (int g = 0; g < 3; g++)
                bHi[g] = sb + W_OFF + g * WSEC + brow * PITCH + bch * 16;
        }

        // stageA: two commit groups (k-halves). kh=0 -> ch 0..31, kh=1 -> ch 32..63
        auto stageA = [&](int par) {
            const __half* shp = g_hh[par] + (size_t)row0 * UG;
            const __half* slp = g_hl[par] + (size_t)row0 * UG;
#pragma unroll
            for (int kh = 0; kh < 2; kh++) {
                for (int idx = ltid; idx < 512; idx += 128) {
                    int r = idx >> 5, ch = (idx & 31) + kh * 32;
                    cpa16(sb + AHI_OFF + r * PITCH + ch * 16, shp + (size_t)r * UG + ch * 8);
                    cpa16(sb + ALO_OFF + r * PITCH + ch * 16, slp + (size_t)r * UG + ch * 8);
                }
                asm volatile("cp.async.commit_group;" ::: "memory");
            }
        };

        stageA(0);

        {
            int spins = 0;
            while (ldAcq(&g_tcnt[0]) < 12u) {
                if (++spins > 16) asm volatile("nanosleep.u32 128;");
            }
        }
        float2 xz[2], xr[2], xh[2];
        {
            const float* xpr1 = g_xp + (size_t)r1 * XN;
            const float* xpr2 = g_xp + (size_t)r2 * XN;
            xz[0] = *(const float2*)(xpr1 + uc);        xz[1] = *(const float2*)(xpr2 + uc);
            xr[0] = *(const float2*)(xpr1 + 512 + uc);  xr[1] = *(const float2*)(xpr2 + 512 + uc);
            xh[0] = *(const float2*)(xpr1 + 1024 + uc); xh[1] = *(const float2*)(xpr2 + 1024 + uc);
        }

        unsigned* barp = &g_barp[bt][0];
        unsigned* genp = &g_genp[bt][0];

        for (int t = 0; t < T; t++) {
            float az[4] = {0.f, 0.f, 0.f, 0.f};
            float ar[4] = {0.f, 0.f, 0.f, 0.f};
            float ah2[4] = {0.f, 0.f, 0.f, 0.f};

            // first k-half arrives (W-load group also drains on t=0)
            asm volatile("cp.async.wait_group 1;" ::: "memory");
            BARNAMED(1, 128);
#pragma unroll 4
            for (int j = 0; j < 8; j++) {
                uint32_t ah0[4], ah1[4], al0[4], al1[4];
                uint32_t a = aHi + j * 64;
                ldm4(ah0, a);
                ldm4(ah1, a + 32);
                uint32_t al = aLo + j * 64;
                ldm4(al0, al);
                ldm4(al1, al + 32);
                uint32_t b4h[4];
                ldm4(b4h, bHi[0] + j * 64);
                mma16816(az, ah0, b4h[0], b4h[1]);
                mma16816(az, ah1, b4h[2], b4h[3]);
                ldm4(b4h, bHi[1] + j * 64);
                mma16816(ar, ah0, b4h[0], b4h[1]);
                mma16816(ar, ah1, b4h[2], b4h[3]);
                ldm4(b4h, bHi[2] + j * 64);
                mma16816(ah2, ah0, b4h[0], b4h[1]);
                mma16816(ah2, al0, b4h[0], b4h[1]);
                mma16816(ah2, ah1, b4h[2], b4h[3]);
                mma16816(ah2, al1, b4h[2], b4h[3]);
            }
            // second k-half
            asm volatile("cp.async.wait_group 0;" ::: "memory");
            BARNAMED(1, 128);
#pragma unroll 4
            for (int j = 8; j < 16; j++) {
                uint32_t ah0[4], ah1[4], al0[4], al1[4];
                uint32_t a = aHi + j * 64;
                ldm4(ah0, a);
                ldm4(ah1, a + 32);
                uint32_t al = aLo + j * 64;
                ldm4(al0, al);
                ldm4(al1, al + 32);
                uint32_t b4h[4];
                ldm4(b4h, bHi[0] + j * 64);
                mma16816(az, ah0, b4h[0], b4h[1]);
                mma16816(az, ah1, b4h[2], b4h[3]);
                ldm4(b4h, bHi[1] + j * 64);
                mma16816(ar, ah0, b4h[0], b4h[1]);
                mma16816(ar, ah1, b4h[2], b4h[3]);
                ldm4(b4h, bHi[2] + j * 64);
                mma16816(ah2, ah0, b4h[0], b4h[1]);
                mma16816(ah2, al0, b4h[0], b4h[1]);
                mma16816(ah2, ah1, b4h[2], b4h[3]);
                mma16816(ah2, al1, b4h[2], b4h[3]);
            }

            int np = (t + 1) & 1;
            bool notlast = (t + 1 < T);
#pragma unroll
            for (int pp = 0; pp < 2; pp++) {
                float hn[2];
#pragma unroll
                for (int j = 0; j < 2; j++) {
                    int i = 2 * pp + j;
                    float xzv = j ? xz[pp].y : xz[pp].x;
                    float xrv = j ? xr[pp].y : xr[pp].x;
                    float xhv = j ? xh[pp].y : xh[pp].x;
                    float z = sigm(xzv + az[i] + bzc[j]);
                    float r = sigm(xrv + ar[i] + brc[j]);
                    float hc = tanhf(xhv + r * (ah2[i] + bhc[j]));
                    hn[j] = z * hprev[i] + (1.f - z) * hc;
                    hprev[i] = hn[j];
                    hmax[i] = fmaxf(hmax[i], hn[j]);
                }
                if (notlast) {
                    int rowg = pp ? r2 : r1;
                    __half2 vh, vl;
                    __half h0b, l0b, h1b, l1b;
                    split_f16(hn[0], h0b, l0b);
                    split_f16(hn[1], h1b, l1b);
                    vh.x = h0b; vh.y = h1b;
                    vl.x = l0b; vl.y = l1b;
                    *(__half2*)&g_hh[np][(size_t)rowg * UG + uc] = vh;
                    *(__half2*)&g_hl[np][(size_t)rowg * UG + uc] = vl;
                }
            }

            if (notlast) {
                // EARLY ARRIVE: publish h before doing local prefetch work
                BARNAMED(1, 128);          // h stores visible CTA-wide
                if (ltid == 0) {
                    unsigned target = (unsigned)(t + 1) * NBLK_BT;
                    unsigned old = atomAddRel(barp, 1);
                    if (old == target - 1) stRel(genp, (unsigned)(t + 1));
                }
                // overlap: xp(t+1) spin + prefetch while peers arrive
                {
                    int spins = 0;
                    while (ldAcq(&g_tcnt[t + 1]) < 12u) {
                        if (++spins > 16) asm volatile("nanosleep.u32 128;");
                    }
                }
                {
                    const float* xp = g_xp + (size_t)(t + 1) * ((size_t)B * XN);
                    const float* xpr1 = xp + (size_t)r1 * XN;
                    const float* xpr2 = xp + (size_t)r2 * XN;
                    xz[0] = *(const float2*)(xpr1 + uc);        xz[1] = *(const float2*)(xpr2 + uc);
                    xr[0] = *(const float2*)(xpr1 + 512 + uc);  xr[1] = *(const float2*)(xpr2 + 512 + uc);
                    xh[0] = *(const float2*)(xpr1 + 1024 + uc); xh[1] = *(const float2*)(xpr2 + 1024 + uc);
                }
                // all threads poll generation directly
                {
                    int spins = 0;
                    while (ldAcq(genp) < (unsigned)(t + 1)) {
                        if (++spins > 64) asm volatile("nanosleep.u32 64;");
                    }
                }
                stageA(np);
            }
        }

        float2 v;
        v.x = hmax[0]; v.y = hmax[1]; *(float2*)&g_hmax[(size_t)r1 * UG + uc] = v;
        v.x = hmax[2]; v.y = hmax[3]; *(float2*)&g_hmax[(size_t)r2 * UG + uc] = v;
        v.x = hprev[0]; v.y = hprev[1]; *(float2*)&g_h0f[(size_t)r1 * UG + uc] = v;
        v.x = hprev[2]; v.y = hprev[3]; *(float2*)&g_h0f[(size_t)r2 * UG + uc] = v;
    }
}

// ---------------- epilogue ---------------------------------------------------
__global__ void k_out(const float* __restrict__ Wout, const float* __restrict__ bout,
                      float* __restrict__ dout, int out_size) {
    int b = blockIdx.x;
    int tid = threadIdx.x; // 256
    __shared__ float red[256];
    float s = 0.f;
    for (int uu = tid; uu < UG; uu += 256) s += g_hmax[b * UG + uu] * Wout[uu];
    red[tid] = s;
    __syncthreads();
    for (int o = 128; o > 0; o >>= 1) {
        if (tid < o) red[tid] += red[tid + o];
        __syncthreads();
    }
    if (tid == 0 && b < out_size) dout[b] = eluf(red[0] + bout[0]);
    for (int uu = tid; uu < UG; uu += 256) {
        int idx = B + b * UG + uu;
        if (idx < out_size) dout[idx] = g_h0f[b * UG + uu];
    }
}

// ---------------- launch ------------------------------------------------------
extern "C" void kernel_launch(void* const* d_in, const int* in_sizes, int n_in,
                              void* d_out, int out_size) {
    const float* motion = (const float*)d_in[0];
    const float* robot  = (const float*)d_in[1];
    const float* action = (const float*)d_in[3];
    const float* osc    = (const float*)d_in[4];
    const float* mu     = (const float*)d_in[5];
    const float* mean   = (const float*)d_in[6];
    const float* state  = (const float*)d_in[7];
    const float* W_mot  = (const float*)d_in[8];
    const float* b_mot  = (const float*)d_in[9];
    const float* W_rob  = (const float*)d_in[10];
    const float* b_rob  = (const float*)d_in[11];
    const float* W_comb = (const float*)d_in[12];
    const float* b_comb = (const float*)d_in[13];
    const float* W_oscr = (const float*)d_in[14];
    const float* b_oscr = (const float*)d_in[15];
    const float* W_osci = (const float*)d_in[16];
    const float* b_osci = (const float*)d_in[17];
    const float* gru_k  = (const float*)d_in[18];
    const float* gru_rk = (const float*)d_in[19];
    const float* gru_b  = (const float*)d_in[20];
    const float* W_out  = (const float*)d_in[21];
    const float* b_out  = (const float*)d_in[22];
    float* out = (float*)d_out;

    static bool attr_set = false;
    if (!attr_set) {
        cudaFuncSetAttribute(k_fused, cudaFuncAttributeMaxDynamicSharedMemorySize, SMEM_FUSED);
        attr_set = true;
    }

    // launch order: k_fused at index 5 (ncu -s 5 -c 1 target)
    k_reset<<<1, 512>>>();                                             // 0
    k_init<<<B, 512>>>(motion, robot, state, W_mot, b_mot,
                       W_rob, b_rob, W_comb, b_comb);                  // 1
    k_front<<<ROWS / 8, 256>>>(action, mu, mean, osc,
                               W_oscr, b_oscr, W_osci, b_osci);        // 2
    k_trb<<<dim3(XN / 32, XK / 32), dim3(32, 8)>>>(gru_k);             // 3
    k_trw<<<dim3(XN / 32, UG / 32), dim3(32, 8)>>>(gru_rk);            // 4
    k_fused<<<128, 384, SMEM_FUSED>>>(gru_b);                          // 5
    k_out<<<B, 256>>>(W_out, b_out, out, out_size);                    // 6
}